// round 7
// baseline (speedup 1.0000x reference)
#include <cuda_runtime.h>
#include <cuda_bf16.h>
#include <math.h>

#define NR 8192
#define HD 128
#define KN 8
#define H3 384
#define EPSF 1e-6f

// ---------------- scratch ----------------
__device__ float g_X1[NR*HD], g_X2[NR*HD];
__device__ float g_U1[NR*HD], g_U2[NR*HD], g_U3[NR*HD];
__device__ float g_F1[NR*HD], g_F2[NR*HD], g_F3[NR*HD];
__device__ float g_W1[NR*HD], g_W2[NR*HD], g_W3[NR*HD];
__device__ float g_Q1[NR*HD], g_Q2[NR*HD], g_Q3[NR*HD];
__device__ float g_h1p[NR*HD], g_h1s[NR*HD], g_h1e[NR*HD];
__device__ float g_yp[NR*HD], g_ys[NR*HD], g_ye[NR*HD];
__device__ float g_nhp2[NR], g_nhs2[NR], g_lyp[NR], g_lys[NR];
__device__ float g_q1ss[NR], g_q2ss[NR], g_c1vss[NR], g_c2vss[NR];
__device__ float g_c1v[NR*HD], g_c2v[NR*HD], g_c3v[NR*HD];
__device__ float g_G1[NR*H3], g_G2[NR*H3], g_G3[NR*H3];

// pre-split bf16 A operands: 12 slots x [NR][64] packed u32 (pairs along K)
#define S_A1 0
#define S_A2 1
#define S_H3 2
#define S_B1 3
#define S_B2 4
#define S_C3 5
#define S_X1 6
#define S_X2 7
#define S_X  8
#define S_T1 9
#define S_T2 10
#define S_T3 11
__device__ unsigned int g_Ahi[12*NR*64], g_Alo[12*NR*64];

// packed bf16 hi/lo weights
#define OFF_UP 0
#define OFF_UF 8192
#define OFF_WC 16384
#define OFF_WQ 24576
#define OFF_IOU 32768
#define WPK_TOT 57344
__device__ unsigned int g_Whi[WPK_TOT], g_Wlo[WPK_TOT];

// ---------------- scalar helpers ----------------
__device__ __forceinline__ float sigm(float v){ return 1.f/(1.f+expf(-v)); }
__device__ __forceinline__ float artk(float u, float k){
  if (k < 0.f){ u = fminf(fmaxf(u, -1.f+1e-5f), 1.f-1e-5f); return atanhf(u); }
  return atanf(u);
}
__device__ __forceinline__ float tank(float u, float k){
  if (k < 0.f) return tanhf(u);
  return tanf(fminf(fmaxf(u, -1.47079f), 1.47079f));
}
__device__ __forceinline__ float sden(float d){
  return d >= 0.f ? fmaxf(d, EPSF) : fminf(d, -EPSF);
}
__device__ __forceinline__ float nrm(float ss){ return sqrtf(ss + 1e-15f); }

// ---------------- reductions ----------------
template<int N> __device__ __forceinline__ void redN(float* v){
  #pragma unroll
  for (int o=16;o;o>>=1){
    float t[N];
    #pragma unroll
    for (int i=0;i<N;i++) t[i] = __shfl_xor_sync(0xffffffffu, v[i], o);
    #pragma unroll
    for (int i=0;i<N;i++) v[i] += t[i];
  }
}
template<int V> __device__ __forceinline__ float pdot(const float* a, const float* b){
  float s = 0.f;
  #pragma unroll
  for (int i=0;i<V;i++) s += a[i]*b[i];
  return s;
}
template<int V> __device__ __forceinline__ float pss(const float* a){ return pdot<V>(a,a); }

// ---------------- analytic (norm-tracked) manifold ops ----------------
template<int V> __device__ __forceinline__ void vscale(float* a, float f){
  #pragma unroll
  for (int i=0;i<V;i++) a[i]*=f;
}
template<int V> __device__ __forceinline__ float aexp0(float* a, float k, float ss){
  float n = nrm(ss);
  float t = tank(n,k);
  if (k < 0.f) t = fminf(t, 1.f-1e-4f);
  vscale<V>(a, t/n);
  return t*t;
}
template<int V> __device__ __forceinline__ float alog0(float* a, float k, float ss){
  float n = nrm(ss);
  float t = artk(n,k);
  vscale<V>(a, t/n);
  return t*t;
}
template<int V> __device__ __forceinline__ float aexplog(float* a, float k, float ss){
  float n = nrm(ss);
  float t;
  if (k < 0.f) t = atanhf(fminf(tanhf(n), 1.f-1e-4f));
  else         t = fminf(n, 1.47079f);
  vscale<V>(a, t/n);
  return t*t;
}
template<int V> __device__ __forceinline__ float asmul(float* a, float r, float k, float ss){
  float n = nrm(ss);
  float t = tank(r*artk(n,k),k);
  if (k < 0.f) t = fminf(t, 1.f-1e-4f);
  vscale<V>(a, t/n);
  return t*t;
}
template<int V> __device__ __forceinline__ float apw(float* wx, float k, float ssx, float ssw){
  float nx = nrm(ssx), nwx = nrm(ssw);
  float t = tank(nwx/nx*artk(nx,k),k);
  if (k < 0.f) t = fminf(t, 1.f-1e-4f);
  vscale<V>(wx, t/nwx);
  return t*t;
}
template<int V> __device__ __forceinline__ float aproj(float* a, float ss){
  float n = nrm(ss);
  const float m = 1.f-1e-4f;
  if (n > m){ float f = m/n; vscale<V>(a, f); return ss*f*f; }
  return ss;
}
__device__ __forceinline__ void amadd_coef(float k, float x2, float y2, float xy,
                                           float& ca, float& cb, float& isd){
  ca = 1.f - 2.f*k*xy - k*y2;
  cb = 1.f + k*x2;
  isd = 1.f/sden(1.f - 2.f*k*xy + k*k*x2*y2);
}
__device__ __forceinline__ float distf(float x2, float y2, float xy, float k){
  float ca = 1.f + 2.f*k*xy - k*y2;
  float cb = 1.f + k*x2;
  float sd = sden(1.f + 2.f*k*xy + k*k*x2*y2);
  float s = fmaxf(ca*ca*x2 + cb*cb*y2 - 2.f*ca*cb*xy, 0.f);
  float nv2 = s/(sd*sd);
  float pn = sqrtf(nv2 + 1e-15f);
  if (k < 0.f){
    const float m = 1.f - 1e-4f;
    if (pn > m){ float sc = m/pn; pn = sqrtf(nv2*sc*sc + 1e-15f); }
  }
  return 2.f*artk(pn, k);
}
// strided layout (element lane + 32i)
__device__ __forceinline__ void ldrow(float* a, const float* p, int row, int lane){
  #pragma unroll
  for (int i=0;i<4;i++) a[i] = p[(size_t)row*HD + i*32 + lane];
}
__device__ __forceinline__ void strow(const float* a, float* p, int row, int lane){
  #pragma unroll
  for (int i=0;i<4;i++) p[(size_t)row*HD + i*32 + lane] = a[i];
}
// paired layout (elements 2lane,2lane+1, 64+2lane, 64+2lane+1)
__device__ __forceinline__ void ldrowp(float* a, const float* p, int row, int lane){
  float2 v0 = *(const float2*)(p + (size_t)row*HD + 2*lane);
  float2 v1 = *(const float2*)(p + (size_t)row*HD + 64 + 2*lane);
  a[0]=v0.x; a[1]=v0.y; a[2]=v1.x; a[3]=v1.y;
}
__device__ __forceinline__ void strowp(const float* a, float* p, int row, int lane){
  *(float2*)(p + (size_t)row*HD + 2*lane)      = make_float2(a[0],a[1]);
  *(float2*)(p + (size_t)row*HD + 64 + 2*lane) = make_float2(a[2],a[3]);
}

// ---------------- bf16 split helpers ----------------
__device__ __forceinline__ unsigned int packbf(__nv_bfloat16 lo, __nv_bfloat16 hi){
  __nv_bfloat162 t = __halves2bfloat162(lo, hi);
  return *reinterpret_cast<unsigned int*>(&t);
}
__device__ __forceinline__ void splitbf(float f, __nv_bfloat16& h, __nv_bfloat16& l){
  h = __float2bfloat16_rn(f);
  l = __float2bfloat16_rn(f - __bfloat162float(h));
}
// store 4 floats in paired layout as split bf16 into slot
__device__ __forceinline__ void stsplit(const float* a, int slot, int row, int lane){
  unsigned int* hi = g_Ahi + (size_t)slot*NR*64 + (size_t)row*64;
  unsigned int* lo = g_Alo + (size_t)slot*NR*64 + (size_t)row*64;
  __nv_bfloat16 h0,l0,h1,l1;
  splitbf(a[0],h0,l0); splitbf(a[1],h1,l1);
  hi[lane]    = packbf(h0,h1);
  lo[lane]    = packbf(l0,l1);
  splitbf(a[2],h0,l0); splitbf(a[3],h1,l1);
  hi[32+lane] = packbf(h0,h1);
  lo[32+lane] = packbf(l0,l1);
}
#define MMA_BF16(c, a, b0, b1) \
  asm volatile("mma.sync.aligned.m16n8k16.row.col.f32.bf16.bf16.f32 " \
    "{%0,%1,%2,%3}, {%4,%5,%6,%7}, {%8,%9}, {%0,%1,%2,%3};" \
    : "+f"((c)[0]),"+f"((c)[1]),"+f"((c)[2]),"+f"((c)[3]) \
    : "r"((a)[0]),"r"((a)[1]),"r"((a)[2]),"r"((a)[3]), "r"(b0),"r"(b1))

// ---------------- k0: weight split ----------------
__global__ void __launch_bounds__(256) k_wconv(const float* __restrict__ Up_w,
    const float* __restrict__ Uf_w, const float* __restrict__ Wc_w,
    const float* __restrict__ Wq_w, const float* __restrict__ Uiou_w){
  int e = blockIdx.x*256 + threadIdx.x;
  const float* src; int off;
  if (e < OFF_UF)        { src = Up_w;   off = e - OFF_UP; }
  else if (e < OFF_WC)   { src = Uf_w;   off = e - OFF_UF; }
  else if (e < OFF_WQ)   { src = Wc_w;   off = e - OFF_WC; }
  else if (e < OFF_IOU)  { src = Wq_w;   off = e - OFF_WQ; }
  else                   { src = Uiou_w; off = e - OFF_IOU; }
  float f0 = src[(size_t)off*2], f1 = src[(size_t)off*2+1];
  __nv_bfloat16 h0,l0,h1,l1;
  splitbf(f0,h0,l0); splitbf(f1,h1,l1);
  g_Whi[e] = packbf(h0,h1);
  g_Wlo[e] = packbf(l0,l1);
}

// ---------------- k1: rowwise logmaps + pre-split A operands ----------------
__global__ void __launch_bounds__(256) k_prep(const float* __restrict__ x,
    const float* __restrict__ h1, const float* __restrict__ h2,
    const float* __restrict__ c1, const float* __restrict__ c2,
    const float* __restrict__ h3, const float* __restrict__ c3){
  int r = blockIdx.x*8 + (threadIdx.x>>5);
  int lane = threadIdx.x & 31;
  float a1[4],a2[4],b1[4],b2[4],xx[4],hh3[4],cc3[4];
  ldrowp(a1,h1,r,lane); ldrowp(a2,h2,r,lane);
  ldrowp(b1,c1,r,lane); ldrowp(b2,c2,r,lane);
  ldrowp(xx,x ,r,lane);
  ldrowp(hh3,h3,r,lane); ldrowp(cc3,c3,r,lane);
  float rv[5] = {pss<4>(a1),pss<4>(a2),pss<4>(b1),pss<4>(b2),pss<4>(xx)};
  redN<5>(rv);
  alog0<4>(a1,-1.f,rv[0]); stsplit(a1,S_A1,r,lane);
  alog0<4>(a2, 1.f,rv[1]); stsplit(a2,S_A2,r,lane);
  alog0<4>(b1,-1.f,rv[2]); stsplit(b1,S_B1,r,lane);
  alog0<4>(b2, 1.f,rv[3]); stsplit(b2,S_B2,r,lane);
  stsplit(hh3,S_H3,r,lane);
  stsplit(cc3,S_C3,r,lane);
  stsplit(xx, S_X ,r,lane);
  float xc[4];
  #pragma unroll
  for (int i=0;i<4;i++) xc[i]=xx[i];
  aexplog<4>(xc,-1.f,rv[4]); stsplit(xc,S_X1,r,lane);
  aexplog<4>(xx, 1.f,rv[4]); stsplit(xx,S_X2,r,lane);
}

// ---------------- tensor-core GEMM: pre-split A, pure-copy staging ----------------
#define KP2 20
__device__ __forceinline__ void gemm_tc_body(
    const unsigned int* __restrict__ Ah_g, const unsigned int* __restrict__ Al_g,
    const unsigned int* __restrict__ Wh_g, const unsigned int* __restrict__ Wl_g,
    const float* __restrict__ bias,
    float* __restrict__ C, int ldc, int colOff, int m0){
  __shared__ unsigned int Ah[128][KP2], Al[128][KP2], Wh[128][KP2], Wl[128][KP2];
  int tid = threadIdx.x;
  int lane = tid & 31, wid = tid >> 5;
  int warpM = wid & 3, warpN = wid >> 2;
  int gid = lane >> 2, tig = lane & 3;
  float acc[2][8][4];
  #pragma unroll
  for (int mi=0;mi<2;mi++)
    #pragma unroll
    for (int ni=0;ni<8;ni++)
      #pragma unroll
      for (int q=0;q<4;q++) acc[mi][ni][q]=0.f;
  int sr = tid>>1, hcol = (tid&1)*8;          // staging: 2 threads/row, 8 u32 each
  for (int kt=0; kt<4; kt++){                  // K chunks of 32 (16 u32 pairs)
    {
      const unsigned int* pa = Ah_g + (size_t)(m0+sr)*64 + kt*16 + hcol;
      uint4 v0 = *(const uint4*)pa, v1 = *(const uint4*)(pa+4);
      *(uint4*)&Ah[sr][hcol]   = v0;
      *(uint4*)&Ah[sr][hcol+4] = v1;
      const unsigned int* pb = Al_g + (size_t)(m0+sr)*64 + kt*16 + hcol;
      uint4 w0 = *(const uint4*)pb, w1 = *(const uint4*)(pb+4);
      *(uint4*)&Al[sr][hcol]   = w0;
      *(uint4*)&Al[sr][hcol+4] = w1;
      const unsigned int* pc = Wh_g + (size_t)sr*64 + kt*16 + hcol;
      uint4 u0 = *(const uint4*)pc, u1 = *(const uint4*)(pc+4);
      *(uint4*)&Wh[sr][hcol]   = u0;
      *(uint4*)&Wh[sr][hcol+4] = u1;
      const unsigned int* pd = Wl_g + (size_t)sr*64 + kt*16 + hcol;
      uint4 t0 = *(const uint4*)pd, t1 = *(const uint4*)(pd+4);
      *(uint4*)&Wl[sr][hcol]   = t0;
      *(uint4*)&Wl[sr][hcol+4] = t1;
    }
    __syncthreads();
    #pragma unroll
    for (int ks=0; ks<2; ks++){
      int kb = ks*8;
      unsigned int ah[2][4], al[2][4];
      #pragma unroll
      for (int mi=0;mi<2;mi++){
        int r0 = warpM*32 + mi*16 + gid;
        ah[mi][0]=Ah[r0][kb+tig];   ah[mi][1]=Ah[r0+8][kb+tig];
        ah[mi][2]=Ah[r0][kb+tig+4]; ah[mi][3]=Ah[r0+8][kb+tig+4];
        al[mi][0]=Al[r0][kb+tig];   al[mi][1]=Al[r0+8][kb+tig];
        al[mi][2]=Al[r0][kb+tig+4]; al[mi][3]=Al[r0+8][kb+tig+4];
      }
      #pragma unroll
      for (int ni=0;ni<8;ni++){
        int c0 = warpN*64 + ni*8 + gid;
        unsigned int bh0 = Wh[c0][kb+tig], bh1 = Wh[c0][kb+tig+4];
        unsigned int bl0 = Wl[c0][kb+tig], bl1 = Wl[c0][kb+tig+4];
        #pragma unroll
        for (int mi=0;mi<2;mi++){
          MMA_BF16(acc[mi][ni], ah[mi], bh0, bh1);
          MMA_BF16(acc[mi][ni], ah[mi], bl0, bl1);
          MMA_BF16(acc[mi][ni], al[mi], bh0, bh1);
        }
      }
    }
    __syncthreads();
  }
  #pragma unroll
  for (int mi=0;mi<2;mi++){
    int r = m0 + warpM*32 + mi*16 + gid;
    #pragma unroll
    for (int ni=0;ni<8;ni++){
      int c = colOff + warpN*64 + ni*8 + tig*2;
      float b0 = bias[c], b1 = bias[c+1];
      float2 v0 = make_float2(acc[mi][ni][0]+b0, acc[mi][ni][1]+b1);
      float2 v1 = make_float2(acc[mi][ni][2]+b0, acc[mi][ni][3]+b1);
      *(float2*)(C + (size_t)r*ldc + c) = v0;
      *(float2*)(C + (size_t)(r+8)*ldc + c) = v1;
    }
  }
}

__global__ void __launch_bounds__(256) k_gemm_tc(const float* __restrict__ Up_b,
    const float* __restrict__ Uf_b, const float* __restrict__ Wc_b,
    const float* __restrict__ Wq_b){
  const float* bias; float* C; int woff, slot;
  switch (blockIdx.z){
    case 0:  slot=S_A1; woff=OFF_UP; bias=Up_b; C=g_U1; break;
    case 1:  slot=S_A2; woff=OFF_UP; bias=Up_b; C=g_U2; break;
    case 2:  slot=S_H3; woff=OFF_UP; bias=Up_b; C=g_U3; break;
    case 3:  slot=S_A1; woff=OFF_UF; bias=Uf_b; C=g_F1; break;
    case 4:  slot=S_A2; woff=OFF_UF; bias=Uf_b; C=g_F2; break;
    case 5:  slot=S_H3; woff=OFF_UF; bias=Uf_b; C=g_F3; break;
    case 6:  slot=S_B1; woff=OFF_WC; bias=Wc_b; C=g_W1; break;
    case 7:  slot=S_B2; woff=OFF_WC; bias=Wc_b; C=g_W2; break;
    case 8:  slot=S_C3; woff=OFF_WC; bias=Wc_b; C=g_W3; break;
    case 9:  slot=S_X1; woff=OFF_WQ; bias=Wq_b; C=g_Q1; break;
    case 10: slot=S_X2; woff=OFF_WQ; bias=Wq_b; C=g_Q2; break;
    default: slot=S_X;  woff=OFF_WQ; bias=Wq_b; C=g_Q3; break;
  }
  gemm_tc_body(g_Ahi + (size_t)slot*NR*64, g_Alo + (size_t)slot*NR*64,
               g_Whi+woff, g_Wlo+woff, bias, C, HD, 0, blockIdx.x*128);
}

__global__ void __launch_bounds__(256) k_iou_tc(const float* __restrict__ Uiou_b){
  int slot; float* C;
  switch (blockIdx.z){
    case 0:  slot=S_T1; C=g_G1; break;
    case 1:  slot=S_T2; C=g_G2; break;
    default: slot=S_T3; C=g_G3; break;
  }
  int colOff = blockIdx.y*128;
  gemm_tc_body(g_Ahi + (size_t)slot*NR*64, g_Alo + (size_t)slot*NR*64,
               g_Whi + OFF_IOU + (size_t)colOff*64,
               g_Wlo + OFF_IOU + (size_t)colOff*64,
               Uiou_b, C, H3, colOff, blockIdx.x*128);
}

// ---------------- k3: h-path rowwise post ----------------
__global__ void __launch_bounds__(256) k_hpost(const float* __restrict__ h1,
    const float* __restrict__ h2, const float* __restrict__ h3){
  int r = blockIdx.x*8 + (threadIdx.x>>5);
  int lane = threadIdx.x & 31;

  float s1[4], s2[4], s3[4], vh1[4], vh2[4], vh3[4], q1[4], q2[4];
  ldrow(s1,g_U1,r,lane); ldrow(s2,g_U2,r,lane); ldrow(s3,g_U3,r,lane);
  ldrow(vh1,h1,r,lane);  ldrow(vh2,h2,r,lane);  ldrow(vh3,h3,r,lane);
  ldrow(q1,g_Q1,r,lane); ldrow(q2,g_Q2,r,lane);

  float rv[7] = {pss<4>(s1),pss<4>(s2),pss<4>(vh1),pss<4>(vh2),pss<4>(vh3),
                 pss<4>(q1),pss<4>(q2)};
  redN<7>(rv);
  float ssh1=rv[2], ssh2=rv[3], ssh3=rv[4];

  aexp0<4>(s1,-1.f,rv[0]);
  aexp0<4>(s2, 1.f,rv[1]);
  #pragma unroll
  for (int i=0;i<4;i++){ s1[i]=sigm(s1[i]); s2[i]=sigm(s2[i]); s3[i]=sigm(s3[i]); }
  float rv2[2] = {pss<4>(s1), pss<4>(s2)};
  redN<2>(rv2);
  alog0<4>(s1,-1.f,rv2[0]);
  alog0<4>(s2, 1.f,rv2[1]);

  float n2h = nrm(ssh2);
  float t2p = tanhf(atanf(n2h));
  float f2p = t2p/n2h;            float ssx2p = t2p*t2p;
  float n3h = nrm(ssh3);
  float t3p = fminf(tanhf(n3h), 1.f-1e-4f);
  float f3p = t3p/n3h;            float ssx3p = t3p*t3p;
  float n1h = nrm(ssh1);
  float a1t = artk(n1h,-1.f);
  float t1s = tanf(fminf(a1t, 1.47079f));
  float f1s = t1s/n1h;            float ssx1s = t1s*t1s;
  float t3s = tanf(fminf(n3h, 1.47079f));
  float f3s = t3s/n3h;            float ssx3s = t3s*t3s;

  float w1p[4],w2p[4],w3p[4],w1s[4],w2s[4],w3s[4];
  #pragma unroll
  for (int i=0;i<4;i++){
    w1p[i]=s1[i]*vh1[i];
    w2p[i]=s2[i]*vh2[i]*f2p;
    w3p[i]=s3[i]*vh3[i]*f3p;
    w1s[i]=s1[i]*vh1[i]*f1s;
    w2s[i]=s2[i]*vh2[i];
    w3s[i]=s3[i]*vh3[i]*f3s;
  }
  float rv3[6] = {pss<4>(w1p),pss<4>(w2p),pss<4>(w3p),
                  pss<4>(w1s),pss<4>(w2s),pss<4>(w3s)};
  redN<6>(rv3);
  float r1p = apw<4>(w1p,-1.f, ssh1,  rv3[0]);
  float r2p = apw<4>(w2p,-1.f, ssx2p, rv3[1]);
  float r3p = apw<4>(w3p,-1.f, ssx3p, rv3[2]);
  float r1s = apw<4>(w1s,-1.f, ssx1s, rv3[3]);
  float r2s = apw<4>(w2s, 1.f, ssh2,  rv3[4]);
  float r3s = apw<4>(w3s, 1.f, ssx3s, rv3[5]);

  float lap=2.f/(1.f-r1p), lbp=2.f/(1.f-r2p), lcp=2.f/(1.f-r3p);
  float idenp = 1.f/fmaxf(fabsf(lap+lbp+lcp-3.f), EPSF);
  float las=2.f/(1.f-r1s), lbs=2.f/(1.f-r2s), lcs=2.f/(1.f-r3s);
  float idens = 1.f/fmaxf(fabsf(las+lbs+lcs-3.f), EPSF);
  float sp[4], sv[4];
  #pragma unroll
  for (int i=0;i<4;i++){
    sp[i] = (lap*w1p[i]+lbp*w2p[i]+lcp*w3p[i])*idenp;
    sv[i] = (las*w1s[i]+lbs*w2s[i]+lcs*w3s[i])*idens;
  }
  float rv4[2] = {pss<4>(sp), pss<4>(sv)};
  redN<2>(rv4);
  float tp2 = asmul<4>(sp,0.5f,-1.f,rv4[0]);
  float ts2 = asmul<4>(sv,0.5f,-1.f,rv4[1]);
  #pragma unroll
  for (int i=0;i<4;i++){ sp[i]*=3.f; sv[i]*=3.f; }
  strow(sp,g_h1p,r,lane);
  strow(sv,g_h1s,r,lane);
  if (lane==0){ g_nhp2[r]=9.f*tp2; g_nhs2[r]=9.f*ts2; }

  float fe1 = artk(nrm(r1p),-1.f)/nrm(r1p);
  float fe2 = artk(nrm(r2s), 1.f)/nrm(r2s);
  float he[4];
  #pragma unroll
  for (int i=0;i<4;i++) he[i] = w1p[i]*fe1 + w2s[i]*fe2 + s3[i]*vh3[i];
  strow(he,g_h1e,r,lane);

  float xe1 = aexp0<4>(q1,-1.f,rv[5]); strow(q1,g_X1,r,lane);
  float xe2 = aexp0<4>(q2, 1.f,rv[6]); strow(q2,g_X2,r,lane);
  if (lane==0){ g_q1ss[r]=xe1; g_q2ss[r]=xe2; }
}

// ---------------- k4: cell-path rowwise post ----------------
__global__ void __launch_bounds__(256) k_cpost(const float* __restrict__ c1,
    const float* __restrict__ c2, const float* __restrict__ c3,
    const float* __restrict__ del_t, const float* __restrict__ dptr){
  int r = blockIdx.x*8 + (threadIdx.x>>5);
  int lane = threadIdx.x & 31;
  float g = dptr[0] / (del_t[r] + 1.f);

  float w1[4],w2[4],vc1[4],vc2[4],f1[4],f2[4];
  ldrow(w1,g_W1,r,lane); ldrow(w2,g_W2,r,lane);
  ldrow(vc1,c1,r,lane);  ldrow(vc2,c2,r,lane);
  ldrow(f1,g_F1,r,lane); ldrow(f2,g_F2,r,lane);
  float rv[6] = {pss<4>(w1),pss<4>(w2),pss<4>(vc1),pss<4>(vc2),
                 pss<4>(f1),pss<4>(f2)};
  redN<6>(rv);

  aexplog<4>(w1,-1.f,rv[0]);
  aexplog<4>(w2, 1.f,rv[1]);
  #pragma unroll
  for (int i=0;i<4;i++){ w1[i]=tanhf(w1[i]); w2[i]=tanhf(w2[i]); }
  float rv2[2] = {pss<4>(w1), pss<4>(w2)};
  redN<2>(rv2);
  float sscp = aexp0<4>(w1,-1.f,rv2[0]);
  float sscs = aexp0<4>(w2, 1.f,rv2[1]);

  float pgp[4], pgs[4];
  #pragma unroll
  for (int i=0;i<4;i++){ pgp[i]=w1[i]*g; pgs[i]=w2[i]*g; }
  float rpgp = apw<4>(pgp,-1.f, g*g, g*g*sscp);
  float rpgs = apw<4>(pgs, 1.f, g*g, g*g*sscs);

  float rv3[2] = {pdot<4>(w1,vc1), pdot<4>(w2,vc2)};
  redN<2>(rv3);
  float ca,cb,isd;
  amadd_coef(-1.f, sscp, rv[2], -rv3[0], ca, cb, isd);
  float map[4];
  #pragma unroll
  for (int i=0;i<4;i++) map[i] = (ca*(-w1[i]) + cb*vc1[i])*isd;
  amadd_coef( 1.f, sscs, rv[3], -rv3[1], ca, cb, isd);
  float mas[4];
  #pragma unroll
  for (int i=0;i<4;i++) mas[i] = (ca*(-w2[i]) + cb*vc2[i])*isd;

  float rv4[4] = {pss<4>(map), pdot<4>(map,pgp), pss<4>(mas), pdot<4>(mas,pgs)};
  redN<4>(rv4);
  {
    float n = nrm(rv4[0]);
    const float m = 1.f-1e-4f;
    if (n > m){
      float f = m/n;
      #pragma unroll
      for (int i=0;i<4;i++) map[i]*=f;
      rv4[1]*=f; rv4[0]*=f*f;
    }
  }
  amadd_coef(-1.f, rv4[0], rpgp, rv4[1], ca, cb, isd);
  float ckp[4];
  #pragma unroll
  for (int i=0;i<4;i++) ckp[i] = (ca*map[i] + cb*pgp[i])*isd;
  amadd_coef( 1.f, rv4[2], rpgs, rv4[3], ca, cb, isd);
  float cks[4];
  #pragma unroll
  for (int i=0;i<4;i++) cks[i] = (ca*mas[i] + cb*pgs[i])*isd;

  aexplog<4>(f1,-1.f,rv[4]);
  aexplog<4>(f2, 1.f,rv[5]);
  #pragma unroll
  for (int i=0;i<4;i++){ f1[i]=sigm(f1[i]); f2[i]=sigm(f2[i]); }

  float wxs[4];
  #pragma unroll
  for (int i=0;i<4;i++) wxs[i]=f2[i]*cks[i];
  float rv5[3] = {pss<4>(ckp), pss<4>(cks), pss<4>(wxs)};
  redN<3>(rv5);
  float ssckp = aproj<4>(ckp, rv5[0]);
  float wxp[4];
  #pragma unroll
  for (int i=0;i<4;i++) wxp[i]=f1[i]*ckp[i];
  float rv6[1] = {pss<4>(wxp)};
  redN<1>(rv6);
  float ryp = apw<4>(wxp,-1.f, ssckp, rv6[0]);
  float rys = apw<4>(wxs, 1.f, rv5[1], rv5[2]);
  strow(wxp,g_yp,r,lane);
  strow(wxs,g_ys,r,lane);
  if (lane==0){ g_lyp[r]=2.f/(1.f-ryp); g_lys[r]=2.f/(1.f+rys); }

  {
    float w3[4],vc3[4],f3[4];
    ldrow(w3,g_W3,r,lane); ldrow(vc3,c3,r,lane); ldrow(f3,g_F3,r,lane);
    float y[4];
    #pragma unroll
    for (int i=0;i<4;i++){
      float csk = tanhf(w3[i]);
      y[i] = sigm(f3[i])*(vc3[i] - csk + csk*g);
    }
    strow(y,g_ye,r,lane);
  }
}

// ---------------- k5: attention + K-aggregation (paired layout; split T out) ----
__global__ void __launch_bounds__(256) k_agg(const int* __restrict__ nbr){
  int n = blockIdx.x*8 + (threadIdx.x>>5);
  int lane = threadIdx.x & 31;
  int j[KN];
  #pragma unroll
  for (int k=0;k<KN;k++) j[k] = nbr[n*KN+k];

  float nump[4], nums[4], nume[4];
  { // Poincare hyp attention
    float q[4]; ldrowp(q,g_X1,n,lane);
    float q2 = g_q1ss[n];
    float yk[KN][4], y2k[KN], d[KN];
    #pragma unroll
    for (int k=0;k<KN;k++){
      ldrowp(yk[k], g_h1p, j[k], lane);
      y2k[k] = g_nhp2[j[k]];
      d[k] = pdot<4>(q, yk[k]);
    }
    redN<KN>(d);
    float sc[KN];
    #pragma unroll
    for (int k=0;k<KN;k++) sc[k] = -distf(q2, y2k[k], d[k], -1.f);
    float m = sc[0];
    #pragma unroll
    for (int k=1;k<KN;k++) m = fmaxf(m, sc[k]);
    float ssum = 0.f;
    #pragma unroll
    for (int k=0;k<KN;k++){ sc[k] = expf(sc[k]-m); ssum += sc[k]; }
    float den = 0.f;
    #pragma unroll
    for (int i=0;i<4;i++) nump[i]=0.f;
    #pragma unroll
    for (int k=0;k<KN;k++){
      float a = sc[k]/ssum;
      float lam = 2.f/(1.f - y2k[k]);
      #pragma unroll
      for (int i=0;i<4;i++) nump[i] += a*lam*yk[k][i];
      den += a*(lam-1.f);
    }
    float iden = 1.f/fmaxf(fabsf(den), EPSF);
    #pragma unroll
    for (int i=0;i<4;i++) nump[i]*=iden;
  }
  { // Sphere hyp attention
    float q[4]; ldrowp(q,g_X2,n,lane);
    float q2 = g_q2ss[n];
    float yk[KN][4], y2k[KN], d[KN];
    #pragma unroll
    for (int k=0;k<KN;k++){
      ldrowp(yk[k], g_h1s, j[k], lane);
      y2k[k] = g_nhs2[j[k]];
      d[k] = pdot<4>(q, yk[k]);
    }
    redN<KN>(d);
    float sc[KN];
    #pragma unroll
    for (int k=0;k<KN;k++) sc[k] = -distf(q2, y2k[k], d[k], 1.f);
    float m = sc[0];
    #pragma unroll
    for (int k=1;k<KN;k++) m = fmaxf(m, sc[k]);
    float ssum = 0.f;
    #pragma unroll
    for (int k=0;k<KN;k++){ sc[k] = expf(sc[k]-m); ssum += sc[k]; }
    float den = 0.f;
    #pragma unroll
    for (int i=0;i<4;i++) nums[i]=0.f;
    #pragma unroll
    for (int k=0;k<KN;k++){
      float a = sc[k]/ssum;
      float lam = 2.f/(1.f + y2k[k]);
      #pragma unroll
      for (int i=0;i<4;i++) nums[i] += a*lam*yk[k][i];
      den += a*(lam-1.f);
    }
    float iden = 1.f/fmaxf(fabsf(den), EPSF);
    #pragma unroll
    for (int i=0;i<4;i++) nums[i]*=iden;
  }
  { // Euclid attention
    float q[4]; ldrowp(q,g_Q3,n,lane);
    float yk[KN][4], d[KN];
    #pragma unroll
    for (int k=0;k<KN;k++){
      ldrowp(yk[k], g_h1e, j[k], lane);
      d[k] = pdot<4>(q, yk[k]);
    }
    redN<KN>(d);
    float sc[KN];
    #pragma unroll
    for (int k=0;k<KN;k++) sc[k] = d[k]*0.08838834764831845f;
    float m = sc[0];
    #pragma unroll
    for (int k=1;k<KN;k++) m = fmaxf(m, sc[k]);
    float ssum = 0.f;
    #pragma unroll
    for (int k=0;k<KN;k++){ sc[k] = expf(sc[k]-m); ssum += sc[k]; }
    #pragma unroll
    for (int i=0;i<4;i++) nume[i]=0.f;
    #pragma unroll
    for (int k=0;k<KN;k++){
      float a = sc[k]/ssum;
      #pragma unroll
      for (int i=0;i<4;i++) nume[i] += a*yk[k][i];
    }
  }
  // cell aggregation
  float np[4]={0,0,0,0}, ns[4]={0,0,0,0}, ne[4]={0,0,0,0};
  float dp=0.f, ds=0.f;
  #pragma unroll
  for (int k=0;k<KN;k++){
    float y[4];
    ldrowp(y, g_yp, j[k], lane);
    float lam = g_lyp[j[k]];
    #pragma unroll
    for (int i=0;i<4;i++) np[i] += lam*y[i];
    dp += lam-1.f;
    ldrowp(y, g_ys, j[k], lane);
    lam = g_lys[j[k]];
    #pragma unroll
    for (int i=0;i<4;i++) ns[i] += lam*y[i];
    ds += lam-1.f;
    ldrowp(y, g_ye, j[k], lane);
    #pragma unroll
    for (int i=0;i<4;i++) ne[i] += y[i];
  }
  float idp = 1.f/fmaxf(fabsf(dp), EPSF);
  float ids = 1.f/fmaxf(fabsf(ds), EPSF);
  #pragma unroll
  for (int i=0;i<4;i++){ np[i]*=idp; ns[i]*=ids; }

  float rv[4] = {pss<4>(nump), pss<4>(nums), pss<4>(np), pss<4>(ns)};
  redN<4>(rv);
  float ssT1 = asmul<4>(nump,0.5f,-1.f,rv[0]);
  alog0<4>(nump,-1.f,ssT1);
  stsplit(nump,S_T1,n,lane);
  float ssT2 = asmul<4>(nums,0.5f, 1.f,rv[1]);
  alog0<4>(nums, 1.f,ssT2);
  stsplit(nums,S_T2,n,lane);
  stsplit(nume,S_T3,n,lane);
  float ssc1 = asmul<4>(np,0.5f,-1.f,rv[2]);
  float ssc2 = asmul<4>(ns,0.5f, 1.f,rv[3]);
  strowp(np,g_c1v,n,lane);
  strowp(ns,g_c2v,n,lane);
  strowp(ne,g_c3v,n,lane);
  if (lane==0){ g_c1vss[n]=ssc1; g_c2vss[n]=ssc2; }
}

// ---------------- k7: apply_node_func ----------------
__global__ void __launch_bounds__(256) k_final(const float* __restrict__ iou1,
    const float* __restrict__ iou2, const float* __restrict__ iou3,
    float* __restrict__ out){
  int r = blockIdx.x*8 + (threadIdx.x>>5);
  int lane = threadIdx.x & 31;

  float e1[12], a1[12], e2[12], a2[12];
  #pragma unroll
  for (int i=0;i<12;i++){
    e1[i] = g_G1[(size_t)r*H3 + i*32 + lane];
    a1[i] = iou1[(size_t)r*H3 + i*32 + lane];
    e2[i] = g_G2[(size_t)r*H3 + i*32 + lane];
    a2[i] = iou2[(size_t)r*H3 + i*32 + lane];
  }
  float rv[4] = {pss<12>(e1), pss<12>(a1), pss<12>(e2), pss<12>(a2)};
  redN<4>(rv);
  float sse1 = aexp0<12>(e1,-1.f,rv[0]);
  float sse2 = aexp0<12>(e2, 1.f,rv[2]);
  float rv2[2] = {pdot<12>(a1,e1), pdot<12>(a2,e2)};
  redN<2>(rv2);
  float ca,cb,isd;
  float nio1[12], nio2[12];
  amadd_coef(-1.f, rv[1], sse1, rv2[0], ca, cb, isd);
  #pragma unroll
  for (int i=0;i<12;i++) nio1[i] = (ca*a1[i] + cb*e1[i])*isd;
  amadd_coef( 1.f, rv[3], sse2, rv2[1], ca, cb, isd);
  #pragma unroll
  for (int i=0;i<12;i++) nio2[i] = (ca*a2[i] + cb*e2[i])*isd;

  float rv3[7] = {pss<12>(nio1),
                  pss<4>(nio1), pss<4>(nio1+4), pss<4>(nio1+8),
                  pss<4>(nio2), pss<4>(nio2+4), pss<4>(nio2+8)};
  redN<7>(rv3);
  {
    float nn = nrm(rv3[0]);
    const float m = 1.f-1e-4f;
    if (nn > m){
      float f = m/nn;
      #pragma unroll
      for (int i=0;i<12;i++) nio1[i]*=f;
      rv3[1]*=f*f; rv3[2]*=f*f; rv3[3]*=f*f;
    }
  }
  float ip1[4], op1[4], up1[4], ip2[4], op2[4], up2[4];
  {
    float fi = artk(nrm(rv3[1]),-1.f)/nrm(rv3[1]);
    float fo = artk(nrm(rv3[2]),-1.f)/nrm(rv3[2]);
    float fu = artk(nrm(rv3[3]),-1.f)/nrm(rv3[3]);
    #pragma unroll
    for (int i=0;i<4;i++){
      ip1[i]=sigm(nio1[i]*fi); op1[i]=sigm(nio1[4+i]*fo); up1[i]=tanhf(nio1[8+i]*fu);
    }
    fi = artk(nrm(rv3[4]),1.f)/nrm(rv3[4]);
    fo = artk(nrm(rv3[5]),1.f)/nrm(rv3[5]);
    fu = artk(nrm(rv3[6]),1.f)/nrm(rv3[6]);
    #pragma unroll
    for (int i=0;i<4;i++){
      ip2[i]=sigm(nio2[i]*fi); op2[i]=sigm(nio2[4+i]*fo); up2[i]=tanhf(nio2[8+i]*fu);
    }
  }
  float wx1[4], wx2[4];
  #pragma unroll
  for (int i=0;i<4;i++){ wx1[i]=ip1[i]*up1[i]; wx2[i]=ip2[i]*up2[i]; }
  float rv4[4] = {pss<4>(wx1), pss<4>(up1), pss<4>(wx2), pss<4>(up2)};
  redN<4>(rv4);
  float rpw1 = apw<4>(wx1,-1.f, rv4[1], rv4[0]);
  float rpw2 = apw<4>(wx2, 1.f, rv4[3], rv4[2]);

  float cv1[4], cv2[4];
  ldrow(cv1,g_c1v,r,lane); ldrow(cv2,g_c2v,r,lane);
  float y21 = g_c1vss[r], y22 = g_c2vss[r];
  float rv5[2] = {pdot<4>(wx1,cv1), pdot<4>(wx2,cv2)};
  redN<2>(rv5);
  float nc1[4], nc2[4];
  amadd_coef(-1.f, rpw1, y21, rv5[0], ca, cb, isd);
  #pragma unroll
  for (int i=0;i<4;i++) nc1[i] = (ca*wx1[i] + cb*cv1[i])*isd;
  amadd_coef( 1.f, rpw2, y22, rv5[1], ca, cb, isd);
  #pragma unroll
  for (int i=0;i<4;i++) nc2[i] = (ca*wx2[i] + cb*cv2[i])*isd;

  float rv6[2] = {pss<4>(nc1), pss<4>(nc2)};
  redN<2>(rv6);
  float ssnc1 = aproj<4>(nc1, rv6[0]);
  strow(nc1, out + (size_t)1*NR*HD, r, lane);
  strow(nc2, out + (size_t)3*NR*HD, r, lane);

  float lg1[4], lg2[4];
  {
    float f1 = artk(nrm(ssnc1),-1.f)/nrm(ssnc1);
    float f2 = artk(nrm(rv6[1]), 1.f)/nrm(rv6[1]);
    #pragma unroll
    for (int i=0;i<4;i++){ lg1[i]=tanhf(nc1[i]*f1); lg2[i]=tanhf(nc2[i]*f2); }
  }
  float wy1[4], wy2[4];
  #pragma unroll
  for (int i=0;i<4;i++){ wy1[i]=op1[i]*lg1[i]; wy2[i]=op2[i]*lg2[i]; }
  float rv7[4] = {pss<4>(lg1), pss<4>(wy1), pss<4>(lg2), pss<4>(wy2)};
  redN<4>(rv7);
  apw<4>(wy1,-1.f, rv7[0], rv7[1]);
  strow(wy1, out + (size_t)0*NR*HD, r, lane);
  apw<4>(wy2, 1.f, rv7[2], rv7[3]);
  strow(wy2, out + (size_t)2*NR*HD, r, lane);

  {
    float cv[4]; ldrow(cv, g_c3v, r, lane);
    #pragma unroll
    for (int i=0;i<4;i++){
      float ie = sigm(iou3[(size_t)r*H3 + i*32 + lane]       + g_G3[(size_t)r*H3 + i*32 + lane]);
      float oe = sigm(iou3[(size_t)r*H3 + 128 + i*32 + lane] + g_G3[(size_t)r*H3 + 128 + i*32 + lane]);
      float ue = tanhf(iou3[(size_t)r*H3 + 256 + i*32 + lane] + g_G3[(size_t)r*H3 + 256 + i*32 + lane]);
      float nc = ie*ue + cv[i];
      out[(size_t)5*NR*HD + (size_t)r*HD + i*32 + lane] = nc;
      out[(size_t)4*NR*HD + (size_t)r*HD + i*32 + lane] = oe*tanhf(nc);
    }
  }
}

// ---------------- launch ----------------
extern "C" void kernel_launch(void* const* d_in, const int* in_sizes, int n_in,
                              void* d_out, int out_size){
  const float* x     = (const float*)d_in[0];
  const float* h1    = (const float*)d_in[1];
  const float* c1    = (const float*)d_in[2];
  const float* h2    = (const float*)d_in[3];
  const float* c2    = (const float*)d_in[4];
  const float* h3    = (const float*)d_in[5];
  const float* c3    = (const float*)d_in[6];
  const float* del_t = (const float*)d_in[7];
  const float* iou1  = (const float*)d_in[8];
  const float* iou2  = (const float*)d_in[9];
  const float* iou3  = (const float*)d_in[10];
  const float* Wq_w  = (const float*)d_in[11];
  const float* Wq_b  = (const float*)d_in[12];
  const float* Wc_w  = (const float*)d_in[13];
  const float* Wc_b  = (const float*)d_in[14];
  const float* Uf_w  = (const float*)d_in[15];
  const float* Uf_b  = (const float*)d_in[16];
  const float* Up_w  = (const float*)d_in[17];
  const float* Up_b  = (const float*)d_in[18];
  const float* Uiou_w= (const float*)d_in[19];
  const float* Uiou_b= (const float*)d_in[20];
  const float* dsc   = (const float*)d_in[21];
  const int*   nbr   = (const int*)d_in[22];
  float* out = (float*)d_out;

  dim3 blk(256);
  k_wconv<<<WPK_TOT/256, blk>>>(Up_w, Uf_w, Wc_w, Wq_w, Uiou_w);
  k_prep<<<NR/8, blk>>>(x, h1, h2, c1, c2, h3, c3);
  k_gemm_tc<<<dim3(NR/128, 1, 12), blk>>>(Up_b, Uf_b, Wc_b, Wq_b);
  k_hpost<<<NR/8, blk>>>(h1, h2, h3);
  k_cpost<<<NR/8, blk>>>(c1, c2, c3, del_t, dsc);
  k_agg<<<NR/8, blk>>>(nbr);
  k_iou_tc<<<dim3(NR/128, 3, 3), blk>>>(Uiou_b);
  k_final<<<NR/8, blk>>>(iou1, iou2, iou3, out);
}

// round 10
// speedup vs baseline: 1.1508x; 1.1508x over previous
#include <cuda_runtime.h>
#include <cuda_bf16.h>
#include <math.h>

#define NR 8192
#define HD 128
#define KN 8
#define H3 384
#define EPSF 1e-6f

// ---------------- scratch ----------------
__device__ float g_A1[NR*HD], g_A2[NR*HD], g_B1[NR*HD], g_B2[NR*HD], g_X1[NR*HD], g_X2[NR*HD];
__device__ float g_U1[NR*HD], g_U2[NR*HD], g_U3[NR*HD];
__device__ float g_F1[NR*HD], g_F2[NR*HD], g_F3[NR*HD];
__device__ float g_W1[NR*HD], g_W2[NR*HD], g_W3[NR*HD];
__device__ float g_Q1[NR*HD], g_Q2[NR*HD], g_Q3[NR*HD];
__device__ float g_h1p[NR*HD], g_h1s[NR*HD], g_h1e[NR*HD];
__device__ float g_yp[NR*HD], g_ys[NR*HD], g_ye[NR*HD];
__device__ float g_nhp2[NR], g_nhs2[NR], g_lyp[NR], g_lys[NR];
__device__ float g_q1ss[NR], g_q2ss[NR], g_c1vss[NR], g_c2vss[NR];
__device__ float g_T1[NR*HD], g_T2[NR*HD], g_T3[NR*HD];
__device__ float g_c1v[NR*HD], g_c2v[NR*HD], g_c3v[NR*HD];
__device__ float g_G1[NR*H3], g_G2[NR*H3], g_G3[NR*H3];

// packed bf16 hi/lo weights
#define OFF_UP 0
#define OFF_UF 8192
#define OFF_WC 16384
#define OFF_WQ 24576
#define OFF_IOU 32768
#define WPK_TOT 57344
__device__ unsigned int g_Whi[WPK_TOT], g_Wlo[WPK_TOT];

// ---------------- fast transcendentals ----------------
__device__ __forceinline__ float fexp(float x){ return __expf(x); }
__device__ __forceinline__ float sigm(float v){
  return __fdividef(1.f, 1.f + __expf(-v));
}
__device__ __forceinline__ float ftanh(float v){
  return fmaf(2.f, __fdividef(1.f, 1.f + __expf(-2.f*v)), -1.f);
}
__device__ __forceinline__ float fatanh(float u){
  return 0.5f*__logf(__fdividef(1.f+u, 1.f-u));
}
__device__ __forceinline__ float artk(float u, float k){
  if (k < 0.f){ u = fminf(fmaxf(u, -1.f+1e-5f), 1.f-1e-5f); return fatanh(u); }
  return atanf(u);
}
__device__ __forceinline__ float tank(float u, float k){
  if (k < 0.f) return ftanh(u);
  return __tanf(fminf(fmaxf(u, -1.47079f), 1.47079f));
}
__device__ __forceinline__ float sden(float d){
  return d >= 0.f ? fmaxf(d, EPSF) : fminf(d, -EPSF);
}
__device__ __forceinline__ float nrm(float ss){ return sqrtf(ss + 1e-15f); }

// ---------------- reductions ----------------
template<int N> __device__ __forceinline__ void redN(float* v){
  #pragma unroll
  for (int o=16;o;o>>=1){
    float t[N];
    #pragma unroll
    for (int i=0;i<N;i++) t[i] = __shfl_xor_sync(0xffffffffu, v[i], o);
    #pragma unroll
    for (int i=0;i<N;i++) v[i] += t[i];
  }
}
template<int V> __device__ __forceinline__ float pdot(const float* a, const float* b){
  float s = 0.f;
  #pragma unroll
  for (int i=0;i<V;i++) s += a[i]*b[i];
  return s;
}
template<int V> __device__ __forceinline__ float pss(const float* a){ return pdot<V>(a,a); }

// ---------------- analytic (norm-tracked) manifold ops ----------------
template<int V> __device__ __forceinline__ void vscale(float* a, float f){
  #pragma unroll
  for (int i=0;i<V;i++) a[i]*=f;
}
template<int V> __device__ __forceinline__ float aexp0(float* a, float k, float ss){
  float n = nrm(ss);
  float t = tank(n,k);
  if (k < 0.f) t = fminf(t, 1.f-1e-4f);
  vscale<V>(a, __fdividef(t,n));
  return t*t;
}
template<int V> __device__ __forceinline__ float alog0(float* a, float k, float ss){
  float n = nrm(ss);
  float t = artk(n,k);
  vscale<V>(a, __fdividef(t,n));
  return t*t;
}
template<int V> __device__ __forceinline__ float aexplog(float* a, float k, float ss){
  float n = nrm(ss);
  float t;
  if (k < 0.f) t = fatanh(fminf(ftanh(n), 1.f-1e-4f));
  else         t = fminf(n, 1.47079f);
  vscale<V>(a, __fdividef(t,n));
  return t*t;
}
template<int V> __device__ __forceinline__ float asmul(float* a, float r, float k, float ss){
  float n = nrm(ss);
  float t = tank(r*artk(n,k),k);
  if (k < 0.f) t = fminf(t, 1.f-1e-4f);
  vscale<V>(a, __fdividef(t,n));
  return t*t;
}
template<int V> __device__ __forceinline__ float apw(float* wx, float k, float ssx, float ssw){
  float nx = nrm(ssx), nwx = nrm(ssw);
  float t = tank(__fdividef(nwx,nx)*artk(nx,k),k);
  if (k < 0.f) t = fminf(t, 1.f-1e-4f);
  vscale<V>(wx, __fdividef(t,nwx));
  return t*t;
}
template<int V> __device__ __forceinline__ float aproj(float* a, float ss){
  float n = nrm(ss);
  const float m = 1.f-1e-4f;
  if (n > m){ float f = __fdividef(m,n); vscale<V>(a, f); return ss*f*f; }
  return ss;
}
__device__ __forceinline__ void amadd_coef(float k, float x2, float y2, float xy,
                                           float& ca, float& cb, float& isd){
  ca = 1.f - 2.f*k*xy - k*y2;
  cb = 1.f + k*x2;
  isd = __fdividef(1.f, sden(1.f - 2.f*k*xy + k*k*x2*y2));
}
__device__ __forceinline__ float distf(float x2, float y2, float xy, float k){
  float ca = 1.f + 2.f*k*xy - k*y2;
  float cb = 1.f + k*x2;
  float sd = sden(1.f + 2.f*k*xy + k*k*x2*y2);
  float s = fmaxf(ca*ca*x2 + cb*cb*y2 - 2.f*ca*cb*xy, 0.f);
  float nv2 = __fdividef(s, sd*sd);
  float pn = sqrtf(nv2 + 1e-15f);
  if (k < 0.f){
    const float m = 1.f - 1e-4f;
    if (pn > m){ float sc = __fdividef(m,pn); pn = sqrtf(nv2*sc*sc + 1e-15f); }
  }
  return 2.f*artk(pn, k);
}
__device__ __forceinline__ void ldrow(float* a, const float* p, int row, int lane){
  #pragma unroll
  for (int i=0;i<4;i++) a[i] = p[(size_t)row*HD + i*32 + lane];
}
__device__ __forceinline__ void strow(const float* a, float* p, int row, int lane){
  #pragma unroll
  for (int i=0;i<4;i++) p[(size_t)row*HD + i*32 + lane] = a[i];
}

// ---------------- bf16 split helpers ----------------
__device__ __forceinline__ unsigned int packbf(__nv_bfloat16 lo, __nv_bfloat16 hi){
  __nv_bfloat162 t = __halves2bfloat162(lo, hi);
  return *reinterpret_cast<unsigned int*>(&t);
}
__device__ __forceinline__ void splitbf(float f, __nv_bfloat16& h, __nv_bfloat16& l){
  h = __float2bfloat16_rn(f);
  l = __float2bfloat16_rn(f - __bfloat162float(h));
}
#define MMA_BF16(c, a, b0, b1) \
  asm volatile("mma.sync.aligned.m16n8k16.row.col.f32.bf16.bf16.f32 " \
    "{%0,%1,%2,%3}, {%4,%5,%6,%7}, {%8,%9}, {%0,%1,%2,%3};" \
    : "+f"((c)[0]),"+f"((c)[1]),"+f"((c)[2]),"+f"((c)[3]) \
    : "r"((a)[0]),"r"((a)[1]),"r"((a)[2]),"r"((a)[3]), "r"(b0),"r"(b1))

// ---------------- k0: weight split ----------------
__global__ void __launch_bounds__(256) k_wconv(const float* __restrict__ Up_w,
    const float* __restrict__ Uf_w, const float* __restrict__ Wc_w,
    const float* __restrict__ Wq_w, const float* __restrict__ Uiou_w){
  int e = blockIdx.x*256 + threadIdx.x;
  const float* src; int off;
  if (e < OFF_UF)        { src = Up_w;   off = e - OFF_UP; }
  else if (e < OFF_WC)   { src = Uf_w;   off = e - OFF_UF; }
  else if (e < OFF_WQ)   { src = Wc_w;   off = e - OFF_WC; }
  else if (e < OFF_IOU)  { src = Wq_w;   off = e - OFF_WQ; }
  else                   { src = Uiou_w; off = e - OFF_IOU; }
  float f0 = src[(size_t)off*2], f1 = src[(size_t)off*2+1];
  __nv_bfloat16 h0,l0,h1,l1;
  splitbf(f0,h0,l0); splitbf(f1,h1,l1);
  g_Whi[e] = packbf(h0,h1);
  g_Wlo[e] = packbf(l0,l1);
}

// ---------------- k1: rowwise logmaps feeding GEMMs ----------------
__global__ void __launch_bounds__(256) k_prep(const float* __restrict__ x,
    const float* __restrict__ h1, const float* __restrict__ h2,
    const float* __restrict__ c1, const float* __restrict__ c2){
  int r = blockIdx.x*8 + (threadIdx.x>>5);
  int lane = threadIdx.x & 31;
  float a1[4],a2[4],b1[4],b2[4],xx[4];
  ldrow(a1,h1,r,lane); ldrow(a2,h2,r,lane);
  ldrow(b1,c1,r,lane); ldrow(b2,c2,r,lane);
  ldrow(xx,x ,r,lane);
  float rv[5] = {pss<4>(a1),pss<4>(a2),pss<4>(b1),pss<4>(b2),pss<4>(xx)};
  redN<5>(rv);
  alog0<4>(a1,-1.f,rv[0]); strow(a1,g_A1,r,lane);
  alog0<4>(a2, 1.f,rv[1]); strow(a2,g_A2,r,lane);
  alog0<4>(b1,-1.f,rv[2]); strow(b1,g_B1,r,lane);
  alog0<4>(b2, 1.f,rv[3]); strow(b2,g_B2,r,lane);
  float xc[4];
  #pragma unroll
  for (int i=0;i<4;i++) xc[i]=xx[i];
  aexplog<4>(xc,-1.f,rv[4]); strow(xc,g_X1,r,lane);
  aexplog<4>(xx, 1.f,rv[4]); strow(xx,g_X2,r,lane);
}

// ---------------- tensor-core GEMM with register-prefetch pipeline ----------------
#define KP2 20
__device__ __forceinline__ void gemm_tc_body(
    const float* __restrict__ A, const unsigned int* __restrict__ Wh_g,
    const unsigned int* __restrict__ Wl_g, const float* __restrict__ bias,
    float* __restrict__ C, int ldc, int colOff, int m0){
  __shared__ unsigned int Ah[128][KP2], Al[128][KP2], Wh[128][KP2], Wl[128][KP2];
  int tid = threadIdx.x;
  int lane = tid & 31, wid = tid >> 5;
  int warpM = wid & 3, warpN = wid >> 2;
  int gid = lane >> 2, tig = lane & 3;
  float acc[2][8][4];
  #pragma unroll
  for (int mi=0;mi<2;mi++)
    #pragma unroll
    for (int ni=0;ni<8;ni++)
      #pragma unroll
      for (int q=0;q<4;q++) acc[mi][ni][q]=0.f;

  int ar = (tid>>3), akq = (tid&7)*4;        // A staging coords
  int wr = (tid>>2), wkq = (tid&3)*4;        // W staging coords
  float4 av[4]; uint4 whv[2], wlv[2];
  // prefetch chunk 0
  #pragma unroll
  for (int p=0;p<4;p++)
    av[p] = *(const float4*)(A + (size_t)(m0+ar+p*32)*HD + akq);
  #pragma unroll
  for (int t=0;t<2;t++){
    whv[t] = *(const uint4*)(Wh_g + (size_t)(wr+t*64)*64 + wkq);
    wlv[t] = *(const uint4*)(Wl_g + (size_t)(wr+t*64)*64 + wkq);
  }

  for (int c=0; c<4; c++){
    // commit staged regs to smem
    #pragma unroll
    for (int p=0;p<4;p++){
      int rr = ar + p*32;
      __nv_bfloat16 h0,l0,h1,l1;
      splitbf(av[p].x,h0,l0); splitbf(av[p].y,h1,l1);
      Ah[rr][(akq>>1)  ] = packbf(h0,h1);
      Al[rr][(akq>>1)  ] = packbf(l0,l1);
      splitbf(av[p].z,h0,l0); splitbf(av[p].w,h1,l1);
      Ah[rr][(akq>>1)+1] = packbf(h0,h1);
      Al[rr][(akq>>1)+1] = packbf(l0,l1);
    }
    #pragma unroll
    for (int t=0;t<2;t++){
      *(uint4*)&Wh[wr+t*64][wkq] = whv[t];
      *(uint4*)&Wl[wr+t*64][wkq] = wlv[t];
    }
    __syncthreads();
    // prefetch next chunk while computing this one
    if (c < 3){
      int kt = (c+1)*32;
      #pragma unroll
      for (int p=0;p<4;p++)
        av[p] = *(const float4*)(A + (size_t)(m0+ar+p*32)*HD + kt + akq);
      #pragma unroll
      for (int t=0;t<2;t++){
        whv[t] = *(const uint4*)(Wh_g + (size_t)(wr+t*64)*64 + (kt>>1) + wkq);
        wlv[t] = *(const uint4*)(Wl_g + (size_t)(wr+t*64)*64 + (kt>>1) + wkq);
      }
    }
    #pragma unroll
    for (int ks=0; ks<2; ks++){
      int kb = ks*8;
      unsigned int ah[2][4], al[2][4];
      #pragma unroll
      for (int mi=0;mi<2;mi++){
        int r0 = warpM*32 + mi*16 + gid;
        ah[mi][0]=Ah[r0][kb+tig];   ah[mi][1]=Ah[r0+8][kb+tig];
        ah[mi][2]=Ah[r0][kb+tig+4]; ah[mi][3]=Ah[r0+8][kb+tig+4];
        al[mi][0]=Al[r0][kb+tig];   al[mi][1]=Al[r0+8][kb+tig];
        al[mi][2]=Al[r0][kb+tig+4]; al[mi][3]=Al[r0+8][kb+tig+4];
      }
      #pragma unroll
      for (int ni=0;ni<8;ni++){
        int c0 = warpN*64 + ni*8 + gid;
        unsigned int bh0 = Wh[c0][kb+tig], bh1 = Wh[c0][kb+tig+4];
        unsigned int bl0 = Wl[c0][kb+tig], bl1 = Wl[c0][kb+tig+4];
        #pragma unroll
        for (int mi=0;mi<2;mi++){
          MMA_BF16(acc[mi][ni], ah[mi], bh0, bh1);
          MMA_BF16(acc[mi][ni], ah[mi], bl0, bl1);
          MMA_BF16(acc[mi][ni], al[mi], bh0, bh1);
        }
      }
    }
    __syncthreads();
  }
  #pragma unroll
  for (int mi=0;mi<2;mi++){
    int r = m0 + warpM*32 + mi*16 + gid;
    #pragma unroll
    for (int ni=0;ni<8;ni++){
      int c = colOff + warpN*64 + ni*8 + tig*2;
      float b0 = bias[c], b1 = bias[c+1];
      float2 v0 = make_float2(acc[mi][ni][0]+b0, acc[mi][ni][1]+b1);
      float2 v1 = make_float2(acc[mi][ni][2]+b0, acc[mi][ni][3]+b1);
      *(float2*)(C + (size_t)r*ldc + c) = v0;
      *(float2*)(C + (size_t)(r+8)*ldc + c) = v1;
    }
  }
}

__global__ void __launch_bounds__(256) k_gemm_tc(const float* __restrict__ x,
    const float* __restrict__ h3, const float* __restrict__ c3,
    const float* __restrict__ Up_b, const float* __restrict__ Uf_b,
    const float* __restrict__ Wc_b, const float* __restrict__ Wq_b){
  const float *A, *bias; float* C; int woff;
  switch (blockIdx.z){
    case 0:  A=g_A1; woff=OFF_UP; bias=Up_b; C=g_U1; break;
    case 1:  A=g_A2; woff=OFF_UP; bias=Up_b; C=g_U2; break;
    case 2:  A=h3;   woff=OFF_UP; bias=Up_b; C=g_U3; break;
    case 3:  A=g_A1; woff=OFF_UF; bias=Uf_b; C=g_F1; break;
    case 4:  A=g_A2; woff=OFF_UF; bias=Uf_b; C=g_F2; break;
    case 5:  A=h3;   woff=OFF_UF; bias=Uf_b; C=g_F3; break;
    case 6:  A=g_B1; woff=OFF_WC; bias=Wc_b; C=g_W1; break;
    case 7:  A=g_B2; woff=OFF_WC; bias=Wc_b; C=g_W2; break;
    case 8:  A=c3;   woff=OFF_WC; bias=Wc_b; C=g_W3; break;
    case 9:  A=g_X1; woff=OFF_WQ; bias=Wq_b; C=g_Q1; break;
    case 10: A=g_X2; woff=OFF_WQ; bias=Wq_b; C=g_Q2; break;
    default: A=x;    woff=OFF_WQ; bias=Wq_b; C=g_Q3; break;
  }
  gemm_tc_body(A, g_Whi+woff, g_Wlo+woff, bias, C, HD, 0, blockIdx.x*128);
}

__global__ void __launch_bounds__(256) k_iou_tc(const float* __restrict__ Uiou_b){
  const float* A; float* C;
  switch (blockIdx.z){
    case 0:  A=g_T1; C=g_G1; break;
    case 1:  A=g_T2; C=g_G2; break;
    default: A=g_T3; C=g_G3; break;
  }
  int colOff = blockIdx.y*128;
  gemm_tc_body(A, g_Whi + OFF_IOU + (size_t)colOff*64,
               g_Wlo + OFF_IOU + (size_t)colOff*64,
               Uiou_b, C, H3, colOff, blockIdx.x*128);
}

// ---------------- k3: h-path rowwise post ----------------
__global__ void __launch_bounds__(256) k_hpost(const float* __restrict__ h1,
    const float* __restrict__ h2, const float* __restrict__ h3){
  int r = blockIdx.x*8 + (threadIdx.x>>5);
  int lane = threadIdx.x & 31;

  float s1[4], s2[4], s3[4], vh1[4], vh2[4], vh3[4], q1[4], q2[4];
  ldrow(s1,g_U1,r,lane); ldrow(s2,g_U2,r,lane); ldrow(s3,g_U3,r,lane);
  ldrow(vh1,h1,r,lane);  ldrow(vh2,h2,r,lane);  ldrow(vh3,h3,r,lane);
  ldrow(q1,g_Q1,r,lane); ldrow(q2,g_Q2,r,lane);

  float rv[7] = {pss<4>(s1),pss<4>(s2),pss<4>(vh1),pss<4>(vh2),pss<4>(vh3),
                 pss<4>(q1),pss<4>(q2)};
  redN<7>(rv);
  float ssh1=rv[2], ssh2=rv[3], ssh3=rv[4];

  aexp0<4>(s1,-1.f,rv[0]);
  aexp0<4>(s2, 1.f,rv[1]);
  #pragma unroll
  for (int i=0;i<4;i++){ s1[i]=sigm(s1[i]); s2[i]=sigm(s2[i]); s3[i]=sigm(s3[i]); }
  float rv2[2] = {pss<4>(s1), pss<4>(s2)};
  redN<2>(rv2);
  alog0<4>(s1,-1.f,rv2[0]);
  alog0<4>(s2, 1.f,rv2[1]);

  float n2h = nrm(ssh2);
  float t2p = ftanh(atanf(n2h));
  float f2p = __fdividef(t2p,n2h);  float ssx2p = t2p*t2p;
  float n3h = nrm(ssh3);
  float t3p = fminf(ftanh(n3h), 1.f-1e-4f);
  float f3p = __fdividef(t3p,n3h);  float ssx3p = t3p*t3p;
  float n1h = nrm(ssh1);
  float a1t = artk(n1h,-1.f);
  float t1s = __tanf(fminf(a1t, 1.47079f));
  float f1s = __fdividef(t1s,n1h);  float ssx1s = t1s*t1s;
  float t3s = __tanf(fminf(n3h, 1.47079f));
  float f3s = __fdividef(t3s,n3h);  float ssx3s = t3s*t3s;

  float w1p[4],w2p[4],w3p[4],w1s[4],w2s[4],w3s[4];
  #pragma unroll
  for (int i=0;i<4;i++){
    w1p[i]=s1[i]*vh1[i];
    w2p[i]=s2[i]*vh2[i]*f2p;
    w3p[i]=s3[i]*vh3[i]*f3p;
    w1s[i]=s1[i]*vh1[i]*f1s;
    w2s[i]=s2[i]*vh2[i];
    w3s[i]=s3[i]*vh3[i]*f3s;
  }
  float rv3[6] = {pss<4>(w1p),pss<4>(w2p),pss<4>(w3p),
                  pss<4>(w1s),pss<4>(w2s),pss<4>(w3s)};
  redN<6>(rv3);
  float r1p = apw<4>(w1p,-1.f, ssh1,  rv3[0]);
  float r2p = apw<4>(w2p,-1.f, ssx2p, rv3[1]);
  float r3p = apw<4>(w3p,-1.f, ssx3p, rv3[2]);
  float r1s = apw<4>(w1s,-1.f, ssx1s, rv3[3]);
  float r2s = apw<4>(w2s, 1.f, ssh2,  rv3[4]);
  float r3s = apw<4>(w3s, 1.f, ssx3s, rv3[5]);

  float lap=__fdividef(2.f,1.f-r1p), lbp=__fdividef(2.f,1.f-r2p), lcp=__fdividef(2.f,1.f-r3p);
  float idenp = __fdividef(1.f, fmaxf(fabsf(lap+lbp+lcp-3.f), EPSF));
  float las=__fdividef(2.f,1.f-r1s), lbs=__fdividef(2.f,1.f-r2s), lcs=__fdividef(2.f,1.f-r3s);
  float idens = __fdividef(1.f, fmaxf(fabsf(las+lbs+lcs-3.f), EPSF));
  float sp[4], sv[4];
  #pragma unroll
  for (int i=0;i<4;i++){
    sp[i] = (lap*w1p[i]+lbp*w2p[i]+lcp*w3p[i])*idenp;
    sv[i] = (las*w1s[i]+lbs*w2s[i]+lcs*w3s[i])*idens;
  }
  float rv4[2] = {pss<4>(sp), pss<4>(sv)};
  redN<2>(rv4);
  float tp2 = asmul<4>(sp,0.5f,-1.f,rv4[0]);
  float ts2 = asmul<4>(sv,0.5f,-1.f,rv4[1]);
  #pragma unroll
  for (int i=0;i<4;i++){ sp[i]*=3.f; sv[i]*=3.f; }
  strow(sp,g_h1p,r,lane);
  strow(sv,g_h1s,r,lane);
  if (lane==0){ g_nhp2[r]=9.f*tp2; g_nhs2[r]=9.f*ts2; }

  float fe1 = __fdividef(artk(nrm(r1p),-1.f), nrm(r1p));
  float fe2 = __fdividef(artk(nrm(r2s), 1.f), nrm(r2s));
  float he[4];
  #pragma unroll
  for (int i=0;i<4;i++) he[i] = w1p[i]*fe1 + w2s[i]*fe2 + s3[i]*vh3[i];
  strow(he,g_h1e,r,lane);

  float xe1 = aexp0<4>(q1,-1.f,rv[5]); strow(q1,g_X1,r,lane);
  float xe2 = aexp0<4>(q2, 1.f,rv[6]); strow(q2,g_X2,r,lane);
  if (lane==0){ g_q1ss[r]=xe1; g_q2ss[r]=xe2; }
}

// ---------------- k4: cell-path rowwise post ----------------
__global__ void __launch_bounds__(256) k_cpost(const float* __restrict__ c1,
    const float* __restrict__ c2, const float* __restrict__ c3,
    const float* __restrict__ del_t, const float* __restrict__ dptr){
  int r = blockIdx.x*8 + (threadIdx.x>>5);
  int lane = threadIdx.x & 31;
  float g = __fdividef(dptr[0], del_t[r] + 1.f);

  float w1[4],w2[4],vc1[4],vc2[4],f1[4],f2[4];
  ldrow(w1,g_W1,r,lane); ldrow(w2,g_W2,r,lane);
  ldrow(vc1,c1,r,lane);  ldrow(vc2,c2,r,lane);
  ldrow(f1,g_F1,r,lane); ldrow(f2,g_F2,r,lane);
  float rv[6] = {pss<4>(w1),pss<4>(w2),pss<4>(vc1),pss<4>(vc2),
                 pss<4>(f1),pss<4>(f2)};
  redN<6>(rv);

  aexplog<4>(w1,-1.f,rv[0]);
  aexplog<4>(w2, 1.f,rv[1]);
  #pragma unroll
  for (int i=0;i<4;i++){ w1[i]=ftanh(w1[i]); w2[i]=ftanh(w2[i]); }
  float rv2[2] = {pss<4>(w1), pss<4>(w2)};
  redN<2>(rv2);
  float sscp = aexp0<4>(w1,-1.f,rv2[0]);
  float sscs = aexp0<4>(w2, 1.f,rv2[1]);

  float pgp[4], pgs[4];
  #pragma unroll
  for (int i=0;i<4;i++){ pgp[i]=w1[i]*g; pgs[i]=w2[i]*g; }
  float rpgp = apw<4>(pgp,-1.f, g*g, g*g*sscp);
  float rpgs = apw<4>(pgs, 1.f, g*g, g*g*sscs);

  float rv3[2] = {pdot<4>(w1,vc1), pdot<4>(w2,vc2)};
  redN<2>(rv3);
  float ca,cb,isd;
  amadd_coef(-1.f, sscp, rv[2], -rv3[0], ca, cb, isd);
  float map[4];
  #pragma unroll
  for (int i=0;i<4;i++) map[i] = (ca*(-w1[i]) + cb*vc1[i])*isd;
  amadd_coef( 1.f, sscs, rv[3], -rv3[1], ca, cb, isd);
  float mas[4];
  #pragma unroll
  for (int i=0;i<4;i++) mas[i] = (ca*(-w2[i]) + cb*vc2[i])*isd;

  float rv4[4] = {pss<4>(map), pdot<4>(map,pgp), pss<4>(mas), pdot<4>(mas,pgs)};
  redN<4>(rv4);
  {
    float n = nrm(rv4[0]);
    const float m = 1.f-1e-4f;
    if (n > m){
      float f = __fdividef(m,n);
      #pragma unroll
      for (int i=0;i<4;i++) map[i]*=f;
      rv4[1]*=f; rv4[0]*=f*f;
    }
  }
  amadd_coef(-1.f, rv4[0], rpgp, rv4[1], ca, cb, isd);
  float ckp[4];
  #pragma unroll
  for (int i=0;i<4;i++) ckp[i] = (ca*map[i] + cb*pgp[i])*isd;
  amadd_coef( 1.f, rv4[2], rpgs, rv4[3], ca, cb, isd);
  float cks[4];
  #pragma unroll
  for (int i=0;i<4;i++) cks[i] = (ca*mas[i] + cb*pgs[i])*isd;

  aexplog<4>(f1,-1.f,rv[4]);
  aexplog<4>(f2, 1.f,rv[5]);
  #pragma unroll
  for (int i=0;i<4;i++){ f1[i]=sigm(f1[i]); f2[i]=sigm(f2[i]); }

  float wxs[4];
  #pragma unroll
  for (int i=0;i<4;i++) wxs[i]=f2[i]*cks[i];
  float rv5[3] = {pss<4>(ckp), pss<4>(cks), pss<4>(wxs)};
  redN<3>(rv5);
  float ssckp = aproj<4>(ckp, rv5[0]);
  float wxp[4];
  #pragma unroll
  for (int i=0;i<4;i++) wxp[i]=f1[i]*ckp[i];
  float rv6[1] = {pss<4>(wxp)};
  redN<1>(rv6);
  float ryp = apw<4>(wxp,-1.f, ssckp, rv6[0]);
  float rys = apw<4>(wxs, 1.f, rv5[1], rv5[2]);
  strow(wxp,g_yp,r,lane);
  strow(wxs,g_ys,r,lane);
  if (lane==0){ g_lyp[r]=__fdividef(2.f,1.f-ryp); g_lys[r]=__fdividef(2.f,1.f+rys); }

  {
    float w3[4],vc3[4],f3[4];
    ldrow(w3,g_W3,r,lane); ldrow(vc3,c3,r,lane); ldrow(f3,g_F3,r,lane);
    float y[4];
    #pragma unroll
    for (int i=0;i<4;i++){
      float csk = ftanh(w3[i]);
      y[i] = sigm(f3[i])*(vc3[i] - csk + csk*g);
    }
    strow(y,g_ye,r,lane);
  }
}

// ---------------- k5: attention + K-aggregation ----------------
__global__ void __launch_bounds__(256) k_agg(const int* __restrict__ nbr){
  int n = blockIdx.x*8 + (threadIdx.x>>5);
  int lane = threadIdx.x & 31;
  int j[KN];
  #pragma unroll
  for (int k=0;k<KN;k++) j[k] = nbr[n*KN+k];

  float nump[4], nums[4], nume[4];
  { // Poincare hyp attention
    float q[4]; ldrow(q,g_X1,n,lane);
    float q2 = g_q1ss[n];
    float yk[KN][4], y2k[KN], d[KN];
    #pragma unroll
    for (int k=0;k<KN;k++){
      ldrow(yk[k], g_h1p, j[k], lane);
      y2k[k] = g_nhp2[j[k]];
      d[k] = pdot<4>(q, yk[k]);
    }
    redN<KN>(d);
    float sc[KN];
    #pragma unroll
    for (int k=0;k<KN;k++) sc[k] = -distf(q2, y2k[k], d[k], -1.f);
    float m = sc[0];
    #pragma unroll
    for (int k=1;k<KN;k++) m = fmaxf(m, sc[k]);
    float ssum = 0.f;
    #pragma unroll
    for (int k=0;k<KN;k++){ sc[k] = __expf(sc[k]-m); ssum += sc[k]; }
    float issum = __fdividef(1.f, ssum);
    float den = 0.f;
    #pragma unroll
    for (int i=0;i<4;i++) nump[i]=0.f;
    #pragma unroll
    for (int k=0;k<KN;k++){
      float a = sc[k]*issum;
      float lam = __fdividef(2.f, 1.f - y2k[k]);
      #pragma unroll
      for (int i=0;i<4;i++) nump[i] += a*lam*yk[k][i];
      den += a*(lam-1.f);
    }
    float iden = __fdividef(1.f, fmaxf(fabsf(den), EPSF));
    #pragma unroll
    for (int i=0;i<4;i++) nump[i]*=iden;
  }
  { // Sphere hyp attention
    float q[4]; ldrow(q,g_X2,n,lane);
    float q2 = g_q2ss[n];
    float yk[KN][4], y2k[KN], d[KN];
    #pragma unroll
    for (int k=0;k<KN;k++){
      ldrow(yk[k], g_h1s, j[k], lane);
      y2k[k] = g_nhs2[j[k]];
      d[k] = pdot<4>(q, yk[k]);
    }
    redN<KN>(d);
    float sc[KN];
    #pragma unroll
    for (int k=0;k<KN;k++) sc[k] = -distf(q2, y2k[k], d[k], 1.f);
    float m = sc[0];
    #pragma unroll
    for (int k=1;k<KN;k++) m = fmaxf(m, sc[k]);
    float ssum = 0.f;
    #pragma unroll
    for (int k=0;k<KN;k++){ sc[k] = __expf(sc[k]-m); ssum += sc[k]; }
    float issum = __fdividef(1.f, ssum);
    float den = 0.f;
    #pragma unroll
    for (int i=0;i<4;i++) nums[i]=0.f;
    #pragma unroll
    for (int k=0;k<KN;k++){
      float a = sc[k]*issum;
      float lam = __fdividef(2.f, 1.f + y2k[k]);
      #pragma unroll
      for (int i=0;i<4;i++) nums[i] += a*lam*yk[k][i];
      den += a*(lam-1.f);
    }
    float iden = __fdividef(1.f, fmaxf(fabsf(den), EPSF));
    #pragma unroll
    for (int i=0;i<4;i++) nums[i]*=iden;
  }
  { // Euclid attention
    float q[4]; ldrow(q,g_Q3,n,lane);
    float yk[KN][4], d[KN];
    #pragma unroll
    for (int k=0;k<KN;k++){
      ldrow(yk[k], g_h1e, j[k], lane);
      d[k] = pdot<4>(q, yk[k]);
    }
    redN<KN>(d);
    float sc[KN];
    #pragma unroll
    for (int k=0;k<KN;k++) sc[k] = d[k]*0.08838834764831845f;
    float m = sc[0];
    #pragma unroll
    for (int k=1;k<KN;k++) m = fmaxf(m, sc[k]);
    float ssum = 0.f;
    #pragma unroll
    for (int k=0;k<KN;k++){ sc[k] = __expf(sc[k]-m); ssum += sc[k]; }
    float issum = __fdividef(1.f, ssum);
    #pragma unroll
    for (int i=0;i<4;i++) nume[i]=0.f;
    #pragma unroll
    for (int k=0;k<KN;k++){
      float a = sc[k]*issum;
      #pragma unroll
      for (int i=0;i<4;i++) nume[i] += a*yk[k][i];
    }
  }
  // cell aggregation
  float np[4]={0,0,0,0}, ns[4]={0,0,0,0}, ne[4]={0,0,0,0};
  float dp=0.f, ds=0.f;
  #pragma unroll
  for (int k=0;k<KN;k++){
    float y[4];
    ldrow(y, g_yp, j[k], lane);
    float lam = g_lyp[j[k]];
    #pragma unroll
    for (int i=0;i<4;i++) np[i] += lam*y[i];
    dp += lam-1.f;
    ldrow(y, g_ys, j[k], lane);
    lam = g_lys[j[k]];
    #pragma unroll
    for (int i=0;i<4;i++) ns[i] += lam*y[i];
    ds += lam-1.f;
    ldrow(y, g_ye, j[k], lane);
    #pragma unroll
    for (int i=0;i<4;i++) ne[i] += y[i];
  }
  float idp = __fdividef(1.f, fmaxf(fabsf(dp), EPSF));
  float ids = __fdividef(1.f, fmaxf(fabsf(ds), EPSF));
  #pragma unroll
  for (int i=0;i<4;i++){ np[i]*=idp; ns[i]*=ids; }

  float rv[4] = {pss<4>(nump), pss<4>(nums), pss<4>(np), pss<4>(ns)};
  redN<4>(rv);
  float ssT1 = asmul<4>(nump,0.5f,-1.f,rv[0]);
  alog0<4>(nump,-1.f,ssT1);
  strow(nump,g_T1,n,lane);
  float ssT2 = asmul<4>(nums,0.5f, 1.f,rv[1]);
  alog0<4>(nums, 1.f,ssT2);
  strow(nums,g_T2,n,lane);
  strow(nume,g_T3,n,lane);
  float ssc1 = asmul<4>(np,0.5f,-1.f,rv[2]);
  float ssc2 = asmul<4>(ns,0.5f, 1.f,rv[3]);
  strow(np,g_c1v,n,lane);
  strow(ns,g_c2v,n,lane);
  strow(ne,g_c3v,n,lane);
  if (lane==0){ g_c1vss[n]=ssc1; g_c2vss[n]=ssc2; }
}

// ---------------- k7: apply_node_func ----------------
__global__ void __launch_bounds__(256) k_final(const float* __restrict__ iou1,
    const float* __restrict__ iou2, const float* __restrict__ iou3,
    float* __restrict__ out){
  int r = blockIdx.x*8 + (threadIdx.x>>5);
  int lane = threadIdx.x & 31;

  float e1[12], a1[12], e2[12], a2[12];
  #pragma unroll
  for (int i=0;i<12;i++){
    e1[i] = g_G1[(size_t)r*H3 + i*32 + lane];
    a1[i] = iou1[(size_t)r*H3 + i*32 + lane];
    e2[i] = g_G2[(size_t)r*H3 + i*32 + lane];
    a2[i] = iou2[(size_t)r*H3 + i*32 + lane];
  }
  float rv[4] = {pss<12>(e1), pss<12>(a1), pss<12>(e2), pss<12>(a2)};
  redN<4>(rv);
  float sse1 = aexp0<12>(e1,-1.f,rv[0]);
  float sse2 = aexp0<12>(e2, 1.f,rv[2]);
  float rv2[2] = {pdot<12>(a1,e1), pdot<12>(a2,e2)};
  redN<2>(rv2);
  float ca,cb,isd;
  float nio1[12], nio2[12];
  amadd_coef(-1.f, rv[1], sse1, rv2[0], ca, cb, isd);
  #pragma unroll
  for (int i=0;i<12;i++) nio1[i] = (ca*a1[i] + cb*e1[i])*isd;
  amadd_coef( 1.f, rv[3], sse2, rv2[1], ca, cb, isd);
  #pragma unroll
  for (int i=0;i<12;i++) nio2[i] = (ca*a2[i] + cb*e2[i])*isd;

  float rv3[7] = {pss<12>(nio1),
                  pss<4>(nio1), pss<4>(nio1+4), pss<4>(nio1+8),
                  pss<4>(nio2), pss<4>(nio2+4), pss<4>(nio2+8)};
  redN<7>(rv3);
  {
    float nn = nrm(rv3[0]);
    const float m = 1.f-1e-4f;
    if (nn > m){
      float f = __fdividef(m,nn);
      #pragma unroll
      for (int i=0;i<12;i++) nio1[i]*=f;
      rv3[1]*=f*f; rv3[2]*=f*f; rv3[3]*=f*f;
    }
  }
  float ip1[4], op1[4], up1[4], ip2[4], op2[4], up2[4];
  {
    float fi = __fdividef(artk(nrm(rv3[1]),-1.f), nrm(rv3[1]));
    float fo = __fdividef(artk(nrm(rv3[2]),-1.f), nrm(rv3[2]));
    float fu = __fdividef(artk(nrm(rv3[3]),-1.f), nrm(rv3[3]));
    #pragma unroll
    for (int i=0;i<4;i++){
      ip1[i]=sigm(nio1[i]*fi); op1[i]=sigm(nio1[4+i]*fo); up1[i]=ftanh(nio1[8+i]*fu);
    }
    fi = __fdividef(artk(nrm(rv3[4]),1.f), nrm(rv3[4]));
    fo = __fdividef(artk(nrm(rv3[5]),1.f), nrm(rv3[5]));
    fu = __fdividef(artk(nrm(rv3[6]),1.f), nrm(rv3[6]));
    #pragma unroll
    for (int i=0;i<4;i++){
      ip2[i]=sigm(nio2[i]*fi); op2[i]=sigm(nio2[4+i]*fo); up2[i]=ftanh(nio2[8+i]*fu);
    }
  }
  float wx1[4], wx2[4];
  #pragma unroll
  for (int i=0;i<4;i++){ wx1[i]=ip1[i]*up1[i]; wx2[i]=ip2[i]*up2[i]; }
  float rv4[4] = {pss<4>(wx1), pss<4>(up1), pss<4>(wx2), pss<4>(up2)};
  redN<4>(rv4);
  float rpw1 = apw<4>(wx1,-1.f, rv4[1], rv4[0]);
  float rpw2 = apw<4>(wx2, 1.f, rv4[3], rv4[2]);

  float cv1[4], cv2[4];
  ldrow(cv1,g_c1v,r,lane); ldrow(cv2,g_c2v,r,lane);
  float y21 = g_c1vss[r], y22 = g_c2vss[r];
  float rv5[2] = {pdot<4>(wx1,cv1), pdot<4>(wx2,cv2)};
  redN<2>(rv5);
  float nc1[4], nc2[4];
  amadd_coef(-1.f, rpw1, y21, rv5[0], ca, cb, isd);
  #pragma unroll
  for (int i=0;i<4;i++) nc1[i] = (ca*wx1[i] + cb*cv1[i])*isd;
  amadd_coef( 1.f, rpw2, y22, rv5[1], ca, cb, isd);
  #pragma unroll
  for (int i=0;i<4;i++) nc2[i] = (ca*wx2[i] + cb*cv2[i])*isd;

  float rv6[2] = {pss<4>(nc1), pss<4>(nc2)};
  redN<2>(rv6);
  float ssnc1 = aproj<4>(nc1, rv6[0]);
  strow(nc1, out + (size_t)1*NR*HD, r, lane);
  strow(nc2, out + (size_t)3*NR*HD, r, lane);

  float lg1[4], lg2[4];
  {
    float f1 = __fdividef(artk(nrm(ssnc1),-1.f), nrm(ssnc1));
    float f2 = __fdividef(artk(nrm(rv6[1]), 1.f), nrm(rv6[1]));
    #pragma unroll
    for (int i=0;i<4;i++){ lg1[i]=ftanh(nc1[i]*f1); lg2[i]=ftanh(nc2[i]*f2); }
  }
  float wy1[4], wy2[4];
  #pragma unroll
  for (int i=0;i<4;i++){ wy1[i]=op1[i]*lg1[i]; wy2[i]=op2[i]*lg2[i]; }
  float rv7[4] = {pss<4>(lg1), pss<4>(wy1), pss<4>(lg2), pss<4>(wy2)};
  redN<4>(rv7);
  apw<4>(wy1,-1.f, rv7[0], rv7[1]);
  strow(wy1, out + (size_t)0*NR*HD, r, lane);
  apw<4>(wy2, 1.f, rv7[2], rv7[3]);
  strow(wy2, out + (size_t)2*NR*HD, r, lane);

  {
    float cv[4]; ldrow(cv, g_c3v, r, lane);
    #pragma unroll
    for (int i=0;i<4;i++){
      float ie = sigm(iou3[(size_t)r*H3 + i*32 + lane]       + g_G3[(size_t)r*H3 + i*32 + lane]);
      float oe = sigm(iou3[(size_t)r*H3 + 128 + i*32 + lane] + g_G3[(size_t)r*H3 + 128 + i*32 + lane]);
      float ue = ftanh(iou3[(size_t)r*H3 + 256 + i*32 + lane] + g_G3[(size_t)r*H3 + 256 + i*32 + lane]);
      float nc = ie*ue + cv[i];
      out[(size_t)5*NR*HD + (size_t)r*HD + i*32 + lane] = nc;
      out[(size_t)4*NR*HD + (size_t)r*HD + i*32 + lane] = oe*ftanh(nc);
    }
  }
}

// ---------------- launch ----------------
extern "C" void kernel_launch(void* const* d_in, const int* in_sizes, int n_in,
                              void* d_out, int out_size){
  const float* x     = (const float*)d_in[0];
  const float* h1    = (const float*)d_in[1];
  const float* c1    = (const float*)d_in[2];
  const float* h2    = (const float*)d_in[3];
  const float* c2    = (const float*)d_in[4];
  const float* h3    = (const float*)d_in[5];
  const float* c3    = (const float*)d_in[6];
  const float* del_t = (const float*)d_in[7];
  const float* iou1  = (const float*)d_in[8];
  const float* iou2  = (const float*)d_in[9];
  const float* iou3  = (const float*)d_in[10];
  const float* Wq_w  = (const float*)d_in[11];
  const float* Wq_b  = (const float*)d_in[12];
  const float* Wc_w  = (const float*)d_in[13];
  const float* Wc_b  = (const float*)d_in[14];
  const float* Uf_w  = (const float*)d_in[15];
  const float* Uf_b  = (const float*)d_in[16];
  const float* Up_w  = (const float*)d_in[17];
  const float* Up_b  = (const float*)d_in[18];
  const float* Uiou_w= (const float*)d_in[19];
  const float* Uiou_b= (const float*)d_in[20];
  const float* dsc   = (const float*)d_in[21];
  const int*   nbr   = (const int*)d_in[22];
  float* out = (float*)d_out;

  dim3 blk(256);
  k_wconv<<<WPK_TOT/256, blk>>>(Up_w, Uf_w, Wc_w, Wq_w, Uiou_w);
  k_prep<<<NR/8, blk>>>(x, h1, h2, c1, c2);
  k_gemm_tc<<<dim3(NR/128, 1, 12), blk>>>(x, h3, c3, Up_b, Uf_b, Wc_b, Wq_b);
  k_hpost<<<NR/8, blk>>>(h1, h2, h3);
  k_cpost<<<NR/8, blk>>>(c1, c2, c3, del_t, dsc);
  k_agg<<<NR/8, blk>>>(nbr);
  k_iou_tc<<<dim3(NR/128, 3, 3), blk>>>(Uiou_b);
  k_final<<<NR/8, blk>>>(iou1, iou2, iou3, out);
}

// round 11
// speedup vs baseline: 1.2183x; 1.0587x over previous
#include <cuda_runtime.h>
#include <cuda_bf16.h>
#include <math.h>

#define NR 8192
#define HD 128
#define KN 8
#define H3 384
#define EPSF 1e-6f

// ---------------- scratch ----------------
__device__ float g_A1[NR*HD], g_A2[NR*HD], g_B1[NR*HD], g_B2[NR*HD], g_X1[NR*HD], g_X2[NR*HD];
__device__ float g_U1[NR*HD], g_U2[NR*HD], g_U3[NR*HD];
__device__ float g_F1[NR*HD], g_F2[NR*HD], g_F3[NR*HD];
__device__ float g_W1[NR*HD], g_W2[NR*HD], g_W3[NR*HD];
__device__ float g_Q1[NR*HD], g_Q2[NR*HD], g_Q3[NR*HD];
__device__ float g_h1p[NR*HD], g_h1s[NR*HD], g_h1e[NR*HD];
__device__ float g_yp[NR*HD], g_ys[NR*HD], g_ye[NR*HD];
__device__ float g_nhp2[NR], g_nhs2[NR], g_lyp[NR], g_lys[NR];
__device__ float g_q1ss[NR], g_q2ss[NR], g_c1vss[NR], g_c2vss[NR];
__device__ float g_T1[NR*HD], g_T2[NR*HD], g_T3[NR*HD];
__device__ float g_c1v[NR*HD], g_c2v[NR*HD], g_c3v[NR*HD];
__device__ float g_G1[NR*H3], g_G2[NR*H3], g_G3[NR*H3];

// packed bf16 hi/lo weights
#define OFF_UP 0
#define OFF_UF 8192
#define OFF_WC 16384
#define OFF_WQ 24576
#define OFF_IOU 32768
#define WPK_TOT 57344
__device__ unsigned int g_Whi[WPK_TOT], g_Wlo[WPK_TOT];

// ---------------- fast transcendentals ----------------
__device__ __forceinline__ float sigm(float v){
  return __fdividef(1.f, 1.f + __expf(-v));
}
__device__ __forceinline__ float ftanh(float v){
  return fmaf(2.f, __fdividef(1.f, 1.f + __expf(-2.f*v)), -1.f);
}
__device__ __forceinline__ float fatanh(float u){
  return 0.5f*__logf(__fdividef(1.f+u, 1.f-u));
}
__device__ __forceinline__ float artk(float u, float k){
  if (k < 0.f){ u = fminf(fmaxf(u, -1.f+1e-5f), 1.f-1e-5f); return fatanh(u); }
  return atanf(u);
}
__device__ __forceinline__ float tank(float u, float k){
  if (k < 0.f) return ftanh(u);
  return __tanf(fminf(fmaxf(u, -1.47079f), 1.47079f));
}
__device__ __forceinline__ float sden(float d){
  return d >= 0.f ? fmaxf(d, EPSF) : fminf(d, -EPSF);
}
__device__ __forceinline__ float nrm(float ss){ return sqrtf(ss + 1e-15f); }

// ---------------- reductions ----------------
template<int N> __device__ __forceinline__ void redN(float* v){
  #pragma unroll
  for (int o=16;o;o>>=1){
    float t[N];
    #pragma unroll
    for (int i=0;i<N;i++) t[i] = __shfl_xor_sync(0xffffffffu, v[i], o);
    #pragma unroll
    for (int i=0;i<N;i++) v[i] += t[i];
  }
}
template<int V> __device__ __forceinline__ float pdot(const float* a, const float* b){
  float s = 0.f;
  #pragma unroll
  for (int i=0;i<V;i++) s += a[i]*b[i];
  return s;
}
template<int V> __device__ __forceinline__ float pss(const float* a){ return pdot<V>(a,a); }

// ---------------- analytic (norm-tracked) manifold ops ----------------
template<int V> __device__ __forceinline__ void vscale(float* a, float f){
  #pragma unroll
  for (int i=0;i<V;i++) a[i]*=f;
}
template<int V> __device__ __forceinline__ float aexp0(float* a, float k, float ss){
  float n = nrm(ss);
  float t = tank(n,k);
  if (k < 0.f) t = fminf(t, 1.f-1e-4f);
  vscale<V>(a, __fdividef(t,n));
  return t*t;
}
template<int V> __device__ __forceinline__ float alog0(float* a, float k, float ss){
  float n = nrm(ss);
  float t = artk(n,k);
  vscale<V>(a, __fdividef(t,n));
  return t*t;
}
template<int V> __device__ __forceinline__ float aexplog(float* a, float k, float ss){
  float n = nrm(ss);
  float t;
  if (k < 0.f) t = fatanh(fminf(ftanh(n), 1.f-1e-4f));
  else         t = fminf(n, 1.47079f);
  vscale<V>(a, __fdividef(t,n));
  return t*t;
}
template<int V> __device__ __forceinline__ float asmul(float* a, float r, float k, float ss){
  float n = nrm(ss);
  float t = tank(r*artk(n,k),k);
  if (k < 0.f) t = fminf(t, 1.f-1e-4f);
  vscale<V>(a, __fdividef(t,n));
  return t*t;
}
template<int V> __device__ __forceinline__ float apw(float* wx, float k, float ssx, float ssw){
  float nx = nrm(ssx), nwx = nrm(ssw);
  float t = tank(__fdividef(nwx,nx)*artk(nx,k),k);
  if (k < 0.f) t = fminf(t, 1.f-1e-4f);
  vscale<V>(wx, __fdividef(t,nwx));
  return t*t;
}
template<int V> __device__ __forceinline__ float aproj(float* a, float ss){
  float n = nrm(ss);
  const float m = 1.f-1e-4f;
  if (n > m){ float f = __fdividef(m,n); vscale<V>(a, f); return ss*f*f; }
  return ss;
}
__device__ __forceinline__ void amadd_coef(float k, float x2, float y2, float xy,
                                           float& ca, float& cb, float& isd){
  ca = 1.f - 2.f*k*xy - k*y2;
  cb = 1.f + k*x2;
  isd = __fdividef(1.f, sden(1.f - 2.f*k*xy + k*k*x2*y2));
}
__device__ __forceinline__ float distf(float x2, float y2, float xy, float k){
  float ca = 1.f + 2.f*k*xy - k*y2;
  float cb = 1.f + k*x2;
  float sd = sden(1.f + 2.f*k*xy + k*k*x2*y2);
  float s = fmaxf(ca*ca*x2 + cb*cb*y2 - 2.f*ca*cb*xy, 0.f);
  float nv2 = __fdividef(s, sd*sd);
  float pn = sqrtf(nv2 + 1e-15f);
  if (k < 0.f){
    const float m = 1.f - 1e-4f;
    if (pn > m){ float sc = __fdividef(m,pn); pn = sqrtf(nv2*sc*sc + 1e-15f); }
  }
  return 2.f*artk(pn, k);
}
__device__ __forceinline__ void ldrow(float* a, const float* p, int row, int lane){
  #pragma unroll
  for (int i=0;i<4;i++) a[i] = p[(size_t)row*HD + i*32 + lane];
}
__device__ __forceinline__ void strow(const float* a, float* p, int row, int lane){
  #pragma unroll
  for (int i=0;i<4;i++) p[(size_t)row*HD + i*32 + lane] = a[i];
}

// ---------------- bf16 split helpers ----------------
__device__ __forceinline__ unsigned int packbf(__nv_bfloat16 lo, __nv_bfloat16 hi){
  __nv_bfloat162 t = __halves2bfloat162(lo, hi);
  return *reinterpret_cast<unsigned int*>(&t);
}
__device__ __forceinline__ void splitbf(float f, __nv_bfloat16& h, __nv_bfloat16& l){
  h = __float2bfloat16_rn(f);
  l = __float2bfloat16_rn(f - __bfloat162float(h));
}
#define MMA_BF16(c, a, b0, b1) \
  asm volatile("mma.sync.aligned.m16n8k16.row.col.f32.bf16.bf16.f32 " \
    "{%0,%1,%2,%3}, {%4,%5,%6,%7}, {%8,%9}, {%0,%1,%2,%3};" \
    : "+f"((c)[0]),"+f"((c)[1]),"+f"((c)[2]),"+f"((c)[3]) \
    : "r"((a)[0]),"r"((a)[1]),"r"((a)[2]),"r"((a)[3]), "r"(b0),"r"(b1))

// ---------------- k1: packed prep + weight split ----------------
__global__ void __launch_bounds__(256) k_prepwc(const float* __restrict__ x,
    const float* __restrict__ h1, const float* __restrict__ h2,
    const float* __restrict__ c1, const float* __restrict__ c2,
    const float* __restrict__ Up_w, const float* __restrict__ Uf_w,
    const float* __restrict__ Wc_w, const float* __restrict__ Wq_w,
    const float* __restrict__ Uiou_w){
  if (blockIdx.x < NR/8){
    int r = blockIdx.x*8 + (threadIdx.x>>5);
    int lane = threadIdx.x & 31;
    float a1[4],a2[4],b1[4],b2[4],xx[4];
    ldrow(a1,h1,r,lane); ldrow(a2,h2,r,lane);
    ldrow(b1,c1,r,lane); ldrow(b2,c2,r,lane);
    ldrow(xx,x ,r,lane);
    float rv[5] = {pss<4>(a1),pss<4>(a2),pss<4>(b1),pss<4>(b2),pss<4>(xx)};
    redN<5>(rv);
    alog0<4>(a1,-1.f,rv[0]); strow(a1,g_A1,r,lane);
    alog0<4>(a2, 1.f,rv[1]); strow(a2,g_A2,r,lane);
    alog0<4>(b1,-1.f,rv[2]); strow(b1,g_B1,r,lane);
    alog0<4>(b2, 1.f,rv[3]); strow(b2,g_B2,r,lane);
    float xc[4];
    #pragma unroll
    for (int i=0;i<4;i++) xc[i]=xx[i];
    aexplog<4>(xc,-1.f,rv[4]); strow(xc,g_X1,r,lane);
    aexplog<4>(xx, 1.f,rv[4]); strow(xx,g_X2,r,lane);
  } else {
    int e = (blockIdx.x - NR/8)*256 + threadIdx.x;
    const float* src; int off;
    if (e < OFF_UF)        { src = Up_w;   off = e - OFF_UP; }
    else if (e < OFF_WC)   { src = Uf_w;   off = e - OFF_UF; }
    else if (e < OFF_WQ)   { src = Wc_w;   off = e - OFF_WC; }
    else if (e < OFF_IOU)  { src = Wq_w;   off = e - OFF_WQ; }
    else                   { src = Uiou_w; off = e - OFF_IOU; }
    float f0 = src[(size_t)off*2], f1 = src[(size_t)off*2+1];
    __nv_bfloat16 h0,l0,h1b,l1b;
    splitbf(f0,h0,l0); splitbf(f1,h1b,l1b);
    g_Whi[e] = packbf(h0,h1b);
    g_Wlo[e] = packbf(l0,l1b);
  }
}

// ---------------- tensor-core GEMM: double-buffered, 1 sync/chunk ----------------
#define KP2 20
#define BUFU 10240   // u32 per buffer: 4 arrays x 128 x KP2
__device__ __forceinline__ void gemm_tc_body(
    const float* __restrict__ A, const unsigned int* __restrict__ Wh_g,
    const unsigned int* __restrict__ Wl_g, const float* __restrict__ bias,
    float* __restrict__ C, int ldc, int colOff, int m0){
  extern __shared__ unsigned int smdy[];
  int tid = threadIdx.x;
  int lane = tid & 31, wid = tid >> 5;
  int warpM = wid & 3, warpN = wid >> 2;
  int gid = lane >> 2, tig = lane & 3;
  float acc[2][8][4];
  #pragma unroll
  for (int mi=0;mi<2;mi++)
    #pragma unroll
    for (int ni=0;ni<8;ni++)
      #pragma unroll
      for (int q=0;q<4;q++) acc[mi][ni][q]=0.f;

  int ar = (tid>>3), akq = (tid&7)*4;        // A staging coords
  int wr = (tid>>2), wkq = (tid&3)*4;        // W staging coords
  float4 av[4]; uint4 whv[2], wlv[2];
  // prefetch chunk 0
  #pragma unroll
  for (int p=0;p<4;p++)
    av[p] = *(const float4*)(A + (size_t)(m0+ar+p*32)*HD + akq);
  #pragma unroll
  for (int t=0;t<2;t++){
    whv[t] = *(const uint4*)(Wh_g + (size_t)(wr+t*64)*64 + wkq);
    wlv[t] = *(const uint4*)(Wl_g + (size_t)(wr+t*64)*64 + wkq);
  }

  for (int c=0; c<4; c++){
    unsigned int* SAh = smdy + (c&1)*BUFU;
    unsigned int* SAl = SAh + 2560;
    unsigned int* SWh = SAh + 5120;
    unsigned int* SWl = SAh + 7680;
    // commit staged regs to this chunk's buffer
    #pragma unroll
    for (int p=0;p<4;p++){
      int rr = ar + p*32;
      __nv_bfloat16 h0,l0,h1,l1;
      splitbf(av[p].x,h0,l0); splitbf(av[p].y,h1,l1);
      SAh[rr*KP2 + (akq>>1)  ] = packbf(h0,h1);
      SAl[rr*KP2 + (akq>>1)  ] = packbf(l0,l1);
      splitbf(av[p].z,h0,l0); splitbf(av[p].w,h1,l1);
      SAh[rr*KP2 + (akq>>1)+1] = packbf(h0,h1);
      SAl[rr*KP2 + (akq>>1)+1] = packbf(l0,l1);
    }
    #pragma unroll
    for (int t=0;t<2;t++){
      *(uint4*)&SWh[(wr+t*64)*KP2 + wkq] = whv[t];
      *(uint4*)&SWl[(wr+t*64)*KP2 + wkq] = wlv[t];
    }
    __syncthreads();     // single barrier per chunk (double-buffered WAR-safe)
    // prefetch next chunk while computing this one
    if (c < 3){
      int kt = (c+1)*32;
      #pragma unroll
      for (int p=0;p<4;p++)
        av[p] = *(const float4*)(A + (size_t)(m0+ar+p*32)*HD + kt + akq);
      #pragma unroll
      for (int t=0;t<2;t++){
        whv[t] = *(const uint4*)(Wh_g + (size_t)(wr+t*64)*64 + (kt>>1) + wkq);
        wlv[t] = *(const uint4*)(Wl_g + (size_t)(wr+t*64)*64 + (kt>>1) + wkq);
      }
    }
    #pragma unroll
    for (int ks=0; ks<2; ks++){
      int kb = ks*8;
      unsigned int ah[2][4], al[2][4];
      #pragma unroll
      for (int mi=0;mi<2;mi++){
        int r0 = warpM*32 + mi*16 + gid;
        ah[mi][0]=SAh[r0*KP2+kb+tig];     ah[mi][1]=SAh[(r0+8)*KP2+kb+tig];
        ah[mi][2]=SAh[r0*KP2+kb+tig+4];   ah[mi][3]=SAh[(r0+8)*KP2+kb+tig+4];
        al[mi][0]=SAl[r0*KP2+kb+tig];     al[mi][1]=SAl[(r0+8)*KP2+kb+tig];
        al[mi][2]=SAl[r0*KP2+kb+tig+4];   al[mi][3]=SAl[(r0+8)*KP2+kb+tig+4];
      }
      #pragma unroll
      for (int ni=0;ni<8;ni++){
        int c0 = warpN*64 + ni*8 + gid;
        unsigned int bh0 = SWh[c0*KP2+kb+tig], bh1 = SWh[c0*KP2+kb+tig+4];
        unsigned int bl0 = SWl[c0*KP2+kb+tig], bl1 = SWl[c0*KP2+kb+tig+4];
        #pragma unroll
        for (int mi=0;mi<2;mi++){
          MMA_BF16(acc[mi][ni], ah[mi], bh0, bh1);
          MMA_BF16(acc[mi][ni], ah[mi], bl0, bl1);
          MMA_BF16(acc[mi][ni], al[mi], bh0, bh1);
        }
      }
    }
  }
  #pragma unroll
  for (int mi=0;mi<2;mi++){
    int r = m0 + warpM*32 + mi*16 + gid;
    #pragma unroll
    for (int ni=0;ni<8;ni++){
      int c = colOff + warpN*64 + ni*8 + tig*2;
      float b0 = bias[c], b1 = bias[c+1];
      float2 v0 = make_float2(acc[mi][ni][0]+b0, acc[mi][ni][1]+b1);
      float2 v1 = make_float2(acc[mi][ni][2]+b0, acc[mi][ni][3]+b1);
      *(float2*)(C + (size_t)r*ldc + c) = v0;
      *(float2*)(C + (size_t)(r+8)*ldc + c) = v1;
    }
  }
}

__global__ void __launch_bounds__(256) k_gemm_tc(const float* __restrict__ x,
    const float* __restrict__ h3, const float* __restrict__ c3,
    const float* __restrict__ Up_b, const float* __restrict__ Uf_b,
    const float* __restrict__ Wc_b, const float* __restrict__ Wq_b){
  const float *A, *bias; float* C; int woff;
  switch (blockIdx.z){
    case 0:  A=g_A1; woff=OFF_UP; bias=Up_b; C=g_U1; break;
    case 1:  A=g_A2; woff=OFF_UP; bias=Up_b; C=g_U2; break;
    case 2:  A=h3;   woff=OFF_UP; bias=Up_b; C=g_U3; break;
    case 3:  A=g_A1; woff=OFF_UF; bias=Uf_b; C=g_F1; break;
    case 4:  A=g_A2; woff=OFF_UF; bias=Uf_b; C=g_F2; break;
    case 5:  A=h3;   woff=OFF_UF; bias=Uf_b; C=g_F3; break;
    case 6:  A=g_B1; woff=OFF_WC; bias=Wc_b; C=g_W1; break;
    case 7:  A=g_B2; woff=OFF_WC; bias=Wc_b; C=g_W2; break;
    case 8:  A=c3;   woff=OFF_WC; bias=Wc_b; C=g_W3; break;
    case 9:  A=g_X1; woff=OFF_WQ; bias=Wq_b; C=g_Q1; break;
    case 10: A=g_X2; woff=OFF_WQ; bias=Wq_b; C=g_Q2; break;
    default: A=x;    woff=OFF_WQ; bias=Wq_b; C=g_Q3; break;
  }
  gemm_tc_body(A, g_Whi+woff, g_Wlo+woff, bias, C, HD, 0, blockIdx.x*128);
}

__global__ void __launch_bounds__(256) k_iou_tc(const float* __restrict__ Uiou_b){
  const float* A; float* C;
  switch (blockIdx.z){
    case 0:  A=g_T1; C=g_G1; break;
    case 1:  A=g_T2; C=g_G2; break;
    default: A=g_T3; C=g_G3; break;
  }
  int colOff = blockIdx.y*128;
  gemm_tc_body(A, g_Whi + OFF_IOU + (size_t)colOff*64,
               g_Wlo + OFF_IOU + (size_t)colOff*64,
               Uiou_b, C, H3, colOff, blockIdx.x*128);
}

// ---------------- rowwise post bodies ----------------
__device__ __forceinline__ void hpost_row(int r, int lane,
    const float* __restrict__ h1, const float* __restrict__ h2,
    const float* __restrict__ h3){
  float s1[4], s2[4], s3[4], vh1[4], vh2[4], vh3[4], q1[4], q2[4];
  ldrow(s1,g_U1,r,lane); ldrow(s2,g_U2,r,lane); ldrow(s3,g_U3,r,lane);
  ldrow(vh1,h1,r,lane);  ldrow(vh2,h2,r,lane);  ldrow(vh3,h3,r,lane);
  ldrow(q1,g_Q1,r,lane); ldrow(q2,g_Q2,r,lane);

  float rv[7] = {pss<4>(s1),pss<4>(s2),pss<4>(vh1),pss<4>(vh2),pss<4>(vh3),
                 pss<4>(q1),pss<4>(q2)};
  redN<7>(rv);
  float ssh1=rv[2], ssh2=rv[3], ssh3=rv[4];

  aexp0<4>(s1,-1.f,rv[0]);
  aexp0<4>(s2, 1.f,rv[1]);
  #pragma unroll
  for (int i=0;i<4;i++){ s1[i]=sigm(s1[i]); s2[i]=sigm(s2[i]); s3[i]=sigm(s3[i]); }
  float rv2[2] = {pss<4>(s1), pss<4>(s2)};
  redN<2>(rv2);
  alog0<4>(s1,-1.f,rv2[0]);
  alog0<4>(s2, 1.f,rv2[1]);

  float n2h = nrm(ssh2);
  float t2p = ftanh(atanf(n2h));
  float f2p = __fdividef(t2p,n2h);  float ssx2p = t2p*t2p;
  float n3h = nrm(ssh3);
  float t3p = fminf(ftanh(n3h), 1.f-1e-4f);
  float f3p = __fdividef(t3p,n3h);  float ssx3p = t3p*t3p;
  float n1h = nrm(ssh1);
  float a1t = artk(n1h,-1.f);
  float t1s = __tanf(fminf(a1t, 1.47079f));
  float f1s = __fdividef(t1s,n1h);  float ssx1s = t1s*t1s;
  float t3s = __tanf(fminf(n3h, 1.47079f));
  float f3s = __fdividef(t3s,n3h);  float ssx3s = t3s*t3s;

  float w1p[4],w2p[4],w3p[4],w1s[4],w2s[4],w3s[4];
  #pragma unroll
  for (int i=0;i<4;i++){
    w1p[i]=s1[i]*vh1[i];
    w2p[i]=s2[i]*vh2[i]*f2p;
    w3p[i]=s3[i]*vh3[i]*f3p;
    w1s[i]=s1[i]*vh1[i]*f1s;
    w2s[i]=s2[i]*vh2[i];
    w3s[i]=s3[i]*vh3[i]*f3s;
  }
  float rv3[6] = {pss<4>(w1p),pss<4>(w2p),pss<4>(w3p),
                  pss<4>(w1s),pss<4>(w2s),pss<4>(w3s)};
  redN<6>(rv3);
  float r1p = apw<4>(w1p,-1.f, ssh1,  rv3[0]);
  float r2p = apw<4>(w2p,-1.f, ssx2p, rv3[1]);
  float r3p = apw<4>(w3p,-1.f, ssx3p, rv3[2]);
  float r1s = apw<4>(w1s,-1.f, ssx1s, rv3[3]);
  float r2s = apw<4>(w2s, 1.f, ssh2,  rv3[4]);
  float r3s = apw<4>(w3s, 1.f, ssx3s, rv3[5]);

  float lap=__fdividef(2.f,1.f-r1p), lbp=__fdividef(2.f,1.f-r2p), lcp=__fdividef(2.f,1.f-r3p);
  float idenp = __fdividef(1.f, fmaxf(fabsf(lap+lbp+lcp-3.f), EPSF));
  float las=__fdividef(2.f,1.f-r1s), lbs=__fdividef(2.f,1.f-r2s), lcs=__fdividef(2.f,1.f-r3s);
  float idens = __fdividef(1.f, fmaxf(fabsf(las+lbs+lcs-3.f), EPSF));
  float sp[4], sv[4];
  #pragma unroll
  for (int i=0;i<4;i++){
    sp[i] = (lap*w1p[i]+lbp*w2p[i]+lcp*w3p[i])*idenp;
    sv[i] = (las*w1s[i]+lbs*w2s[i]+lcs*w3s[i])*idens;
  }
  float rv4[2] = {pss<4>(sp), pss<4>(sv)};
  redN<2>(rv4);
  float tp2 = asmul<4>(sp,0.5f,-1.f,rv4[0]);
  float ts2 = asmul<4>(sv,0.5f,-1.f,rv4[1]);
  #pragma unroll
  for (int i=0;i<4;i++){ sp[i]*=3.f; sv[i]*=3.f; }
  strow(sp,g_h1p,r,lane);
  strow(sv,g_h1s,r,lane);
  if (lane==0){ g_nhp2[r]=9.f*tp2; g_nhs2[r]=9.f*ts2; }

  float fe1 = __fdividef(artk(nrm(r1p),-1.f), nrm(r1p));
  float fe2 = __fdividef(artk(nrm(r2s), 1.f), nrm(r2s));
  float he[4];
  #pragma unroll
  for (int i=0;i<4;i++) he[i] = w1p[i]*fe1 + w2s[i]*fe2 + s3[i]*vh3[i];
  strow(he,g_h1e,r,lane);

  float xe1 = aexp0<4>(q1,-1.f,rv[5]); strow(q1,g_X1,r,lane);
  float xe2 = aexp0<4>(q2, 1.f,rv[6]); strow(q2,g_X2,r,lane);
  if (lane==0){ g_q1ss[r]=xe1; g_q2ss[r]=xe2; }
}

__device__ __forceinline__ void cpost_row(int r, int lane,
    const float* __restrict__ c1, const float* __restrict__ c2,
    const float* __restrict__ c3, const float* __restrict__ del_t,
    const float* __restrict__ dptr){
  float g = __fdividef(dptr[0], del_t[r] + 1.f);

  float w1[4],w2[4],vc1[4],vc2[4],f1[4],f2[4];
  ldrow(w1,g_W1,r,lane); ldrow(w2,g_W2,r,lane);
  ldrow(vc1,c1,r,lane);  ldrow(vc2,c2,r,lane);
  ldrow(f1,g_F1,r,lane); ldrow(f2,g_F2,r,lane);
  float rv[6] = {pss<4>(w1),pss<4>(w2),pss<4>(vc1),pss<4>(vc2),
                 pss<4>(f1),pss<4>(f2)};
  redN<6>(rv);

  aexplog<4>(w1,-1.f,rv[0]);
  aexplog<4>(w2, 1.f,rv[1]);
  #pragma unroll
  for (int i=0;i<4;i++){ w1[i]=ftanh(w1[i]); w2[i]=ftanh(w2[i]); }
  float rv2[2] = {pss<4>(w1), pss<4>(w2)};
  redN<2>(rv2);
  float sscp = aexp0<4>(w1,-1.f,rv2[0]);
  float sscs = aexp0<4>(w2, 1.f,rv2[1]);

  float pgp[4], pgs[4];
  #pragma unroll
  for (int i=0;i<4;i++){ pgp[i]=w1[i]*g; pgs[i]=w2[i]*g; }
  float rpgp = apw<4>(pgp,-1.f, g*g, g*g*sscp);
  float rpgs = apw<4>(pgs, 1.f, g*g, g*g*sscs);

  float rv3[2] = {pdot<4>(w1,vc1), pdot<4>(w2,vc2)};
  redN<2>(rv3);
  float ca,cb,isd;
  amadd_coef(-1.f, sscp, rv[2], -rv3[0], ca, cb, isd);
  float map[4];
  #pragma unroll
  for (int i=0;i<4;i++) map[i] = (ca*(-w1[i]) + cb*vc1[i])*isd;
  amadd_coef( 1.f, sscs, rv[3], -rv3[1], ca, cb, isd);
  float mas[4];
  #pragma unroll
  for (int i=0;i<4;i++) mas[i] = (ca*(-w2[i]) + cb*vc2[i])*isd;

  float rv4[4] = {pss<4>(map), pdot<4>(map,pgp), pss<4>(mas), pdot<4>(mas,pgs)};
  redN<4>(rv4);
  {
    float n = nrm(rv4[0]);
    const float m = 1.f-1e-4f;
    if (n > m){
      float f = __fdividef(m,n);
      #pragma unroll
      for (int i=0;i<4;i++) map[i]*=f;
      rv4[1]*=f; rv4[0]*=f*f;
    }
  }
  amadd_coef(-1.f, rv4[0], rpgp, rv4[1], ca, cb, isd);
  float ckp[4];
  #pragma unroll
  for (int i=0;i<4;i++) ckp[i] = (ca*map[i] + cb*pgp[i])*isd;
  amadd_coef( 1.f, rv4[2], rpgs, rv4[3], ca, cb, isd);
  float cks[4];
  #pragma unroll
  for (int i=0;i<4;i++) cks[i] = (ca*mas[i] + cb*pgs[i])*isd;

  aexplog<4>(f1,-1.f,rv[4]);
  aexplog<4>(f2, 1.f,rv[5]);
  #pragma unroll
  for (int i=0;i<4;i++){ f1[i]=sigm(f1[i]); f2[i]=sigm(f2[i]); }

  float wxs[4];
  #pragma unroll
  for (int i=0;i<4;i++) wxs[i]=f2[i]*cks[i];
  float rv5[3] = {pss<4>(ckp), pss<4>(cks), pss<4>(wxs)};
  redN<3>(rv5);
  float ssckp = aproj<4>(ckp, rv5[0]);
  float wxp[4];
  #pragma unroll
  for (int i=0;i<4;i++) wxp[i]=f1[i]*ckp[i];
  float rv6[1] = {pss<4>(wxp)};
  redN<1>(rv6);
  float ryp = apw<4>(wxp,-1.f, ssckp, rv6[0]);
  float rys = apw<4>(wxs, 1.f, rv5[1], rv5[2]);
  strow(wxp,g_yp,r,lane);
  strow(wxs,g_ys,r,lane);
  if (lane==0){ g_lyp[r]=__fdividef(2.f,1.f-ryp); g_lys[r]=__fdividef(2.f,1.f+rys); }

  {
    float w3[4],vc3[4],f3[4];
    ldrow(w3,g_W3,r,lane); ldrow(vc3,c3,r,lane); ldrow(f3,g_F3,r,lane);
    float y[4];
    #pragma unroll
    for (int i=0;i<4;i++){
      float csk = ftanh(w3[i]);
      y[i] = sigm(f3[i])*(vc3[i] - csk + csk*g);
    }
    strow(y,g_ye,r,lane);
  }
}

// ---------------- k3: packed hpost + cpost ----------------
__global__ void __launch_bounds__(256) k_post2(const float* __restrict__ h1,
    const float* __restrict__ h2, const float* __restrict__ h3,
    const float* __restrict__ c1, const float* __restrict__ c2,
    const float* __restrict__ c3, const float* __restrict__ del_t,
    const float* __restrict__ dptr){
  int lane = threadIdx.x & 31;
  int w = threadIdx.x >> 5;
  if (blockIdx.x < NR/8){
    hpost_row(blockIdx.x*8 + w, lane, h1, h2, h3);
  } else {
    cpost_row((blockIdx.x - NR/8)*8 + w, lane, c1, c2, c3, del_t, dptr);
  }
}

// ---------------- k5: attention + K-aggregation ----------------
__global__ void __launch_bounds__(256) k_agg(const int* __restrict__ nbr){
  int n = blockIdx.x*8 + (threadIdx.x>>5);
  int lane = threadIdx.x & 31;
  int j[KN];
  #pragma unroll
  for (int k=0;k<KN;k++) j[k] = nbr[n*KN+k];

  float nump[4], nums[4], nume[4];
  { // Poincare hyp attention
    float q[4]; ldrow(q,g_X1,n,lane);
    float q2 = g_q1ss[n];
    float yk[KN][4], y2k[KN], d[KN];
    #pragma unroll
    for (int k=0;k<KN;k++){
      ldrow(yk[k], g_h1p, j[k], lane);
      y2k[k] = g_nhp2[j[k]];
      d[k] = pdot<4>(q, yk[k]);
    }
    redN<KN>(d);
    float sc[KN];
    #pragma unroll
    for (int k=0;k<KN;k++) sc[k] = -distf(q2, y2k[k], d[k], -1.f);
    float m = sc[0];
    #pragma unroll
    for (int k=1;k<KN;k++) m = fmaxf(m, sc[k]);
    float ssum = 0.f;
    #pragma unroll
    for (int k=0;k<KN;k++){ sc[k] = __expf(sc[k]-m); ssum += sc[k]; }
    float issum = __fdividef(1.f, ssum);
    float den = 0.f;
    #pragma unroll
    for (int i=0;i<4;i++) nump[i]=0.f;
    #pragma unroll
    for (int k=0;k<KN;k++){
      float a = sc[k]*issum;
      float lam = __fdividef(2.f, 1.f - y2k[k]);
      #pragma unroll
      for (int i=0;i<4;i++) nump[i] += a*lam*yk[k][i];
      den += a*(lam-1.f);
    }
    float iden = __fdividef(1.f, fmaxf(fabsf(den), EPSF));
    #pragma unroll
    for (int i=0;i<4;i++) nump[i]*=iden;
  }
  { // Sphere hyp attention
    float q[4]; ldrow(q,g_X2,n,lane);
    float q2 = g_q2ss[n];
    float yk[KN][4], y2k[KN], d[KN];
    #pragma unroll
    for (int k=0;k<KN;k++){
      ldrow(yk[k], g_h1s, j[k], lane);
      y2k[k] = g_nhs2[j[k]];
      d[k] = pdot<4>(q, yk[k]);
    }
    redN<KN>(d);
    float sc[KN];
    #pragma unroll
    for (int k=0;k<KN;k++) sc[k] = -distf(q2, y2k[k], d[k], 1.f);
    float m = sc[0];
    #pragma unroll
    for (int k=1;k<KN;k++) m = fmaxf(m, sc[k]);
    float ssum = 0.f;
    #pragma unroll
    for (int k=0;k<KN;k++){ sc[k] = __expf(sc[k]-m); ssum += sc[k]; }
    float issum = __fdividef(1.f, ssum);
    float den = 0.f;
    #pragma unroll
    for (int i=0;i<4;i++) nums[i]=0.f;
    #pragma unroll
    for (int k=0;k<KN;k++){
      float a = sc[k]*issum;
      float lam = __fdividef(2.f, 1.f + y2k[k]);
      #pragma unroll
      for (int i=0;i<4;i++) nums[i] += a*lam*yk[k][i];
      den += a*(lam-1.f);
    }
    float iden = __fdividef(1.f, fmaxf(fabsf(den), EPSF));
    #pragma unroll
    for (int i=0;i<4;i++) nums[i]*=iden;
  }
  { // Euclid attention
    float q[4]; ldrow(q,g_Q3,n,lane);
    float yk[KN][4], d[KN];
    #pragma unroll
    for (int k=0;k<KN;k++){
      ldrow(yk[k], g_h1e, j[k], lane);
      d[k] = pdot<4>(q, yk[k]);
    }
    redN<KN>(d);
    float sc[KN];
    #pragma unroll
    for (int k=0;k<KN;k++) sc[k] = d[k]*0.08838834764831845f;
    float m = sc[0];
    #pragma unroll
    for (int k=1;k<KN;k++) m = fmaxf(m, sc[k]);
    float ssum = 0.f;
    #pragma unroll
    for (int k=0;k<KN;k++){ sc[k] = __expf(sc[k]-m); ssum += sc[k]; }
    float issum = __fdividef(1.f, ssum);
    #pragma unroll
    for (int i=0;i<4;i++) nume[i]=0.f;
    #pragma unroll
    for (int k=0;k<KN;k++){
      float a = sc[k]*issum;
      #pragma unroll
      for (int i=0;i<4;i++) nume[i] += a*yk[k][i];
    }
  }
  // cell aggregation
  float np[4]={0,0,0,0}, ns[4]={0,0,0,0}, ne[4]={0,0,0,0};
  float dp=0.f, ds=0.f;
  #pragma unroll
  for (int k=0;k<KN;k++){
    float y[4];
    ldrow(y, g_yp, j[k], lane);
    float lam = g_lyp[j[k]];
    #pragma unroll
    for (int i=0;i<4;i++) np[i] += lam*y[i];
    dp += lam-1.f;
    ldrow(y, g_ys, j[k], lane);
    lam = g_lys[j[k]];
    #pragma unroll
    for (int i=0;i<4;i++) ns[i] += lam*y[i];
    ds += lam-1.f;
    ldrow(y, g_ye, j[k], lane);
    #pragma unroll
    for (int i=0;i<4;i++) ne[i] += y[i];
  }
  float idp = __fdividef(1.f, fmaxf(fabsf(dp), EPSF));
  float ids = __fdividef(1.f, fmaxf(fabsf(ds), EPSF));
  #pragma unroll
  for (int i=0;i<4;i++){ np[i]*=idp; ns[i]*=ids; }

  float rv[4] = {pss<4>(nump), pss<4>(nums), pss<4>(np), pss<4>(ns)};
  redN<4>(rv);
  float ssT1 = asmul<4>(nump,0.5f,-1.f,rv[0]);
  alog0<4>(nump,-1.f,ssT1);
  strow(nump,g_T1,n,lane);
  float ssT2 = asmul<4>(nums,0.5f, 1.f,rv[1]);
  alog0<4>(nums, 1.f,ssT2);
  strow(nums,g_T2,n,lane);
  strow(nume,g_T3,n,lane);
  float ssc1 = asmul<4>(np,0.5f,-1.f,rv[2]);
  float ssc2 = asmul<4>(ns,0.5f, 1.f,rv[3]);
  strow(np,g_c1v,n,lane);
  strow(ns,g_c2v,n,lane);
  strow(ne,g_c3v,n,lane);
  if (lane==0){ g_c1vss[n]=ssc1; g_c2vss[n]=ssc2; }
}

// ---------------- k7: apply_node_func ----------------
__global__ void __launch_bounds__(256) k_final(const float* __restrict__ iou1,
    const float* __restrict__ iou2, const float* __restrict__ iou3,
    float* __restrict__ out){
  int r = blockIdx.x*8 + (threadIdx.x>>5);
  int lane = threadIdx.x & 31;

  float e1[12], a1[12], e2[12], a2[12];
  #pragma unroll
  for (int i=0;i<12;i++){
    e1[i] = g_G1[(size_t)r*H3 + i*32 + lane];
    a1[i] = iou1[(size_t)r*H3 + i*32 + lane];
    e2[i] = g_G2[(size_t)r*H3 + i*32 + lane];
    a2[i] = iou2[(size_t)r*H3 + i*32 + lane];
  }
  float rv[4] = {pss<12>(e1), pss<12>(a1), pss<12>(e2), pss<12>(a2)};
  redN<4>(rv);
  float sse1 = aexp0<12>(e1,-1.f,rv[0]);
  float sse2 = aexp0<12>(e2, 1.f,rv[2]);
  float rv2[2] = {pdot<12>(a1,e1), pdot<12>(a2,e2)};
  redN<2>(rv2);
  float ca,cb,isd;
  float nio1[12], nio2[12];
  amadd_coef(-1.f, rv[1], sse1, rv2[0], ca, cb, isd);
  #pragma unroll
  for (int i=0;i<12;i++) nio1[i] = (ca*a1[i] + cb*e1[i])*isd;
  amadd_coef( 1.f, rv[3], sse2, rv2[1], ca, cb, isd);
  #pragma unroll
  for (int i=0;i<12;i++) nio2[i] = (ca*a2[i] + cb*e2[i])*isd;

  float rv3[7] = {pss<12>(nio1),
                  pss<4>(nio1), pss<4>(nio1+4), pss<4>(nio1+8),
                  pss<4>(nio2), pss<4>(nio2+4), pss<4>(nio2+8)};
  redN<7>(rv3);
  {
    float nn = nrm(rv3[0]);
    const float m = 1.f-1e-4f;
    if (nn > m){
      float f = __fdividef(m,nn);
      #pragma unroll
      for (int i=0;i<12;i++) nio1[i]*=f;
      rv3[1]*=f*f; rv3[2]*=f*f; rv3[3]*=f*f;
    }
  }
  float ip1[4], op1[4], up1[4], ip2[4], op2[4], up2[4];
  {
    float fi = __fdividef(artk(nrm(rv3[1]),-1.f), nrm(rv3[1]));
    float fo = __fdividef(artk(nrm(rv3[2]),-1.f), nrm(rv3[2]));
    float fu = __fdividef(artk(nrm(rv3[3]),-1.f), nrm(rv3[3]));
    #pragma unroll
    for (int i=0;i<4;i++){
      ip1[i]=sigm(nio1[i]*fi); op1[i]=sigm(nio1[4+i]*fo); up1[i]=ftanh(nio1[8+i]*fu);
    }
    fi = __fdividef(artk(nrm(rv3[4]),1.f), nrm(rv3[4]));
    fo = __fdividef(artk(nrm(rv3[5]),1.f), nrm(rv3[5]));
    fu = __fdividef(artk(nrm(rv3[6]),1.f), nrm(rv3[6]));
    #pragma unroll
    for (int i=0;i<4;i++){
      ip2[i]=sigm(nio2[i]*fi); op2[i]=sigm(nio2[4+i]*fo); up2[i]=ftanh(nio2[8+i]*fu);
    }
  }
  float wx1[4], wx2[4];
  #pragma unroll
  for (int i=0;i<4;i++){ wx1[i]=ip1[i]*up1[i]; wx2[i]=ip2[i]*up2[i]; }
  float rv4[4] = {pss<4>(wx1), pss<4>(up1), pss<4>(wx2), pss<4>(up2)};
  redN<4>(rv4);
  float rpw1 = apw<4>(wx1,-1.f, rv4[1], rv4[0]);
  float rpw2 = apw<4>(wx2, 1.f, rv4[3], rv4[2]);

  float cv1[4], cv2[4];
  ldrow(cv1,g_c1v,r,lane); ldrow(cv2,g_c2v,r,lane);
  float y21 = g_c1vss[r], y22 = g_c2vss[r];
  float rv5[2] = {pdot<4>(wx1,cv1), pdot<4>(wx2,cv2)};
  redN<2>(rv5);
  float nc1[4], nc2[4];
  amadd_coef(-1.f, rpw1, y21, rv5[0], ca, cb, isd);
  #pragma unroll
  for (int i=0;i<4;i++) nc1[i] = (ca*wx1[i] + cb*cv1[i])*isd;
  amadd_coef( 1.f, rpw2, y22, rv5[1], ca, cb, isd);
  #pragma unroll
  for (int i=0;i<4;i++) nc2[i] = (ca*wx2[i] + cb*cv2[i])*isd;

  float rv6[2] = {pss<4>(nc1), pss<4>(nc2)};
  redN<2>(rv6);
  float ssnc1 = aproj<4>(nc1, rv6[0]);
  strow(nc1, out + (size_t)1*NR*HD, r, lane);
  strow(nc2, out + (size_t)3*NR*HD, r, lane);

  float lg1[4], lg2[4];
  {
    float f1 = __fdividef(artk(nrm(ssnc1),-1.f), nrm(ssnc1));
    float f2 = __fdividef(artk(nrm(rv6[1]), 1.f), nrm(rv6[1]));
    #pragma unroll
    for (int i=0;i<4;i++){ lg1[i]=ftanh(nc1[i]*f1); lg2[i]=ftanh(nc2[i]*f2); }
  }
  float wy1[4], wy2[4];
  #pragma unroll
  for (int i=0;i<4;i++){ wy1[i]=op1[i]*lg1[i]; wy2[i]=op2[i]*lg2[i]; }
  float rv7[4] = {pss<4>(lg1), pss<4>(wy1), pss<4>(lg2), pss<4>(wy2)};
  redN<4>(rv7);
  apw<4>(wy1,-1.f, rv7[0], rv7[1]);
  strow(wy1, out + (size_t)0*NR*HD, r, lane);
  apw<4>(wy2, 1.f, rv7[2], rv7[3]);
  strow(wy2, out + (size_t)2*NR*HD, r, lane);

  {
    float cv[4]; ldrow(cv, g_c3v, r, lane);
    #pragma unroll
    for (int i=0;i<4;i++){
      float ie = sigm(iou3[(size_t)r*H3 + i*32 + lane]       + g_G3[(size_t)r*H3 + i*32 + lane]);
      float oe = sigm(iou3[(size_t)r*H3 + 128 + i*32 + lane] + g_G3[(size_t)r*H3 + 128 + i*32 + lane]);
      float ue = ftanh(iou3[(size_t)r*H3 + 256 + i*32 + lane] + g_G3[(size_t)r*H3 + 256 + i*32 + lane]);
      float nc = ie*ue + cv[i];
      out[(size_t)5*NR*HD + (size_t)r*HD + i*32 + lane] = nc;
      out[(size_t)4*NR*HD + (size_t)r*HD + i*32 + lane] = oe*ftanh(nc);
    }
  }
}

// ---------------- launch ----------------
extern "C" void kernel_launch(void* const* d_in, const int* in_sizes, int n_in,
                              void* d_out, int out_size){
  const float* x     = (const float*)d_in[0];
  const float* h1    = (const float*)d_in[1];
  const float* c1    = (const float*)d_in[2];
  const float* h2    = (const float*)d_in[3];
  const float* c2    = (const float*)d_in[4];
  const float* h3    = (const float*)d_in[5];
  const float* c3    = (const float*)d_in[6];
  const float* del_t = (const float*)d_in[7];
  const float* iou1  = (const float*)d_in[8];
  const float* iou2  = (const float*)d_in[9];
  const float* iou3  = (const float*)d_in[10];
  const float* Wq_w  = (const float*)d_in[11];
  const float* Wq_b  = (const float*)d_in[12];
  const float* Wc_w  = (const float*)d_in[13];
  const float* Wc_b  = (const float*)d_in[14];
  const float* Uf_w  = (const float*)d_in[15];
  const float* Uf_b  = (const float*)d_in[16];
  const float* Up_w  = (const float*)d_in[17];
  const float* Up_b  = (const float*)d_in[18];
  const float* Uiou_w= (const float*)d_in[19];
  const float* Uiou_b= (const float*)d_in[20];
  const float* dsc   = (const float*)d_in[21];
  const int*   nbr   = (const int*)d_in[22];
  float* out = (float*)d_out;

  const int GEMM_SMEM = 2*BUFU*4;   // 81920 bytes
  cudaFuncSetAttribute(k_gemm_tc, cudaFuncAttributeMaxDynamicSharedMemorySize, GEMM_SMEM);
  cudaFuncSetAttribute(k_iou_tc,  cudaFuncAttributeMaxDynamicSharedMemorySize, GEMM_SMEM);

  dim3 blk(256);
  k_prepwc<<<NR/8 + WPK_TOT/256, blk>>>(x, h1, h2, c1, c2,
                                        Up_w, Uf_w, Wc_w, Wq_w, Uiou_w);
  k_gemm_tc<<<dim3(NR/128, 1, 12), blk, GEMM_SMEM>>>(x, h3, c3, Up_b, Uf_b, Wc_b, Wq_b);
  k_post2<<<2*(NR/8), blk>>>(h1, h2, h3, c1, c2, c3, del_t, dsc);
  k_agg<<<NR/8, blk>>>(nbr);
  k_iou_tc<<<dim3(NR/128, 3, 3), blk, GEMM_SMEM>>>(Uiou_b);
  k_final<<<NR/8, blk>>>(iou1, iou2, iou3, out);
}

// round 14
// speedup vs baseline: 1.3205x; 1.0838x over previous
#include <cuda_runtime.h>
#include <cuda_bf16.h>
#include <math.h>

#define NR 8192
#define HD 128
#define KN 8
#define H3 384
#define EPSF 1e-6f
#define NB (NR/8)

// ---------------- scratch ----------------
__device__ float g_A1[NR*HD], g_A2[NR*HD], g_B1[NR*HD], g_B2[NR*HD], g_X1[NR*HD], g_X2[NR*HD];
__device__ float g_U1[NR*HD], g_U2[NR*HD], g_U3[NR*HD];
__device__ float g_F1[NR*HD], g_F2[NR*HD], g_F3[NR*HD];
__device__ float g_W1[NR*HD], g_W2[NR*HD], g_W3[NR*HD];
__device__ float g_Q1[NR*HD], g_Q2[NR*HD], g_Q3[NR*HD];
__device__ float g_h1p[NR*HD], g_h1s[NR*HD], g_h1e[NR*HD];
__device__ float g_yp[NR*HD], g_ys[NR*HD], g_ye[NR*HD];
__device__ float g_nhp2[NR], g_nhs2[NR], g_lyp[NR], g_lys[NR];
__device__ float g_q1ss[NR], g_q2ss[NR], g_c1vss[NR], g_c2vss[NR];
__device__ float g_T1[NR*HD], g_T2[NR*HD], g_T3[NR*HD];
__device__ float g_c1v[NR*HD], g_c2v[NR*HD], g_c3v[NR*HD];
__device__ float g_G1[NR*H3], g_G2[NR*H3], g_G3[NR*H3];

// packed bf16 hi/lo weights
#define OFF_UP 0
#define OFF_UF 8192
#define OFF_WC 16384
#define OFF_WQ 24576
#define OFF_IOU 32768
#define WPK_TOT 57344
__device__ unsigned int g_Whi[WPK_TOT], g_Wlo[WPK_TOT];

// ---------------- fast transcendentals ----------------
__device__ __forceinline__ float sigm(float v){
  return __fdividef(1.f, 1.f + __expf(-v));
}
__device__ __forceinline__ float ftanh(float v){
  return fmaf(2.f, __fdividef(1.f, 1.f + __expf(-2.f*v)), -1.f);
}
__device__ __forceinline__ float fatanh(float u){
  return 0.5f*__logf(__fdividef(1.f+u, 1.f-u));
}
__device__ __forceinline__ float artk(float u, float k){
  if (k < 0.f){ u = fminf(fmaxf(u, -1.f+1e-5f), 1.f-1e-5f); return fatanh(u); }
  return atanf(u);
}
__device__ __forceinline__ float tank(float u, float k){
  if (k < 0.f) return ftanh(u);
  return __tanf(fminf(fmaxf(u, -1.47079f), 1.47079f));
}
__device__ __forceinline__ float sden(float d){
  return d >= 0.f ? fmaxf(d, EPSF) : fminf(d, -EPSF);
}
__device__ __forceinline__ float nrm(float ss){ return sqrtf(ss + 1e-15f); }

// ---------------- reductions ----------------
template<int N> __device__ __forceinline__ void redN(float* v){
  #pragma unroll
  for (int o=16;o;o>>=1){
    float t[N];
    #pragma unroll
    for (int i=0;i<N;i++) t[i] = __shfl_xor_sync(0xffffffffu, v[i], o);
    #pragma unroll
    for (int i=0;i<N;i++) v[i] += t[i];
  }
}
template<int V> __device__ __forceinline__ float pdot(const float* a, const float* b){
  float s = 0.f;
  #pragma unroll
  for (int i=0;i<V;i++) s += a[i]*b[i];
  return s;
}
template<int V> __device__ __forceinline__ float pss(const float* a){ return pdot<V>(a,a); }

// ---------------- analytic (norm-tracked) manifold ops ----------------
template<int V> __device__ __forceinline__ void vscale(float* a, float f){
  #pragma unroll
  for (int i=0;i<V;i++) a[i]*=f;
}
template<int V> __device__ __forceinline__ float aexp0(float* a, float k, float ss){
  float n = nrm(ss);
  float t = tank(n,k);
  if (k < 0.f) t = fminf(t, 1.f-1e-4f);
  vscale<V>(a, __fdividef(t,n));
  return t*t;
}
template<int V> __device__ __forceinline__ float alog0(float* a, float k, float ss){
  float n = nrm(ss);
  float t = artk(n,k);
  vscale<V>(a, __fdividef(t,n));
  return t*t;
}
template<int V> __device__ __forceinline__ float aexplog(float* a, float k, float ss){
  float n = nrm(ss);
  float t;
  if (k < 0.f) t = fatanh(fminf(ftanh(n), 1.f-1e-4f));
  else         t = fminf(n, 1.47079f);
  vscale<V>(a, __fdividef(t,n));
  return t*t;
}
template<int V> __device__ __forceinline__ float asmul(float* a, float r, float k, float ss){
  float n = nrm(ss);
  float t = tank(r*artk(n,k),k);
  if (k < 0.f) t = fminf(t, 1.f-1e-4f);
  vscale<V>(a, __fdividef(t,n));
  return t*t;
}
template<int V> __device__ __forceinline__ float apw(float* wx, float k, float ssx, float ssw){
  float nx = nrm(ssx), nwx = nrm(ssw);
  float t = tank(__fdividef(nwx,nx)*artk(nx,k),k);
  if (k < 0.f) t = fminf(t, 1.f-1e-4f);
  vscale<V>(wx, __fdividef(t,nwx));
  return t*t;
}
template<int V> __device__ __forceinline__ float aproj(float* a, float ss){
  float n = nrm(ss);
  const float m = 1.f-1e-4f;
  if (n > m){ float f = __fdividef(m,n); vscale<V>(a, f); return ss*f*f; }
  return ss;
}
__device__ __forceinline__ void amadd_coef(float k, float x2, float y2, float xy,
                                           float& ca, float& cb, float& isd){
  ca = 1.f - 2.f*k*xy - k*y2;
  cb = 1.f + k*x2;
  isd = __fdividef(1.f, sden(1.f - 2.f*k*xy + k*k*x2*y2));
}
__device__ __forceinline__ float distf(float x2, float y2, float xy, float k){
  float ca = 1.f + 2.f*k*xy - k*y2;
  float cb = 1.f + k*x2;
  float sd = sden(1.f + 2.f*k*xy + k*k*x2*y2);
  float s = fmaxf(ca*ca*x2 + cb*cb*y2 - 2.f*ca*cb*xy, 0.f);
  float nv2 = __fdividef(s, sd*sd);
  float pn = sqrtf(nv2 + 1e-15f);
  if (k < 0.f){
    const float m = 1.f - 1e-4f;
    if (pn > m){ float sc = __fdividef(m,pn); pn = sqrtf(nv2*sc*sc + 1e-15f); }
  }
  return 2.f*artk(pn, k);
}
__device__ __forceinline__ void ldrow(float* a, const float* p, int row, int lane){
  #pragma unroll
  for (int i=0;i<4;i++) a[i] = p[(size_t)row*HD + i*32 + lane];
}
__device__ __forceinline__ void strow(const float* a, float* p, int row, int lane){
  #pragma unroll
  for (int i=0;i<4;i++) p[(size_t)row*HD + i*32 + lane] = a[i];
}

// ---------------- bf16 split helpers ----------------
__device__ __forceinline__ unsigned int packbf(__nv_bfloat16 lo, __nv_bfloat16 hi){
  __nv_bfloat162 t = __halves2bfloat162(lo, hi);
  return *reinterpret_cast<unsigned int*>(&t);
}
__device__ __forceinline__ void splitbf(float f, __nv_bfloat16& h, __nv_bfloat16& l){
  h = __float2bfloat16_rn(f);
  l = __float2bfloat16_rn(f - __bfloat162float(h));
}
#define MMA_BF16(c, a, b0, b1) \
  asm volatile("mma.sync.aligned.m16n8k16.row.col.f32.bf16.bf16.f32 " \
    "{%0,%1,%2,%3}, {%4,%5,%6,%7}, {%8,%9}, {%0,%1,%2,%3};" \
    : "+f"((c)[0]),"+f"((c)[1]),"+f"((c)[2]),"+f"((c)[3]) \
    : "r"((a)[0]),"r"((a)[1]),"r"((a)[2]),"r"((a)[3]), "r"(b0),"r"(b1))

// ---------------- k1: packed prep + weight split ----------------
__global__ void __launch_bounds__(256) k_prepwc(const float* __restrict__ x,
    const float* __restrict__ h1, const float* __restrict__ h2,
    const float* __restrict__ c1, const float* __restrict__ c2,
    const float* __restrict__ Up_w, const float* __restrict__ Uf_w,
    const float* __restrict__ Wc_w, const float* __restrict__ Wq_w,
    const float* __restrict__ Uiou_w){
  if (blockIdx.x < NB){
    int r = blockIdx.x*8 + (threadIdx.x>>5);
    int lane = threadIdx.x & 31;
    float a1[4],a2[4],b1[4],b2[4],xx[4];
    ldrow(a1,h1,r,lane); ldrow(a2,h2,r,lane);
    ldrow(b1,c1,r,lane); ldrow(b2,c2,r,lane);
    ldrow(xx,x ,r,lane);
    float rv[5] = {pss<4>(a1),pss<4>(a2),pss<4>(b1),pss<4>(b2),pss<4>(xx)};
    redN<5>(rv);
    alog0<4>(a1,-1.f,rv[0]); strow(a1,g_A1,r,lane);
    alog0<4>(a2, 1.f,rv[1]); strow(a2,g_A2,r,lane);
    alog0<4>(b1,-1.f,rv[2]); strow(b1,g_B1,r,lane);
    alog0<4>(b2, 1.f,rv[3]); strow(b2,g_B2,r,lane);
    float xc[4];
    #pragma unroll
    for (int i=0;i<4;i++) xc[i]=xx[i];
    aexplog<4>(xc,-1.f,rv[4]); strow(xc,g_X1,r,lane);
    aexplog<4>(xx, 1.f,rv[4]); strow(xx,g_X2,r,lane);
  } else {
    int e = (blockIdx.x - NB)*256 + threadIdx.x;
    const float* src; int off;
    if (e < OFF_UF)        { src = Up_w;   off = e - OFF_UP; }
    else if (e < OFF_WC)   { src = Uf_w;   off = e - OFF_UF; }
    else if (e < OFF_WQ)   { src = Wc_w;   off = e - OFF_WC; }
    else if (e < OFF_IOU)  { src = Wq_w;   off = e - OFF_WQ; }
    else                   { src = Uiou_w; off = e - OFF_IOU; }
    float f0 = src[(size_t)off*2], f1 = src[(size_t)off*2+1];
    __nv_bfloat16 h0,l0,h1b,l1b;
    splitbf(f0,h0,l0); splitbf(f1,h1b,l1b);
    g_Whi[e] = packbf(h0,h1b);
    g_Wlo[e] = packbf(l0,l1b);
  }
}

// ---------------- tensor-core GEMM: double-buffered, 1 sync/chunk ----------------
#define KP2 20
#define BUFU 10240
__device__ __forceinline__ void gemm_tc_body(
    const float* __restrict__ A, const unsigned int* __restrict__ Wh_g,
    const unsigned int* __restrict__ Wl_g, const float* __restrict__ bias,
    float* __restrict__ C, int ldc, int colOff, int m0){
  extern __shared__ unsigned int smdy[];
  int tid = threadIdx.x;
  int lane = tid & 31, wid = tid >> 5;
  int warpM = wid & 3, warpN = wid >> 2;
  int gid = lane >> 2, tig = lane & 3;
  float acc[2][8][4];
  #pragma unroll
  for (int mi=0;mi<2;mi++)
    #pragma unroll
    for (int ni=0;ni<8;ni++)
      #pragma unroll
      for (int q=0;q<4;q++) acc[mi][ni][q]=0.f;

  int ar = (tid>>3), akq = (tid&7)*4;
  int wr = (tid>>2), wkq = (tid&3)*4;
  float4 av[4]; uint4 whv[2], wlv[2];
  #pragma unroll
  for (int p=0;p<4;p++)
    av[p] = *(const float4*)(A + (size_t)(m0+ar+p*32)*HD + akq);
  #pragma unroll
  for (int t=0;t<2;t++){
    whv[t] = *(const uint4*)(Wh_g + (size_t)(wr+t*64)*64 + wkq);
    wlv[t] = *(const uint4*)(Wl_g + (size_t)(wr+t*64)*64 + wkq);
  }

  for (int c=0; c<4; c++){
    unsigned int* SAh = smdy + (c&1)*BUFU;
    unsigned int* SAl = SAh + 2560;
    unsigned int* SWh = SAh + 5120;
    unsigned int* SWl = SAh + 7680;
    #pragma unroll
    for (int p=0;p<4;p++){
      int rr = ar + p*32;
      __nv_bfloat16 h0,l0,h1,l1;
      splitbf(av[p].x,h0,l0); splitbf(av[p].y,h1,l1);
      SAh[rr*KP2 + (akq>>1)  ] = packbf(h0,h1);
      SAl[rr*KP2 + (akq>>1)  ] = packbf(l0,l1);
      splitbf(av[p].z,h0,l0); splitbf(av[p].w,h1,l1);
      SAh[rr*KP2 + (akq>>1)+1] = packbf(h0,h1);
      SAl[rr*KP2 + (akq>>1)+1] = packbf(l0,l1);
    }
    #pragma unroll
    for (int t=0;t<2;t++){
      *(uint4*)&SWh[(wr+t*64)*KP2 + wkq] = whv[t];
      *(uint4*)&SWl[(wr+t*64)*KP2 + wkq] = wlv[t];
    }
    __syncthreads();
    if (c < 3){
      int kt = (c+1)*32;
      #pragma unroll
      for (int p=0;p<4;p++)
        av[p] = *(const float4*)(A + (size_t)(m0+ar+p*32)*HD + kt + akq);
      #pragma unroll
      for (int t=0;t<2;t++){
        whv[t] = *(const uint4*)(Wh_g + (size_t)(wr+t*64)*64 + (kt>>1) + wkq);
        wlv[t] = *(const uint4*)(Wl_g + (size_t)(wr+t*64)*64 + (kt>>1) + wkq);
      }
    }
    #pragma unroll
    for (int ks=0; ks<2; ks++){
      int kb = ks*8;
      unsigned int ah[2][4], al[2][4];
      #pragma unroll
      for (int mi=0;mi<2;mi++){
        int r0 = warpM*32 + mi*16 + gid;
        ah[mi][0]=SAh[r0*KP2+kb+tig];     ah[mi][1]=SAh[(r0+8)*KP2+kb+tig];
        ah[mi][2]=SAh[r0*KP2+kb+tig+4];   ah[mi][3]=SAh[(r0+8)*KP2+kb+tig+4];
        al[mi][0]=SAl[r0*KP2+kb+tig];     al[mi][1]=SAl[(r0+8)*KP2+kb+tig];
        al[mi][2]=SAl[r0*KP2+kb+tig+4];   al[mi][3]=SAl[(r0+8)*KP2+kb+tig+4];
      }
      #pragma unroll
      for (int ni=0;ni<8;ni++){
        int c0 = warpN*64 + ni*8 + gid;
        unsigned int bh0 = SWh[c0*KP2+kb+tig], bh1 = SWh[c0*KP2+kb+tig+4];
        unsigned int bl0 = SWl[c0*KP2+kb+tig], bl1 = SWl[c0*KP2+kb+tig+4];
        #pragma unroll
        for (int mi=0;mi<2;mi++){
          MMA_BF16(acc[mi][ni], ah[mi], bh0, bh1);
          MMA_BF16(acc[mi][ni], ah[mi], bl0, bl1);
          MMA_BF16(acc[mi][ni], al[mi], bh0, bh1);
        }
      }
    }
  }
  #pragma unroll
  for (int mi=0;mi<2;mi++){
    int r = m0 + warpM*32 + mi*16 + gid;
    #pragma unroll
    for (int ni=0;ni<8;ni++){
      int c = colOff + warpN*64 + ni*8 + tig*2;
      float b0 = bias[c], b1 = bias[c+1];
      float2 v0 = make_float2(acc[mi][ni][0]+b0, acc[mi][ni][1]+b1);
      float2 v1 = make_float2(acc[mi][ni][2]+b0, acc[mi][ni][3]+b1);
      *(float2*)(C + (size_t)r*ldc + c) = v0;
      *(float2*)(C + (size_t)(r+8)*ldc + c) = v1;
    }
  }
}

__global__ void __launch_bounds__(256) k_gemm_tc(const float* __restrict__ x,
    const float* __restrict__ h3, const float* __restrict__ c3,
    const float* __restrict__ Up_b, const float* __restrict__ Uf_b,
    const float* __restrict__ Wc_b, const float* __restrict__ Wq_b){
  const float *A, *bias; float* C; int woff;
  switch (blockIdx.z){
    case 0:  A=g_A1; woff=OFF_UP; bias=Up_b; C=g_U1; break;
    case 1:  A=g_A2; woff=OFF_UP; bias=Up_b; C=g_U2; break;
    case 2:  A=h3;   woff=OFF_UP; bias=Up_b; C=g_U3; break;
    case 3:  A=g_A1; woff=OFF_UF; bias=Uf_b; C=g_F1; break;
    case 4:  A=g_A2; woff=OFF_UF; bias=Uf_b; C=g_F2; break;
    case 5:  A=h3;   woff=OFF_UF; bias=Uf_b; C=g_F3; break;
    case 6:  A=g_B1; woff=OFF_WC; bias=Wc_b; C=g_W1; break;
    case 7:  A=g_B2; woff=OFF_WC; bias=Wc_b; C=g_W2; break;
    case 8:  A=c3;   woff=OFF_WC; bias=Wc_b; C=g_W3; break;
    case 9:  A=g_X1; woff=OFF_WQ; bias=Wq_b; C=g_Q1; break;
    case 10: A=g_X2; woff=OFF_WQ; bias=Wq_b; C=g_Q2; break;
    default: A=x;    woff=OFF_WQ; bias=Wq_b; C=g_Q3; break;
  }
  gemm_tc_body(A, g_Whi+woff, g_Wlo+woff, bias, C, HD, 0, blockIdx.x*128);
}

__global__ void __launch_bounds__(256) k_iou_tc(const float* __restrict__ Uiou_b){
  const float* A; float* C;
  switch (blockIdx.z){
    case 0:  A=g_T1; C=g_G1; break;
    case 1:  A=g_T2; C=g_G2; break;
    default: A=g_T3; C=g_G3; break;
  }
  int colOff = blockIdx.y*128;
  gemm_tc_body(A, g_Whi + OFF_IOU + (size_t)colOff*64,
               g_Wlo + OFF_IOU + (size_t)colOff*64,
               Uiou_b, C, H3, colOff, blockIdx.x*128);
}

// ---------------- rowwise post bodies ----------------
__device__ __forceinline__ void hpost_row(int r, int lane,
    const float* __restrict__ h1, const float* __restrict__ h2,
    const float* __restrict__ h3){
  float s1[4], s2[4], s3[4], vh1[4], vh2[4], vh3[4], q1[4], q2[4];
  ldrow(s1,g_U1,r,lane); ldrow(s2,g_U2,r,lane); ldrow(s3,g_U3,r,lane);
  ldrow(vh1,h1,r,lane);  ldrow(vh2,h2,r,lane);  ldrow(vh3,h3,r,lane);
  ldrow(q1,g_Q1,r,lane); ldrow(q2,g_Q2,r,lane);

  float rv[7] = {pss<4>(s1),pss<4>(s2),pss<4>(vh1),pss<4>(vh2),pss<4>(vh3),
                 pss<4>(q1),pss<4>(q2)};
  redN<7>(rv);
  float ssh1=rv[2], ssh2=rv[3], ssh3=rv[4];

  aexp0<4>(s1,-1.f,rv[0]);
  aexp0<4>(s2, 1.f,rv[1]);
  #pragma unroll
  for (int i=0;i<4;i++){ s1[i]=sigm(s1[i]); s2[i]=sigm(s2[i]); s3[i]=sigm(s3[i]); }
  float rv2[2] = {pss<4>(s1), pss<4>(s2)};
  redN<2>(rv2);
  alog0<4>(s1,-1.f,rv2[0]);
  alog0<4>(s2, 1.f,rv2[1]);

  float n2h = nrm(ssh2);
  float t2p = ftanh(atanf(n2h));
  float f2p = __fdividef(t2p,n2h);  float ssx2p = t2p*t2p;
  float n3h = nrm(ssh3);
  float t3p = fminf(ftanh(n3h), 1.f-1e-4f);
  float f3p = __fdividef(t3p,n3h);  float ssx3p = t3p*t3p;
  float n1h = nrm(ssh1);
  float a1t = artk(n1h,-1.f);
  float t1s = __tanf(fminf(a1t, 1.47079f));
  float f1s = __fdividef(t1s,n1h);  float ssx1s = t1s*t1s;
  float t3s = __tanf(fminf(n3h, 1.47079f));
  float f3s = __fdividef(t3s,n3h);  float ssx3s = t3s*t3s;

  float w1p[4],w2p[4],w3p[4],w1s[4],w2s[4],w3s[4];
  #pragma unroll
  for (int i=0;i<4;i++){
    w1p[i]=s1[i]*vh1[i];
    w2p[i]=s2[i]*vh2[i]*f2p;
    w3p[i]=s3[i]*vh3[i]*f3p;
    w1s[i]=s1[i]*vh1[i]*f1s;
    w2s[i]=s2[i]*vh2[i];
    w3s[i]=s3[i]*vh3[i]*f3s;
  }
  float rv3[6] = {pss<4>(w1p),pss<4>(w2p),pss<4>(w3p),
                  pss<4>(w1s),pss<4>(w2s),pss<4>(w3s)};
  redN<6>(rv3);
  float r1p = apw<4>(w1p,-1.f, ssh1,  rv3[0]);
  float r2p = apw<4>(w2p,-1.f, ssx2p, rv3[1]);
  float r3p = apw<4>(w3p,-1.f, ssx3p, rv3[2]);
  float r1s = apw<4>(w1s,-1.f, ssx1s, rv3[3]);
  float r2s = apw<4>(w2s, 1.f, ssh2,  rv3[4]);
  float r3s = apw<4>(w3s, 1.f, ssx3s, rv3[5]);

  float lap=__fdividef(2.f,1.f-r1p), lbp=__fdividef(2.f,1.f-r2p), lcp=__fdividef(2.f,1.f-r3p);
  float idenp = __fdividef(1.f, fmaxf(fabsf(lap+lbp+lcp-3.f), EPSF));
  float las=__fdividef(2.f,1.f-r1s), lbs=__fdividef(2.f,1.f-r2s), lcs=__fdividef(2.f,1.f-r3s);
  float idens = __fdividef(1.f, fmaxf(fabsf(las+lbs+lcs-3.f), EPSF));
  float sp[4], sv[4];
  #pragma unroll
  for (int i=0;i<4;i++){
    sp[i] = (lap*w1p[i]+lbp*w2p[i]+lcp*w3p[i])*idenp;
    sv[i] = (las*w1s[i]+lbs*w2s[i]+lcs*w3s[i])*idens;
  }
  float rv4[2] = {pss<4>(sp), pss<4>(sv)};
  redN<2>(rv4);
  float tp2 = asmul<4>(sp,0.5f,-1.f,rv4[0]);
  float ts2 = asmul<4>(sv,0.5f,-1.f,rv4[1]);
  #pragma unroll
  for (int i=0;i<4;i++){ sp[i]*=3.f; sv[i]*=3.f; }
  strow(sp,g_h1p,r,lane);
  strow(sv,g_h1s,r,lane);
  if (lane==0){ g_nhp2[r]=9.f*tp2; g_nhs2[r]=9.f*ts2; }

  float fe1 = __fdividef(artk(nrm(r1p),-1.f), nrm(r1p));
  float fe2 = __fdividef(artk(nrm(r2s), 1.f), nrm(r2s));
  float he[4];
  #pragma unroll
  for (int i=0;i<4;i++) he[i] = w1p[i]*fe1 + w2s[i]*fe2 + s3[i]*vh3[i];
  strow(he,g_h1e,r,lane);

  float xe1 = aexp0<4>(q1,-1.f,rv[5]); strow(q1,g_X1,r,lane);
  float xe2 = aexp0<4>(q2, 1.f,rv[6]); strow(q2,g_X2,r,lane);
  if (lane==0){ g_q1ss[r]=xe1; g_q2ss[r]=xe2; }
}

__device__ __forceinline__ void cpost_row(int r, int lane,
    const float* __restrict__ c1, const float* __restrict__ c2,
    const float* __restrict__ c3, const float* __restrict__ del_t,
    const float* __restrict__ dptr){
  float g = __fdividef(dptr[0], del_t[r] + 1.f);

  float w1[4],w2[4],vc1[4],vc2[4],f1[4],f2[4];
  ldrow(w1,g_W1,r,lane); ldrow(w2,g_W2,r,lane);
  ldrow(vc1,c1,r,lane);  ldrow(vc2,c2,r,lane);
  ldrow(f1,g_F1,r,lane); ldrow(f2,g_F2,r,lane);
  float rv[6] = {pss<4>(w1),pss<4>(w2),pss<4>(vc1),pss<4>(vc2),
                 pss<4>(f1),pss<4>(f2)};
  redN<6>(rv);

  aexplog<4>(w1,-1.f,rv[0]);
  aexplog<4>(w2, 1.f,rv[1]);
  #pragma unroll
  for (int i=0;i<4;i++){ w1[i]=ftanh(w1[i]); w2[i]=ftanh(w2[i]); }
  float rv2[2] = {pss<4>(w1), pss<4>(w2)};
  redN<2>(rv2);
  float sscp = aexp0<4>(w1,-1.f,rv2[0]);
  float sscs = aexp0<4>(w2, 1.f,rv2[1]);

  float pgp[4], pgs[4];
  #pragma unroll
  for (int i=0;i<4;i++){ pgp[i]=w1[i]*g; pgs[i]=w2[i]*g; }
  float rpgp = apw<4>(pgp,-1.f, g*g, g*g*sscp);
  float rpgs = apw<4>(pgs, 1.f, g*g, g*g*sscs);

  float rv3[2] = {pdot<4>(w1,vc1), pdot<4>(w2,vc2)};
  redN<2>(rv3);
  float ca,cb,isd;
  amadd_coef(-1.f, sscp, rv[2], -rv3[0], ca, cb, isd);
  float map[4];
  #pragma unroll
  for (int i=0;i<4;i++) map[i] = (ca*(-w1[i]) + cb*vc1[i])*isd;
  amadd_coef( 1.f, sscs, rv[3], -rv3[1], ca, cb, isd);
  float mas[4];
  #pragma unroll
  for (int i=0;i<4;i++) mas[i] = (ca*(-w2[i]) + cb*vc2[i])*isd;

  float rv4[4] = {pss<4>(map), pdot<4>(map,pgp), pss<4>(mas), pdot<4>(mas,pgs)};
  redN<4>(rv4);
  {
    float n = nrm(rv4[0]);
    const float m = 1.f-1e-4f;
    if (n > m){
      float f = __fdividef(m,n);
      #pragma unroll
      for (int i=0;i<4;i++) map[i]*=f;
      rv4[1]*=f; rv4[0]*=f*f;
    }
  }
  amadd_coef(-1.f, rv4[0], rpgp, rv4[1], ca, cb, isd);
  float ckp[4];
  #pragma unroll
  for (int i=0;i<4;i++) ckp[i] = (ca*map[i] + cb*pgp[i])*isd;
  amadd_coef( 1.f, rv4[2], rpgs, rv4[3], ca, cb, isd);
  float cks[4];
  #pragma unroll
  for (int i=0;i<4;i++) cks[i] = (ca*mas[i] + cb*pgs[i])*isd;

  aexplog<4>(f1,-1.f,rv[4]);
  aexplog<4>(f2, 1.f,rv[5]);
  #pragma unroll
  for (int i=0;i<4;i++){ f1[i]=sigm(f1[i]); f2[i]=sigm(f2[i]); }

  float wxs[4];
  #pragma unroll
  for (int i=0;i<4;i++) wxs[i]=f2[i]*cks[i];
  float rv5[3] = {pss<4>(ckp), pss<4>(cks), pss<4>(wxs)};
  redN<3>(rv5);
  float ssckp = aproj<4>(ckp, rv5[0]);
  float wxp[4];
  #pragma unroll
  for (int i=0;i<4;i++) wxp[i]=f1[i]*ckp[i];
  float rv6[1] = {pss<4>(wxp)};
  redN<1>(rv6);
  float ryp = apw<4>(wxp,-1.f, ssckp, rv6[0]);
  float rys = apw<4>(wxs, 1.f, rv5[1], rv5[2]);
  strow(wxp,g_yp,r,lane);
  strow(wxs,g_ys,r,lane);
  if (lane==0){ g_lyp[r]=__fdividef(2.f,1.f-ryp); g_lys[r]=__fdividef(2.f,1.f+rys); }

  {
    float w3[4],vc3[4],f3[4];
    ldrow(w3,g_W3,r,lane); ldrow(vc3,c3,r,lane); ldrow(f3,g_F3,r,lane);
    float y[4];
    #pragma unroll
    for (int i=0;i<4;i++){
      float csk = ftanh(w3[i]);
      y[i] = sigm(f3[i])*(vc3[i] - csk + csk*g);
    }
    strow(y,g_ye,r,lane);
  }
}

// ---------------- k3: packed hpost + cpost ----------------
__global__ void __launch_bounds__(256) k_post2(const float* __restrict__ h1,
    const float* __restrict__ h2, const float* __restrict__ h3,
    const float* __restrict__ c1, const float* __restrict__ c2,
    const float* __restrict__ c3, const float* __restrict__ del_t,
    const float* __restrict__ dptr){
  int lane = threadIdx.x & 31;
  int w = threadIdx.x >> 5;
  if (blockIdx.x < NB){
    hpost_row(blockIdx.x*8 + w, lane, h1, h2, h3);
  } else {
    cpost_row((blockIdx.x - NB)*8 + w, lane, c1, c2, c3, del_t, dptr);
  }
}

// ---------------- hyperbolic attention section (two-pass, low-reg) ----------------
// Y = gathered points, ss = per-row sumsq, q/qss = query, k = curvature
__device__ __forceinline__ void hyp_attn_sec(int n, int lane, const int* __restrict__ nbr,
    const float* __restrict__ Q, const float* __restrict__ QSS,
    const float* __restrict__ Y, const float* __restrict__ YSS,
    float* __restrict__ T, float kk){
  int j[KN];
  #pragma unroll
  for (int k=0;k<KN;k++) j[k] = nbr[n*KN+k];
  float q[4]; ldrow(q,Q,n,lane);
  float q2 = QSS[n];
  float d[KN], y2k[KN];
  #pragma unroll
  for (int k=0;k<KN;k++){
    float yk[4]; ldrow(yk, Y, j[k], lane);
    y2k[k] = YSS[j[k]];
    d[k] = pdot<4>(q, yk);
  }
  redN<KN>(d);
  // softmax over -dist, then weights a*lam (den needs only scalars)
  #pragma unroll
  for (int k=0;k<KN;k++) d[k] = -distf(q2, y2k[k], d[k], kk);
  float m = d[0];
  #pragma unroll
  for (int k=1;k<KN;k++) m = fmaxf(m, d[k]);
  float ssum = 0.f;
  #pragma unroll
  for (int k=0;k<KN;k++){ d[k] = __expf(d[k]-m); ssum += d[k]; }
  float issum = __fdividef(1.f, ssum);
  float den = 0.f;
  #pragma unroll
  for (int k=0;k<KN;k++){
    float a = d[k]*issum;
    float lam = __fdividef(2.f, 1.f + kk*y2k[k]);
    d[k] = a*lam;                 // reuse d as weight
    den += a*(lam-1.f);
  }
  float iden = __fdividef(1.f, fmaxf(fabsf(den), EPSF));
  // pass 2: re-gather and accumulate
  float num[4] = {0,0,0,0};
  #pragma unroll
  for (int k=0;k<KN;k++){
    float yk[4]; ldrow(yk, Y, j[k], lane);
    #pragma unroll
    for (int i=0;i<4;i++) num[i] += d[k]*yk[i];
  }
  #pragma unroll
  for (int i=0;i<4;i++) num[i]*=iden;
  float rv[1] = {pss<4>(num)};
  redN<1>(rv);
  float ssT = asmul<4>(num,0.5f,kk,rv[0]);
  alog0<4>(num,kk,ssT);
  strow(num,T,n,lane);
}

// ---------------- k5: attention + K-aggregation, section-split ----------------
__global__ void __launch_bounds__(256) k_agg(const int* __restrict__ nbr){
  int sec  = blockIdx.x >> 10;          // 4 sections x 1024 blocks
  int blk  = blockIdx.x & 1023;
  int n    = blk*8 + (threadIdx.x>>5);
  int lane = threadIdx.x & 31;

  if (sec == 0){
    hyp_attn_sec(n, lane, nbr, g_X1, g_q1ss, g_h1p, g_nhp2, g_T1, -1.f);
  } else if (sec == 1){
    hyp_attn_sec(n, lane, nbr, g_X2, g_q2ss, g_h1s, g_nhs2, g_T2,  1.f);
  } else if (sec == 2){
    // Euclid attention (two-pass)
    int j[KN];
    #pragma unroll
    for (int k=0;k<KN;k++) j[k] = nbr[n*KN+k];
    float q[4]; ldrow(q,g_Q3,n,lane);
    float d[KN];
    #pragma unroll
    for (int k=0;k<KN;k++){
      float yk[4]; ldrow(yk, g_h1e, j[k], lane);
      d[k] = pdot<4>(q, yk);
    }
    redN<KN>(d);
    #pragma unroll
    for (int k=0;k<KN;k++) d[k] *= 0.08838834764831845f;
    float m = d[0];
    #pragma unroll
    for (int k=1;k<KN;k++) m = fmaxf(m, d[k]);
    float ssum = 0.f;
    #pragma unroll
    for (int k=0;k<KN;k++){ d[k] = __expf(d[k]-m); ssum += d[k]; }
    float issum = __fdividef(1.f, ssum);
    float num[4] = {0,0,0,0};
    #pragma unroll
    for (int k=0;k<KN;k++){
      float a = d[k]*issum;
      float yk[4]; ldrow(yk, g_h1e, j[k], lane);
      #pragma unroll
      for (int i=0;i<4;i++) num[i] += a*yk[i];
    }
    strow(num,g_T3,n,lane);
  } else {
    // cell aggregation
    int j[KN];
    #pragma unroll
    for (int k=0;k<KN;k++) j[k] = nbr[n*KN+k];
    float np[4]={0,0,0,0}, ns[4]={0,0,0,0}, ne[4]={0,0,0,0};
    float dp=0.f, ds=0.f;
    #pragma unroll
    for (int k=0;k<KN;k++){
      float y[4];
      ldrow(y, g_yp, j[k], lane);
      float lam = g_lyp[j[k]];
      #pragma unroll
      for (int i=0;i<4;i++) np[i] += lam*y[i];
      dp += lam-1.f;
      ldrow(y, g_ys, j[k], lane);
      lam = g_lys[j[k]];
      #pragma unroll
      for (int i=0;i<4;i++) ns[i] += lam*y[i];
      ds += lam-1.f;
      ldrow(y, g_ye, j[k], lane);
      #pragma unroll
      for (int i=0;i<4;i++) ne[i] += y[i];
    }
    float idp = __fdividef(1.f, fmaxf(fabsf(dp), EPSF));
    float ids = __fdividef(1.f, fmaxf(fabsf(ds), EPSF));
    #pragma unroll
    for (int i=0;i<4;i++){ np[i]*=idp; ns[i]*=ids; }
    float rv[2] = {pss<4>(np), pss<4>(ns)};
    redN<2>(rv);
    float ssc1 = asmul<4>(np,0.5f,-1.f,rv[0]);
    float ssc2 = asmul<4>(ns,0.5f, 1.f,rv[1]);
    strow(np,g_c1v,n,lane);
    strow(ns,g_c2v,n,lane);
    strow(ne,g_c3v,n,lane);
    if (lane==0){ g_c1vss[n]=ssc1; g_c2vss[n]=ssc2; }
  }
}

// ---------------- k7: apply_node_func ----------------
__global__ void __launch_bounds__(256) k_final(const float* __restrict__ iou1,
    const float* __restrict__ iou2, const float* __restrict__ iou3,
    float* __restrict__ out){
  int r = blockIdx.x*8 + (threadIdx.x>>5);
  int lane = threadIdx.x & 31;

  float e1[12], a1[12], e2[12], a2[12];
  #pragma unroll
  for (int i=0;i<12;i++){
    e1[i] = g_G1[(size_t)r*H3 + i*32 + lane];
    a1[i] = iou1[(size_t)r*H3 + i*32 + lane];
    e2[i] = g_G2[(size_t)r*H3 + i*32 + lane];
    a2[i] = iou2[(size_t)r*H3 + i*32 + lane];
  }
  float rv[4] = {pss<12>(e1), pss<12>(a1), pss<12>(e2), pss<12>(a2)};
  redN<4>(rv);
  float sse1 = aexp0<12>(e1,-1.f,rv[0]);
  float sse2 = aexp0<12>(e2, 1.f,rv[2]);
  float rv2[2] = {pdot<12>(a1,e1), pdot<12>(a2,e2)};
  redN<2>(rv2);
  float ca,cb,isd;
  float nio1[12], nio2[12];
  amadd_coef(-1.f, rv[1], sse1, rv2[0], ca, cb, isd);
  #pragma unroll
  for (int i=0;i<12;i++) nio1[i] = (ca*a1[i] + cb*e1[i])*isd;
  amadd_coef( 1.f, rv[3], sse2, rv2[1], ca, cb, isd);
  #pragma unroll
  for (int i=0;i<12;i++) nio2[i] = (ca*a2[i] + cb*e2[i])*isd;

  float rv3[7] = {pss<12>(nio1),
                  pss<4>(nio1), pss<4>(nio1+4), pss<4>(nio1+8),
                  pss<4>(nio2), pss<4>(nio2+4), pss<4>(nio2+8)};
  redN<7>(rv3);
  {
    float nn = nrm(rv3[0]);
    const float m = 1.f-1e-4f;
    if (nn > m){
      float f = __fdividef(m,nn);
      #pragma unroll
      for (int i=0;i<12;i++) nio1[i]*=f;
      rv3[1]*=f*f; rv3[2]*=f*f; rv3[3]*=f*f;
    }
  }
  float ip1[4], op1[4], up1[4], ip2[4], op2[4], up2[4];
  {
    float fi = __fdividef(artk(nrm(rv3[1]),-1.f), nrm(rv3[1]));
    float fo = __fdividef(artk(nrm(rv3[2]),-1.f), nrm(rv3[2]));
    float fu = __fdividef(artk(nrm(rv3[3]),-1.f), nrm(rv3[3]));
    #pragma unroll
    for (int i=0;i<4;i++){
      ip1[i]=sigm(nio1[i]*fi); op1[i]=sigm(nio1[4+i]*fo); up1[i]=ftanh(nio1[8+i]*fu);
    }
    fi = __fdividef(artk(nrm(rv3[4]),1.f), nrm(rv3[4]));
    fo = __fdividef(artk(nrm(rv3[5]),1.f), nrm(rv3[5]));
    fu = __fdividef(artk(nrm(rv3[6]),1.f), nrm(rv3[6]));
    #pragma unroll
    for (int i=0;i<4;i++){
      ip2[i]=sigm(nio2[i]*fi); op2[i]=sigm(nio2[4+i]*fo); up2[i]=ftanh(nio2[8+i]*fu);
    }
  }
  float wx1[4], wx2[4];
  #pragma unroll
  for (int i=0;i<4;i++){ wx1[i]=ip1[i]*up1[i]; wx2[i]=ip2[i]*up2[i]; }
  float rv4[4] = {pss<4>(wx1), pss<4>(up1), pss<4>(wx2), pss<4>(up2)};
  redN<4>(rv4);
  float rpw1 = apw<4>(wx1,-1.f, rv4[1], rv4[0]);
  float rpw2 = apw<4>(wx2, 1.f, rv4[3], rv4[2]);

  float cv1[4], cv2[4];
  ldrow(cv1,g_c1v,r,lane); ldrow(cv2,g_c2v,r,lane);
  float y21 = g_c1vss[r], y22 = g_c2vss[r];
  float rv5[2] = {pdot<4>(wx1,cv1), pdot<4>(wx2,cv2)};
  redN<2>(rv5);
  float nc1[4], nc2[4];
  amadd_coef(-1.f, rpw1, y21, rv5[0], ca, cb, isd);
  #pragma unroll
  for (int i=0;i<4;i++) nc1[i] = (ca*wx1[i] + cb*cv1[i])*isd;
  amadd_coef( 1.f, rpw2, y22, rv5[1], ca, cb, isd);
  #pragma unroll
  for (int i=0;i<4;i++) nc2[i] = (ca*wx2[i] + cb*cv2[i])*isd;

  float rv6[2] = {pss<4>(nc1), pss<4>(nc2)};
  redN<2>(rv6);
  float ssnc1 = aproj<4>(nc1, rv6[0]);
  strow(nc1, out + (size_t)1*NR*HD, r, lane);
  strow(nc2, out + (size_t)3*NR*HD, r, lane);

  float lg1[4], lg2[4];
  {
    float f1 = __fdividef(artk(nrm(ssnc1),-1.f), nrm(ssnc1));
    float f2 = __fdividef(artk(nrm(rv6[1]), 1.f), nrm(rv6[1]));
    #pragma unroll
    for (int i=0;i<4;i++){ lg1[i]=ftanh(nc1[i]*f1); lg2[i]=ftanh(nc2[i]*f2); }
  }
  float wy1[4], wy2[4];
  #pragma unroll
  for (int i=0;i<4;i++){ wy1[i]=op1[i]*lg1[i]; wy2[i]=op2[i]*lg2[i]; }
  float rv7[4] = {pss<4>(lg1), pss<4>(wy1), pss<4>(lg2), pss<4>(wy2)};
  redN<4>(rv7);
  apw<4>(wy1,-1.f, rv7[0], rv7[1]);
  strow(wy1, out + (size_t)0*NR*HD, r, lane);
  apw<4>(wy2, 1.f, rv7[2], rv7[3]);
  strow(wy2, out + (size_t)2*NR*HD, r, lane);

  {
    float cv[4]; ldrow(cv, g_c3v, r, lane);
    #pragma unroll
    for (int i=0;i<4;i++){
      float ie = sigm(iou3[(size_t)r*H3 + i*32 + lane]       + g_G3[(size_t)r*H3 + i*32 + lane]);
      float oe = sigm(iou3[(size_t)r*H3 + 128 + i*32 + lane] + g_G3[(size_t)r*H3 + 128 + i*32 + lane]);
      float ue = ftanh(iou3[(size_t)r*H3 + 256 + i*32 + lane] + g_G3[(size_t)r*H3 + 256 + i*32 + lane]);
      float nc = ie*ue + cv[i];
      out[(size_t)5*NR*HD + (size_t)r*HD + i*32 + lane] = nc;
      out[(size_t)4*NR*HD + (size_t)r*HD + i*32 + lane] = oe*ftanh(nc);
    }
  }
}

// ---------------- launch ----------------
extern "C" void kernel_launch(void* const* d_in, const int* in_sizes, int n_in,
                              void* d_out, int out_size){
  const float* x     = (const float*)d_in[0];
  const float* h1    = (const float*)d_in[1];
  const float* c1    = (const float*)d_in[2];
  const float* h2    = (const float*)d_in[3];
  const float* c2    = (const float*)d_in[4];
  const float* h3    = (const float*)d_in[5];
  const float* c3    = (const float*)d_in[6];
  const float* del_t = (const float*)d_in[7];
  const float* iou1  = (const float*)d_in[8];
  const float* iou2  = (const float*)d_in[9];
  const float* iou3  = (const float*)d_in[10];
  const float* Wq_w  = (const float*)d_in[11];
  const float* Wq_b  = (const float*)d_in[12];
  const float* Wc_w  = (const float*)d_in[13];
  const float* Wc_b  = (const float*)d_in[14];
  const float* Uf_w  = (const float*)d_in[15];
  const float* Uf_b  = (const float*)d_in[16];
  const float* Up_w  = (const float*)d_in[17];
  const float* Up_b  = (const float*)d_in[18];
  const float* Uiou_w= (const float*)d_in[19];
  const float* Uiou_b= (const float*)d_in[20];
  const float* dsc   = (const float*)d_in[21];
  const int*   nbr   = (const int*)d_in[22];
  float* out = (float*)d_out;

  const int GEMM_SMEM = 2*BUFU*4;   // 81920 bytes
  cudaFuncSetAttribute(k_gemm_tc, cudaFuncAttributeMaxDynamicSharedMemorySize, GEMM_SMEM);
  cudaFuncSetAttribute(k_iou_tc,  cudaFuncAttributeMaxDynamicSharedMemorySize, GEMM_SMEM);

  dim3 blk(256);
  k_prepwc<<<NB + WPK_TOT/256, blk>>>(x, h1, h2, c1, c2,
                                      Up_w, Uf_w, Wc_w, Wq_w, Uiou_w);
  k_gemm_tc<<<dim3(NR/128, 1, 12), blk, GEMM_SMEM>>>(x, h3, c3, Up_b, Uf_b, Wc_b, Wq_b);
  k_post2<<<2*NB, blk>>>(h1, h2, h3, c1, c2, c3, del_t, dsc);
  k_agg<<<4*NB, blk>>>(nbr);
  k_iou_tc<<<dim3(NR/128, 3, 3), blk, GEMM_SMEM>>>(Uiou_b);
  k_final<<<NR/8, blk>>>(iou1, iou2, iou3, out);
}

// round 15
// speedup vs baseline: 1.4016x; 1.0614x over previous
#include <cuda_runtime.h>
#include <cuda_bf16.h>
#include <math.h>

#define NR 8192
#define HD 128
#define KN 8
#define H3 384
#define EPSF 1e-6f
#define NB (NR/8)

// ---------------- scratch ----------------
__device__ float g_A1[NR*HD], g_A2[NR*HD], g_B1[NR*HD], g_B2[NR*HD], g_X1[NR*HD], g_X2[NR*HD];
__device__ float g_U1[NR*HD], g_U2[NR*HD], g_U3[NR*HD];
__device__ float g_F1[NR*HD], g_F2[NR*HD], g_F3[NR*HD];
__device__ float g_W1[NR*HD], g_W2[NR*HD], g_W3[NR*HD];
__device__ float g_Q1[NR*HD], g_Q2[NR*HD], g_Q3[NR*HD];
__device__ float g_h1p[NR*HD], g_h1s[NR*HD], g_h1e[NR*HD];
__device__ float g_yp[NR*HD], g_ys[NR*HD], g_ye[NR*HD];
__device__ float g_nhp2[NR], g_nhs2[NR], g_lyp[NR], g_lys[NR];
__device__ float g_q1ss[NR], g_q2ss[NR], g_c1vss[NR], g_c2vss[NR];
__device__ float g_T1[NR*HD], g_T2[NR*HD], g_T3[NR*HD];
__device__ float g_c1v[NR*HD], g_c2v[NR*HD], g_c3v[NR*HD];
__device__ float g_G1[NR*H3], g_G2[NR*H3], g_G3[NR*H3];

// packed bf16 hi/lo weights
#define OFF_UP 0
#define OFF_UF 8192
#define OFF_WC 16384
#define OFF_WQ 24576
#define OFF_IOU 32768
#define WPK_TOT 57344
__device__ unsigned int g_Whi[WPK_TOT], g_Wlo[WPK_TOT];

// ---------------- fast transcendentals ----------------
__device__ __forceinline__ float sigm(float v){
  return __fdividef(1.f, 1.f + __expf(-v));
}
__device__ __forceinline__ float ftanh(float v){
  return fmaf(2.f, __fdividef(1.f, 1.f + __expf(-2.f*v)), -1.f);
}
__device__ __forceinline__ float fatanh(float u){
  return 0.5f*__logf(__fdividef(1.f+u, 1.f-u));
}
__device__ __forceinline__ float artk(float u, float k){
  if (k < 0.f){ u = fminf(fmaxf(u, -1.f+1e-5f), 1.f-1e-5f); return fatanh(u); }
  return atanf(u);
}
__device__ __forceinline__ float tank(float u, float k){
  if (k < 0.f) return ftanh(u);
  return __tanf(fminf(fmaxf(u, -1.47079f), 1.47079f));
}
__device__ __forceinline__ float sden(float d){
  return d >= 0.f ? fmaxf(d, EPSF) : fminf(d, -EPSF);
}
__device__ __forceinline__ float nrm(float ss){ return sqrtf(ss + 1e-15f); }

// ---------------- reductions ----------------
template<int N> __device__ __forceinline__ void redN(float* v){
  #pragma unroll
  for (int o=16;o;o>>=1){
    float t[N];
    #pragma unroll
    for (int i=0;i<N;i++) t[i] = __shfl_xor_sync(0xffffffffu, v[i], o);
    #pragma unroll
    for (int i=0;i<N;i++) v[i] += t[i];
  }
}
template<int V> __device__ __forceinline__ float pdot(const float* a, const float* b){
  float s = 0.f;
  #pragma unroll
  for (int i=0;i<V;i++) s += a[i]*b[i];
  return s;
}
template<int V> __device__ __forceinline__ float pss(const float* a){ return pdot<V>(a,a); }

// ---------------- analytic (norm-tracked) manifold ops ----------------
template<int V> __device__ __forceinline__ void vscale(float* a, float f){
  #pragma unroll
  for (int i=0;i<V;i++) a[i]*=f;
}
template<int V> __device__ __forceinline__ float aexp0(float* a, float k, float ss){
  float n = nrm(ss);
  float t = tank(n,k);
  if (k < 0.f) t = fminf(t, 1.f-1e-4f);
  vscale<V>(a, __fdividef(t,n));
  return t*t;
}
template<int V> __device__ __forceinline__ float alog0(float* a, float k, float ss){
  float n = nrm(ss);
  float t = artk(n,k);
  vscale<V>(a, __fdividef(t,n));
  return t*t;
}
template<int V> __device__ __forceinline__ float aexplog(float* a, float k, float ss){
  float n = nrm(ss);
  float t;
  if (k < 0.f) t = fatanh(fminf(ftanh(n), 1.f-1e-4f));
  else         t = fminf(n, 1.47079f);
  vscale<V>(a, __fdividef(t,n));
  return t*t;
}
template<int V> __device__ __forceinline__ float asmul(float* a, float r, float k, float ss){
  float n = nrm(ss);
  float t = tank(r*artk(n,k),k);
  if (k < 0.f) t = fminf(t, 1.f-1e-4f);
  vscale<V>(a, __fdividef(t,n));
  return t*t;
}
template<int V> __device__ __forceinline__ float apw(float* wx, float k, float ssx, float ssw){
  float nx = nrm(ssx), nwx = nrm(ssw);
  float t = tank(__fdividef(nwx,nx)*artk(nx,k),k);
  if (k < 0.f) t = fminf(t, 1.f-1e-4f);
  vscale<V>(wx, __fdividef(t,nwx));
  return t*t;
}
template<int V> __device__ __forceinline__ float aproj(float* a, float ss){
  float n = nrm(ss);
  const float m = 1.f-1e-4f;
  if (n > m){ float f = __fdividef(m,n); vscale<V>(a, f); return ss*f*f; }
  return ss;
}
__device__ __forceinline__ void amadd_coef(float k, float x2, float y2, float xy,
                                           float& ca, float& cb, float& isd){
  ca = 1.f - 2.f*k*xy - k*y2;
  cb = 1.f + k*x2;
  isd = __fdividef(1.f, sden(1.f - 2.f*k*xy + k*k*x2*y2));
}
__device__ __forceinline__ float distf(float x2, float y2, float xy, float k){
  float ca = 1.f + 2.f*k*xy - k*y2;
  float cb = 1.f + k*x2;
  float sd = sden(1.f + 2.f*k*xy + k*k*x2*y2);
  float s = fmaxf(ca*ca*x2 + cb*cb*y2 - 2.f*ca*cb*xy, 0.f);
  float nv2 = __fdividef(s, sd*sd);
  float pn = sqrtf(nv2 + 1e-15f);
  if (k < 0.f){
    const float m = 1.f - 1e-4f;
    if (pn > m){ float sc = __fdividef(m,pn); pn = sqrtf(nv2*sc*sc + 1e-15f); }
  }
  return 2.f*artk(pn, k);
}

// ---------------- vectorized row access: lane owns elems [4lane..4lane+3] ----------
// memory stays element-indexed; reductions/elementwise ops are layout-agnostic.
__device__ __forceinline__ void ldrow(float* a, const float* p, int row, int lane){
  float4 v = *(const float4*)(p + (size_t)row*HD + lane*4);
  a[0]=v.x; a[1]=v.y; a[2]=v.z; a[3]=v.w;
}
__device__ __forceinline__ void strow(const float* a, float* p, int row, int lane){
  *(float4*)(p + (size_t)row*HD + lane*4) = make_float4(a[0],a[1],a[2],a[3]);
}
// 12-wide (H3 rows): 3 float4 chunks mapping exactly onto the 128-elem i/o/u blocks
__device__ __forceinline__ void ldrow12(float* a, const float* p, int row, int lane){
  #pragma unroll
  for (int b=0;b<3;b++){
    float4 v = *(const float4*)(p + (size_t)row*H3 + b*128 + lane*4);
    a[b*4]=v.x; a[b*4+1]=v.y; a[b*4+2]=v.z; a[b*4+3]=v.w;
  }
}

// ---------------- bf16 split helpers ----------------
__device__ __forceinline__ unsigned int packbf(__nv_bfloat16 lo, __nv_bfloat16 hi){
  __nv_bfloat162 t = __halves2bfloat162(lo, hi);
  return *reinterpret_cast<unsigned int*>(&t);
}
__device__ __forceinline__ void splitbf(float f, __nv_bfloat16& h, __nv_bfloat16& l){
  h = __float2bfloat16_rn(f);
  l = __float2bfloat16_rn(f - __bfloat162float(h));
}
#define MMA_BF16(c, a, b0, b1) \
  asm volatile("mma.sync.aligned.m16n8k16.row.col.f32.bf16.bf16.f32 " \
    "{%0,%1,%2,%3}, {%4,%5,%6,%7}, {%8,%9}, {%0,%1,%2,%3};" \
    : "+f"((c)[0]),"+f"((c)[1]),"+f"((c)[2]),"+f"((c)[3]) \
    : "r"((a)[0]),"r"((a)[1]),"r"((a)[2]),"r"((a)[3]), "r"(b0),"r"(b1))

// ---------------- k1: packed prep + weight split ----------------
__global__ void __launch_bounds__(256) k_prepwc(const float* __restrict__ x,
    const float* __restrict__ h1, const float* __restrict__ h2,
    const float* __restrict__ c1, const float* __restrict__ c2,
    const float* __restrict__ Up_w, const float* __restrict__ Uf_w,
    const float* __restrict__ Wc_w, const float* __restrict__ Wq_w,
    const float* __restrict__ Uiou_w){
  if (blockIdx.x < NB){
    int r = blockIdx.x*8 + (threadIdx.x>>5);
    int lane = threadIdx.x & 31;
    float a1[4],a2[4],b1[4],b2[4],xx[4];
    ldrow(a1,h1,r,lane); ldrow(a2,h2,r,lane);
    ldrow(b1,c1,r,lane); ldrow(b2,c2,r,lane);
    ldrow(xx,x ,r,lane);
    float rv[5] = {pss<4>(a1),pss<4>(a2),pss<4>(b1),pss<4>(b2),pss<4>(xx)};
    redN<5>(rv);
    alog0<4>(a1,-1.f,rv[0]); strow(a1,g_A1,r,lane);
    alog0<4>(a2, 1.f,rv[1]); strow(a2,g_A2,r,lane);
    alog0<4>(b1,-1.f,rv[2]); strow(b1,g_B1,r,lane);
    alog0<4>(b2, 1.f,rv[3]); strow(b2,g_B2,r,lane);
    float xc[4];
    #pragma unroll
    for (int i=0;i<4;i++) xc[i]=xx[i];
    aexplog<4>(xc,-1.f,rv[4]); strow(xc,g_X1,r,lane);
    aexplog<4>(xx, 1.f,rv[4]); strow(xx,g_X2,r,lane);
  } else {
    int e = (blockIdx.x - NB)*256 + threadIdx.x;
    const float* src; int off;
    if (e < OFF_UF)        { src = Up_w;   off = e - OFF_UP; }
    else if (e < OFF_WC)   { src = Uf_w;   off = e - OFF_UF; }
    else if (e < OFF_WQ)   { src = Wc_w;   off = e - OFF_WC; }
    else if (e < OFF_IOU)  { src = Wq_w;   off = e - OFF_WQ; }
    else                   { src = Uiou_w; off = e - OFF_IOU; }
    float f0 = src[(size_t)off*2], f1 = src[(size_t)off*2+1];
    __nv_bfloat16 h0,l0,h1b,l1b;
    splitbf(f0,h0,l0); splitbf(f1,h1b,l1b);
    g_Whi[e] = packbf(h0,h1b);
    g_Wlo[e] = packbf(l0,l1b);
  }
}

// ---------------- tensor-core GEMM: double-buffered, 1 sync/chunk ----------------
#define KP2 20
#define BUFU 10240
__device__ __forceinline__ void gemm_tc_body(
    const float* __restrict__ A, const unsigned int* __restrict__ Wh_g,
    const unsigned int* __restrict__ Wl_g, const float* __restrict__ bias,
    float* __restrict__ C, int ldc, int colOff, int m0){
  extern __shared__ unsigned int smdy[];
  int tid = threadIdx.x;
  int lane = tid & 31, wid = tid >> 5;
  int warpM = wid & 3, warpN = wid >> 2;
  int gid = lane >> 2, tig = lane & 3;
  float acc[2][8][4];
  #pragma unroll
  for (int mi=0;mi<2;mi++)
    #pragma unroll
    for (int ni=0;ni<8;ni++)
      #pragma unroll
      for (int q=0;q<4;q++) acc[mi][ni][q]=0.f;

  int ar = (tid>>3), akq = (tid&7)*4;
  int wr = (tid>>2), wkq = (tid&3)*4;
  float4 av[4]; uint4 whv[2], wlv[2];
  #pragma unroll
  for (int p=0;p<4;p++)
    av[p] = *(const float4*)(A + (size_t)(m0+ar+p*32)*HD + akq);
  #pragma unroll
  for (int t=0;t<2;t++){
    whv[t] = *(const uint4*)(Wh_g + (size_t)(wr+t*64)*64 + wkq);
    wlv[t] = *(const uint4*)(Wl_g + (size_t)(wr+t*64)*64 + wkq);
  }

  for (int c=0; c<4; c++){
    unsigned int* SAh = smdy + (c&1)*BUFU;
    unsigned int* SAl = SAh + 2560;
    unsigned int* SWh = SAh + 5120;
    unsigned int* SWl = SAh + 7680;
    #pragma unroll
    for (int p=0;p<4;p++){
      int rr = ar + p*32;
      __nv_bfloat16 h0,l0,h1,l1;
      splitbf(av[p].x,h0,l0); splitbf(av[p].y,h1,l1);
      SAh[rr*KP2 + (akq>>1)  ] = packbf(h0,h1);
      SAl[rr*KP2 + (akq>>1)  ] = packbf(l0,l1);
      splitbf(av[p].z,h0,l0); splitbf(av[p].w,h1,l1);
      SAh[rr*KP2 + (akq>>1)+1] = packbf(h0,h1);
      SAl[rr*KP2 + (akq>>1)+1] = packbf(l0,l1);
    }
    #pragma unroll
    for (int t=0;t<2;t++){
      *(uint4*)&SWh[(wr+t*64)*KP2 + wkq] = whv[t];
      *(uint4*)&SWl[(wr+t*64)*KP2 + wkq] = wlv[t];
    }
    __syncthreads();
    if (c < 3){
      int kt = (c+1)*32;
      #pragma unroll
      for (int p=0;p<4;p++)
        av[p] = *(const float4*)(A + (size_t)(m0+ar+p*32)*HD + kt + akq);
      #pragma unroll
      for (int t=0;t<2;t++){
        whv[t] = *(const uint4*)(Wh_g + (size_t)(wr+t*64)*64 + (kt>>1) + wkq);
        wlv[t] = *(const uint4*)(Wl_g + (size_t)(wr+t*64)*64 + (kt>>1) + wkq);
      }
    }
    #pragma unroll
    for (int ks=0; ks<2; ks++){
      int kb = ks*8;
      unsigned int ah[2][4], al[2][4];
      #pragma unroll
      for (int mi=0;mi<2;mi++){
        int r0 = warpM*32 + mi*16 + gid;
        ah[mi][0]=SAh[r0*KP2+kb+tig];     ah[mi][1]=SAh[(r0+8)*KP2+kb+tig];
        ah[mi][2]=SAh[r0*KP2+kb+tig+4];   ah[mi][3]=SAh[(r0+8)*KP2+kb+tig+4];
        al[mi][0]=SAl[r0*KP2+kb+tig];     al[mi][1]=SAl[(r0+8)*KP2+kb+tig];
        al[mi][2]=SAl[r0*KP2+kb+tig+4];   al[mi][3]=SAl[(r0+8)*KP2+kb+tig+4];
      }
      #pragma unroll
      for (int ni=0;ni<8;ni++){
        int c0 = warpN*64 + ni*8 + gid;
        unsigned int bh0 = SWh[c0*KP2+kb+tig], bh1 = SWh[c0*KP2+kb+tig+4];
        unsigned int bl0 = SWl[c0*KP2+kb+tig], bl1 = SWl[c0*KP2+kb+tig+4];
        #pragma unroll
        for (int mi=0;mi<2;mi++){
          MMA_BF16(acc[mi][ni], ah[mi], bh0, bh1);
          MMA_BF16(acc[mi][ni], ah[mi], bl0, bl1);
          MMA_BF16(acc[mi][ni], al[mi], bh0, bh1);
        }
      }
    }
  }
  #pragma unroll
  for (int mi=0;mi<2;mi++){
    int r = m0 + warpM*32 + mi*16 + gid;
    #pragma unroll
    for (int ni=0;ni<8;ni++){
      int c = colOff + warpN*64 + ni*8 + tig*2;
      float b0 = bias[c], b1 = bias[c+1];
      float2 v0 = make_float2(acc[mi][ni][0]+b0, acc[mi][ni][1]+b1);
      float2 v1 = make_float2(acc[mi][ni][2]+b0, acc[mi][ni][3]+b1);
      *(float2*)(C + (size_t)r*ldc + c) = v0;
      *(float2*)(C + (size_t)(r+8)*ldc + c) = v1;
    }
  }
}

__global__ void __launch_bounds__(256) k_gemm_tc(const float* __restrict__ x,
    const float* __restrict__ h3, const float* __restrict__ c3,
    const float* __restrict__ Up_b, const float* __restrict__ Uf_b,
    const float* __restrict__ Wc_b, const float* __restrict__ Wq_b){
  const float *A, *bias; float* C; int woff;
  switch (blockIdx.z){
    case 0:  A=g_A1; woff=OFF_UP; bias=Up_b; C=g_U1; break;
    case 1:  A=g_A2; woff=OFF_UP; bias=Up_b; C=g_U2; break;
    case 2:  A=h3;   woff=OFF_UP; bias=Up_b; C=g_U3; break;
    case 3:  A=g_A1; woff=OFF_UF; bias=Uf_b; C=g_F1; break;
    case 4:  A=g_A2; woff=OFF_UF; bias=Uf_b; C=g_F2; break;
    case 5:  A=h3;   woff=OFF_UF; bias=Uf_b; C=g_F3; break;
    case 6:  A=g_B1; woff=OFF_WC; bias=Wc_b; C=g_W1; break;
    case 7:  A=g_B2; woff=OFF_WC; bias=Wc_b; C=g_W2; break;
    case 8:  A=c3;   woff=OFF_WC; bias=Wc_b; C=g_W3; break;
    case 9:  A=g_X1; woff=OFF_WQ; bias=Wq_b; C=g_Q1; break;
    case 10: A=g_X2; woff=OFF_WQ; bias=Wq_b; C=g_Q2; break;
    default: A=x;    woff=OFF_WQ; bias=Wq_b; C=g_Q3; break;
  }
  gemm_tc_body(A, g_Whi+woff, g_Wlo+woff, bias, C, HD, 0, blockIdx.x*128);
}

__global__ void __launch_bounds__(256) k_iou_tc(const float* __restrict__ Uiou_b){
  const float* A; float* C;
  switch (blockIdx.z){
    case 0:  A=g_T1; C=g_G1; break;
    case 1:  A=g_T2; C=g_G2; break;
    default: A=g_T3; C=g_G3; break;
  }
  int colOff = blockIdx.y*128;
  gemm_tc_body(A, g_Whi + OFF_IOU + (size_t)colOff*64,
               g_Wlo + OFF_IOU + (size_t)colOff*64,
               Uiou_b, C, H3, colOff, blockIdx.x*128);
}

// ---------------- rowwise post bodies ----------------
__device__ __forceinline__ void hpost_row(int r, int lane,
    const float* __restrict__ h1, const float* __restrict__ h2,
    const float* __restrict__ h3){
  float s1[4], s2[4], s3[4], vh1[4], vh2[4], vh3[4], q1[4], q2[4];
  ldrow(s1,g_U1,r,lane); ldrow(s2,g_U2,r,lane); ldrow(s3,g_U3,r,lane);
  ldrow(vh1,h1,r,lane);  ldrow(vh2,h2,r,lane);  ldrow(vh3,h3,r,lane);
  ldrow(q1,g_Q1,r,lane); ldrow(q2,g_Q2,r,lane);

  float rv[7] = {pss<4>(s1),pss<4>(s2),pss<4>(vh1),pss<4>(vh2),pss<4>(vh3),
                 pss<4>(q1),pss<4>(q2)};
  redN<7>(rv);
  float ssh1=rv[2], ssh2=rv[3], ssh3=rv[4];

  aexp0<4>(s1,-1.f,rv[0]);
  aexp0<4>(s2, 1.f,rv[1]);
  #pragma unroll
  for (int i=0;i<4;i++){ s1[i]=sigm(s1[i]); s2[i]=sigm(s2[i]); s3[i]=sigm(s3[i]); }
  float rv2[2] = {pss<4>(s1), pss<4>(s2)};
  redN<2>(rv2);
  alog0<4>(s1,-1.f,rv2[0]);
  alog0<4>(s2, 1.f,rv2[1]);

  float n2h = nrm(ssh2);
  float t2p = ftanh(atanf(n2h));
  float f2p = __fdividef(t2p,n2h);  float ssx2p = t2p*t2p;
  float n3h = nrm(ssh3);
  float t3p = fminf(ftanh(n3h), 1.f-1e-4f);
  float f3p = __fdividef(t3p,n3h);  float ssx3p = t3p*t3p;
  float n1h = nrm(ssh1);
  float a1t = artk(n1h,-1.f);
  float t1s = __tanf(fminf(a1t, 1.47079f));
  float f1s = __fdividef(t1s,n1h);  float ssx1s = t1s*t1s;
  float t3s = __tanf(fminf(n3h, 1.47079f));
  float f3s = __fdividef(t3s,n3h);  float ssx3s = t3s*t3s;

  float w1p[4],w2p[4],w3p[4],w1s[4],w2s[4],w3s[4];
  #pragma unroll
  for (int i=0;i<4;i++){
    w1p[i]=s1[i]*vh1[i];
    w2p[i]=s2[i]*vh2[i]*f2p;
    w3p[i]=s3[i]*vh3[i]*f3p;
    w1s[i]=s1[i]*vh1[i]*f1s;
    w2s[i]=s2[i]*vh2[i];
    w3s[i]=s3[i]*vh3[i]*f3s;
  }
  float rv3[6] = {pss<4>(w1p),pss<4>(w2p),pss<4>(w3p),
                  pss<4>(w1s),pss<4>(w2s),pss<4>(w3s)};
  redN<6>(rv3);
  float r1p = apw<4>(w1p,-1.f, ssh1,  rv3[0]);
  float r2p = apw<4>(w2p,-1.f, ssx2p, rv3[1]);
  float r3p = apw<4>(w3p,-1.f, ssx3p, rv3[2]);
  float r1s = apw<4>(w1s,-1.f, ssx1s, rv3[3]);
  float r2s = apw<4>(w2s, 1.f, ssh2,  rv3[4]);
  float r3s = apw<4>(w3s, 1.f, ssx3s, rv3[5]);

  float lap=__fdividef(2.f,1.f-r1p), lbp=__fdividef(2.f,1.f-r2p), lcp=__fdividef(2.f,1.f-r3p);
  float idenp = __fdividef(1.f, fmaxf(fabsf(lap+lbp+lcp-3.f), EPSF));
  float las=__fdividef(2.f,1.f-r1s), lbs=__fdividef(2.f,1.f-r2s), lcs=__fdividef(2.f,1.f-r3s);
  float idens = __fdividef(1.f, fmaxf(fabsf(las+lbs+lcs-3.f), EPSF));
  float sp[4], sv[4];
  #pragma unroll
  for (int i=0;i<4;i++){
    sp[i] = (lap*w1p[i]+lbp*w2p[i]+lcp*w3p[i])*idenp;
    sv[i] = (las*w1s[i]+lbs*w2s[i]+lcs*w3s[i])*idens;
  }
  float rv4[2] = {pss<4>(sp), pss<4>(sv)};
  redN<2>(rv4);
  float tp2 = asmul<4>(sp,0.5f,-1.f,rv4[0]);
  float ts2 = asmul<4>(sv,0.5f,-1.f,rv4[1]);
  #pragma unroll
  for (int i=0;i<4;i++){ sp[i]*=3.f; sv[i]*=3.f; }
  strow(sp,g_h1p,r,lane);
  strow(sv,g_h1s,r,lane);
  if (lane==0){ g_nhp2[r]=9.f*tp2; g_nhs2[r]=9.f*ts2; }

  float fe1 = __fdividef(artk(nrm(r1p),-1.f), nrm(r1p));
  float fe2 = __fdividef(artk(nrm(r2s), 1.f), nrm(r2s));
  float he[4];
  #pragma unroll
  for (int i=0;i<4;i++) he[i] = w1p[i]*fe1 + w2s[i]*fe2 + s3[i]*vh3[i];
  strow(he,g_h1e,r,lane);

  float xe1 = aexp0<4>(q1,-1.f,rv[5]); strow(q1,g_X1,r,lane);
  float xe2 = aexp0<4>(q2, 1.f,rv[6]); strow(q2,g_X2,r,lane);
  if (lane==0){ g_q1ss[r]=xe1; g_q2ss[r]=xe2; }
}

__device__ __forceinline__ void cpost_row(int r, int lane,
    const float* __restrict__ c1, const float* __restrict__ c2,
    const float* __restrict__ c3, const float* __restrict__ del_t,
    const float* __restrict__ dptr){
  float g = __fdividef(dptr[0], del_t[r] + 1.f);

  float w1[4],w2[4],vc1[4],vc2[4],f1[4],f2[4];
  ldrow(w1,g_W1,r,lane); ldrow(w2,g_W2,r,lane);
  ldrow(vc1,c1,r,lane);  ldrow(vc2,c2,r,lane);
  ldrow(f1,g_F1,r,lane); ldrow(f2,g_F2,r,lane);
  float rv[6] = {pss<4>(w1),pss<4>(w2),pss<4>(vc1),pss<4>(vc2),
                 pss<4>(f1),pss<4>(f2)};
  redN<6>(rv);

  aexplog<4>(w1,-1.f,rv[0]);
  aexplog<4>(w2, 1.f,rv[1]);
  #pragma unroll
  for (int i=0;i<4;i++){ w1[i]=ftanh(w1[i]); w2[i]=ftanh(w2[i]); }
  float rv2[2] = {pss<4>(w1), pss<4>(w2)};
  redN<2>(rv2);
  float sscp = aexp0<4>(w1,-1.f,rv2[0]);
  float sscs = aexp0<4>(w2, 1.f,rv2[1]);

  float pgp[4], pgs[4];
  #pragma unroll
  for (int i=0;i<4;i++){ pgp[i]=w1[i]*g; pgs[i]=w2[i]*g; }
  float rpgp = apw<4>(pgp,-1.f, g*g, g*g*sscp);
  float rpgs = apw<4>(pgs, 1.f, g*g, g*g*sscs);

  float rv3[2] = {pdot<4>(w1,vc1), pdot<4>(w2,vc2)};
  redN<2>(rv3);
  float ca,cb,isd;
  amadd_coef(-1.f, sscp, rv[2], -rv3[0], ca, cb, isd);
  float map[4];
  #pragma unroll
  for (int i=0;i<4;i++) map[i] = (ca*(-w1[i]) + cb*vc1[i])*isd;
  amadd_coef( 1.f, sscs, rv[3], -rv3[1], ca, cb, isd);
  float mas[4];
  #pragma unroll
  for (int i=0;i<4;i++) mas[i] = (ca*(-w2[i]) + cb*vc2[i])*isd;

  float rv4[4] = {pss<4>(map), pdot<4>(map,pgp), pss<4>(mas), pdot<4>(mas,pgs)};
  redN<4>(rv4);
  {
    float n = nrm(rv4[0]);
    const float m = 1.f-1e-4f;
    if (n > m){
      float f = __fdividef(m,n);
      #pragma unroll
      for (int i=0;i<4;i++) map[i]*=f;
      rv4[1]*=f; rv4[0]*=f*f;
    }
  }
  amadd_coef(-1.f, rv4[0], rpgp, rv4[1], ca, cb, isd);
  float ckp[4];
  #pragma unroll
  for (int i=0;i<4;i++) ckp[i] = (ca*map[i] + cb*pgp[i])*isd;
  amadd_coef( 1.f, rv4[2], rpgs, rv4[3], ca, cb, isd);
  float cks[4];
  #pragma unroll
  for (int i=0;i<4;i++) cks[i] = (ca*mas[i] + cb*pgs[i])*isd;

  aexplog<4>(f1,-1.f,rv[4]);
  aexplog<4>(f2, 1.f,rv[5]);
  #pragma unroll
  for (int i=0;i<4;i++){ f1[i]=sigm(f1[i]); f2[i]=sigm(f2[i]); }

  float wxs[4];
  #pragma unroll
  for (int i=0;i<4;i++) wxs[i]=f2[i]*cks[i];
  float rv5[3] = {pss<4>(ckp), pss<4>(cks), pss<4>(wxs)};
  redN<3>(rv5);
  float ssckp = aproj<4>(ckp, rv5[0]);
  float wxp[4];
  #pragma unroll
  for (int i=0;i<4;i++) wxp[i]=f1[i]*ckp[i];
  float rv6[1] = {pss<4>(wxp)};
  redN<1>(rv6);
  float ryp = apw<4>(wxp,-1.f, ssckp, rv6[0]);
  float rys = apw<4>(wxs, 1.f, rv5[1], rv5[2]);
  strow(wxp,g_yp,r,lane);
  strow(wxs,g_ys,r,lane);
  if (lane==0){ g_lyp[r]=__fdividef(2.f,1.f-ryp); g_lys[r]=__fdividef(2.f,1.f+rys); }

  {
    float w3[4],vc3[4],f3[4];
    ldrow(w3,g_W3,r,lane); ldrow(vc3,c3,r,lane); ldrow(f3,g_F3,r,lane);
    float y[4];
    #pragma unroll
    for (int i=0;i<4;i++){
      float csk = ftanh(w3[i]);
      y[i] = sigm(f3[i])*(vc3[i] - csk + csk*g);
    }
    strow(y,g_ye,r,lane);
  }
}

// ---------------- k3: packed hpost + cpost ----------------
__global__ void __launch_bounds__(256) k_post2(const float* __restrict__ h1,
    const float* __restrict__ h2, const float* __restrict__ h3,
    const float* __restrict__ c1, const float* __restrict__ c2,
    const float* __restrict__ c3, const float* __restrict__ del_t,
    const float* __restrict__ dptr){
  int lane = threadIdx.x & 31;
  int w = threadIdx.x >> 5;
  if (blockIdx.x < NB){
    hpost_row(blockIdx.x*8 + w, lane, h1, h2, h3);
  } else {
    cpost_row((blockIdx.x - NB)*8 + w, lane, c1, c2, c3, del_t, dptr);
  }
}

// ---------------- hyperbolic attention section (two-pass, low-reg) ----------------
__device__ __forceinline__ void hyp_attn_sec(int n, int lane, const int* __restrict__ nbr,
    const float* __restrict__ Q, const float* __restrict__ QSS,
    const float* __restrict__ Y, const float* __restrict__ YSS,
    float* __restrict__ T, float kk){
  int j[KN];
  #pragma unroll
  for (int k=0;k<KN;k++) j[k] = nbr[n*KN+k];
  float q[4]; ldrow(q,Q,n,lane);
  float q2 = QSS[n];
  float d[KN], y2k[KN];
  #pragma unroll
  for (int k=0;k<KN;k++){
    float yk[4]; ldrow(yk, Y, j[k], lane);
    y2k[k] = YSS[j[k]];
    d[k] = pdot<4>(q, yk);
  }
  redN<KN>(d);
  #pragma unroll
  for (int k=0;k<KN;k++) d[k] = -distf(q2, y2k[k], d[k], kk);
  float m = d[0];
  #pragma unroll
  for (int k=1;k<KN;k++) m = fmaxf(m, d[k]);
  float ssum = 0.f;
  #pragma unroll
  for (int k=0;k<KN;k++){ d[k] = __expf(d[k]-m); ssum += d[k]; }
  float issum = __fdividef(1.f, ssum);
  float den = 0.f;
  #pragma unroll
  for (int k=0;k<KN;k++){
    float a = d[k]*issum;
    float lam = __fdividef(2.f, 1.f + kk*y2k[k]);
    d[k] = a*lam;
    den += a*(lam-1.f);
  }
  float iden = __fdividef(1.f, fmaxf(fabsf(den), EPSF));
  float num[4] = {0,0,0,0};
  #pragma unroll
  for (int k=0;k<KN;k++){
    float yk[4]; ldrow(yk, Y, j[k], lane);
    #pragma unroll
    for (int i=0;i<4;i++) num[i] += d[k]*yk[i];
  }
  #pragma unroll
  for (int i=0;i<4;i++) num[i]*=iden;
  float rv[1] = {pss<4>(num)};
  redN<1>(rv);
  float ssT = asmul<4>(num,0.5f,kk,rv[0]);
  alog0<4>(num,kk,ssT);
  strow(num,T,n,lane);
}

// ---------------- k5: attention + K-aggregation, section-split ----------------
__global__ void __launch_bounds__(256) k_agg(const int* __restrict__ nbr){
  int sec  = blockIdx.x >> 10;
  int blk  = blockIdx.x & 1023;
  int n    = blk*8 + (threadIdx.x>>5);
  int lane = threadIdx.x & 31;

  if (sec == 0){
    hyp_attn_sec(n, lane, nbr, g_X1, g_q1ss, g_h1p, g_nhp2, g_T1, -1.f);
  } else if (sec == 1){
    hyp_attn_sec(n, lane, nbr, g_X2, g_q2ss, g_h1s, g_nhs2, g_T2,  1.f);
  } else if (sec == 2){
    int j[KN];
    #pragma unroll
    for (int k=0;k<KN;k++) j[k] = nbr[n*KN+k];
    float q[4]; ldrow(q,g_Q3,n,lane);
    float d[KN];
    #pragma unroll
    for (int k=0;k<KN;k++){
      float yk[4]; ldrow(yk, g_h1e, j[k], lane);
      d[k] = pdot<4>(q, yk);
    }
    redN<KN>(d);
    #pragma unroll
    for (int k=0;k<KN;k++) d[k] *= 0.08838834764831845f;
    float m = d[0];
    #pragma unroll
    for (int k=1;k<KN;k++) m = fmaxf(m, d[k]);
    float ssum = 0.f;
    #pragma unroll
    for (int k=0;k<KN;k++){ d[k] = __expf(d[k]-m); ssum += d[k]; }
    float issum = __fdividef(1.f, ssum);
    float num[4] = {0,0,0,0};
    #pragma unroll
    for (int k=0;k<KN;k++){
      float a = d[k]*issum;
      float yk[4]; ldrow(yk, g_h1e, j[k], lane);
      #pragma unroll
      for (int i=0;i<4;i++) num[i] += a*yk[i];
    }
    strow(num,g_T3,n,lane);
  } else {
    int j[KN];
    #pragma unroll
    for (int k=0;k<KN;k++) j[k] = nbr[n*KN+k];
    float np[4]={0,0,0,0}, ns[4]={0,0,0,0}, ne[4]={0,0,0,0};
    float dp=0.f, ds=0.f;
    #pragma unroll
    for (int k=0;k<KN;k++){
      float y[4];
      ldrow(y, g_yp, j[k], lane);
      float lam = g_lyp[j[k]];
      #pragma unroll
      for (int i=0;i<4;i++) np[i] += lam*y[i];
      dp += lam-1.f;
      ldrow(y, g_ys, j[k], lane);
      lam = g_lys[j[k]];
      #pragma unroll
      for (int i=0;i<4;i++) ns[i] += lam*y[i];
      ds += lam-1.f;
      ldrow(y, g_ye, j[k], lane);
      #pragma unroll
      for (int i=0;i<4;i++) ne[i] += y[i];
    }
    float idp = __fdividef(1.f, fmaxf(fabsf(dp), EPSF));
    float ids = __fdividef(1.f, fmaxf(fabsf(ds), EPSF));
    #pragma unroll
    for (int i=0;i<4;i++){ np[i]*=idp; ns[i]*=ids; }
    float rv[2] = {pss<4>(np), pss<4>(ns)};
    redN<2>(rv);
    float ssc1 = asmul<4>(np,0.5f,-1.f,rv[0]);
    float ssc2 = asmul<4>(ns,0.5f, 1.f,rv[1]);
    strow(np,g_c1v,n,lane);
    strow(ns,g_c2v,n,lane);
    strow(ne,g_c3v,n,lane);
    if (lane==0){ g_c1vss[n]=ssc1; g_c2vss[n]=ssc2; }
  }
}

// ---------------- k7: apply_node_func ----------------
__global__ void __launch_bounds__(256) k_final(const float* __restrict__ iou1,
    const float* __restrict__ iou2, const float* __restrict__ iou3,
    float* __restrict__ out){
  int r = blockIdx.x*8 + (threadIdx.x>>5);
  int lane = threadIdx.x & 31;

  float e1[12], a1[12], e2[12], a2[12];
  ldrow12(e1, g_G1, r, lane);
  ldrow12(a1, iou1, r, lane);
  ldrow12(e2, g_G2, r, lane);
  ldrow12(a2, iou2, r, lane);
  float rv[4] = {pss<12>(e1), pss<12>(a1), pss<12>(e2), pss<12>(a2)};
  redN<4>(rv);
  float sse1 = aexp0<12>(e1,-1.f,rv[0]);
  float sse2 = aexp0<12>(e2, 1.f,rv[2]);
  float rv2[2] = {pdot<12>(a1,e1), pdot<12>(a2,e2)};
  redN<2>(rv2);
  float ca,cb,isd;
  float nio1[12], nio2[12];
  amadd_coef(-1.f, rv[1], sse1, rv2[0], ca, cb, isd);
  #pragma unroll
  for (int i=0;i<12;i++) nio1[i] = (ca*a1[i] + cb*e1[i])*isd;
  amadd_coef( 1.f, rv[3], sse2, rv2[1], ca, cb, isd);
  #pragma unroll
  for (int i=0;i<12;i++) nio2[i] = (ca*a2[i] + cb*e2[i])*isd;

  float rv3[7] = {pss<12>(nio1),
                  pss<4>(nio1), pss<4>(nio1+4), pss<4>(nio1+8),
                  pss<4>(nio2), pss<4>(nio2+4), pss<4>(nio2+8)};
  redN<7>(rv3);
  {
    float nn = nrm(rv3[0]);
    const float m = 1.f-1e-4f;
    if (nn > m){
      float f = __fdividef(m,nn);
      #pragma unroll
      for (int i=0;i<12;i++) nio1[i]*=f;
      rv3[1]*=f*f; rv3[2]*=f*f; rv3[3]*=f*f;
    }
  }
  float ip1[4], op1[4], up1[4], ip2[4], op2[4], up2[4];
  {
    float fi = __fdividef(artk(nrm(rv3[1]),-1.f), nrm(rv3[1]));
    float fo = __fdividef(artk(nrm(rv3[2]),-1.f), nrm(rv3[2]));
    float fu = __fdividef(artk(nrm(rv3[3]),-1.f), nrm(rv3[3]));
    #pragma unroll
    for (int i=0;i<4;i++){
      ip1[i]=sigm(nio1[i]*fi); op1[i]=sigm(nio1[4+i]*fo); up1[i]=ftanh(nio1[8+i]*fu);
    }
    fi = __fdividef(artk(nrm(rv3[4]),1.f), nrm(rv3[4]));
    fo = __fdividef(artk(nrm(rv3[5]),1.f), nrm(rv3[5]));
    fu = __fdividef(artk(nrm(rv3[6]),1.f), nrm(rv3[6]));
    #pragma unroll
    for (int i=0;i<4;i++){
      ip2[i]=sigm(nio2[i]*fi); op2[i]=sigm(nio2[4+i]*fo); up2[i]=ftanh(nio2[8+i]*fu);
    }
  }
  float wx1[4], wx2[4];
  #pragma unroll
  for (int i=0;i<4;i++){ wx1[i]=ip1[i]*up1[i]; wx2[i]=ip2[i]*up2[i]; }
  float rv4[4] = {pss<4>(wx1), pss<4>(up1), pss<4>(wx2), pss<4>(up2)};
  redN<4>(rv4);
  float rpw1 = apw<4>(wx1,-1.f, rv4[1], rv4[0]);
  float rpw2 = apw<4>(wx2, 1.f, rv4[3], rv4[2]);

  float cv1[4], cv2[4];
  ldrow(cv1,g_c1v,r,lane); ldrow(cv2,g_c2v,r,lane);
  float y21 = g_c1vss[r], y22 = g_c2vss[r];
  float rv5[2] = {pdot<4>(wx1,cv1), pdot<4>(wx2,cv2)};
  redN<2>(rv5);
  float nc1[4], nc2[4];
  amadd_coef(-1.f, rpw1, y21, rv5[0], ca, cb, isd);
  #pragma unroll
  for (int i=0;i<4;i++) nc1[i] = (ca*wx1[i] + cb*cv1[i])*isd;
  amadd_coef( 1.f, rpw2, y22, rv5[1], ca, cb, isd);
  #pragma unroll
  for (int i=0;i<4;i++) nc2[i] = (ca*wx2[i] + cb*cv2[i])*isd;

  float rv6[2] = {pss<4>(nc1), pss<4>(nc2)};
  redN<2>(rv6);
  float ssnc1 = aproj<4>(nc1, rv6[0]);
  strow(nc1, out + (size_t)1*NR*HD, r, lane);
  strow(nc2, out + (size_t)3*NR*HD, r, lane);

  float lg1[4], lg2[4];
  {
    float f1 = __fdividef(artk(nrm(ssnc1),-1.f), nrm(ssnc1));
    float f2 = __fdividef(artk(nrm(rv6[1]), 1.f), nrm(rv6[1]));
    #pragma unroll
    for (int i=0;i<4;i++){ lg1[i]=ftanh(nc1[i]*f1); lg2[i]=ftanh(nc2[i]*f2); }
  }
  float wy1[4], wy2[4];
  #pragma unroll
  for (int i=0;i<4;i++){ wy1[i]=op1[i]*lg1[i]; wy2[i]=op2[i]*lg2[i]; }
  float rv7[4] = {pss<4>(lg1), pss<4>(wy1), pss<4>(lg2), pss<4>(wy2)};
  redN<4>(rv7);
  apw<4>(wy1,-1.f, rv7[0], rv7[1]);
  strow(wy1, out + (size_t)0*NR*HD, r, lane);
  apw<4>(wy2, 1.f, rv7[2], rv7[3]);
  strow(wy2, out + (size_t)2*NR*HD, r, lane);

  { // euclid (vectorized chunk loads; chunk b = elems b*128+4lane..+3)
    float cv[4]; ldrow(cv, g_c3v, r, lane);
    float i3[4], o3[4], u3[4], gi[4], go[4], gu[4];
    {
      float4 v;
      v = *(const float4*)(iou3 + (size_t)r*H3 +       lane*4); i3[0]=v.x;i3[1]=v.y;i3[2]=v.z;i3[3]=v.w;
      v = *(const float4*)(iou3 + (size_t)r*H3 + 128 + lane*4); o3[0]=v.x;o3[1]=v.y;o3[2]=v.z;o3[3]=v.w;
      v = *(const float4*)(iou3 + (size_t)r*H3 + 256 + lane*4); u3[0]=v.x;u3[1]=v.y;u3[2]=v.z;u3[3]=v.w;
      v = *(const float4*)(g_G3 + (size_t)r*H3 +       lane*4); gi[0]=v.x;gi[1]=v.y;gi[2]=v.z;gi[3]=v.w;
      v = *(const float4*)(g_G3 + (size_t)r*H3 + 128 + lane*4); go[0]=v.x;go[1]=v.y;go[2]=v.z;go[3]=v.w;
      v = *(const float4*)(g_G3 + (size_t)r*H3 + 256 + lane*4); gu[0]=v.x;gu[1]=v.y;gu[2]=v.z;gu[3]=v.w;
    }
    float nc[4], nh[4];
    #pragma unroll
    for (int i=0;i<4;i++){
      float ie = sigm(i3[i] + gi[i]);
      float oe = sigm(o3[i] + go[i]);
      float ue = ftanh(u3[i] + gu[i]);
      nc[i] = ie*ue + cv[i];
      nh[i] = oe*ftanh(nc[i]);
    }
    strow(nc, out + (size_t)5*NR*HD, r, lane);
    strow(nh, out + (size_t)4*NR*HD, r, lane);
  }
}

// ---------------- launch ----------------
extern "C" void kernel_launch(void* const* d_in, const int* in_sizes, int n_in,
                              void* d_out, int out_size){
  const float* x     = (const float*)d_in[0];
  const float* h1    = (const float*)d_in[1];
  const float* c1    = (const float*)d_in[2];
  const float* h2    = (const float*)d_in[3];
  const float* c2    = (const float*)d_in[4];
  const float* h3    = (const float*)d_in[5];
  const float* c3    = (const float*)d_in[6];
  const float* del_t = (const float*)d_in[7];
  const float* iou1  = (const float*)d_in[8];
  const float* iou2  = (const float*)d_in[9];
  const float* iou3  = (const float*)d_in[10];
  const float* Wq_w  = (const float*)d_in[11];
  const float* Wq_b  = (const float*)d_in[12];
  const float* Wc_w  = (const float*)d_in[13];
  const float* Wc_b  = (const float*)d_in[14];
  const float* Uf_w  = (const float*)d_in[15];
  const float* Uf_b  = (const float*)d_in[16];
  const float* Up_w  = (const float*)d_in[17];
  const float* Up_b  = (const float*)d_in[18];
  const float* Uiou_w= (const float*)d_in[19];
  const float* Uiou_b= (const float*)d_in[20];
  const float* dsc   = (const float*)d_in[21];
  const int*   nbr   = (const int*)d_in[22];
  float* out = (float*)d_out;

  const int GEMM_SMEM = 2*BUFU*4;   // 81920 bytes
  cudaFuncSetAttribute(k_gemm_tc, cudaFuncAttributeMaxDynamicSharedMemorySize, GEMM_SMEM);
  cudaFuncSetAttribute(k_iou_tc,  cudaFuncAttributeMaxDynamicSharedMemorySize, GEMM_SMEM);

  dim3 blk(256);
  k_prepwc<<<NB + WPK_TOT/256, blk>>>(x, h1, h2, c1, c2,
                                      Up_w, Uf_w, Wc_w, Wq_w, Uiou_w);
  k_gemm_tc<<<dim3(NR/128, 1, 12), blk, GEMM_SMEM>>>(x, h3, c3, Up_b, Uf_b, Wc_b, Wq_b);
  k_post2<<<2*NB, blk>>>(h1, h2, h3, c1, c2, c3, del_t, dsc);
  k_agg<<<4*NB, blk>>>(nbr);
  k_iou_tc<<<dim3(NR/128, 3, 3), blk, GEMM_SMEM>>>(Uiou_b);
  k_final<<<NR/8, blk>>>(iou1, iou2, iou3, out);
}